// round 10
// baseline (speedup 1.0000x reference)
#include <cuda_runtime.h>
#include <math.h>

#define TWO_PI_F 6.2831853071795864769f

// ---------------- device scratch ----------------
__device__ float d_h0[64*64*64*64];
__device__ float d_h1[64*128*32*32];
__device__ float d_Zbuf[64*168*16*16];
__device__ float d_g0[64*256*32*32];
__device__ float d_g1[64*128*64*64];
__device__ float d_stat0[128];
__device__ float d_stat1[256];
__device__ float d_stat2[512];
__device__ float d_stat3[256];
__device__ float d_a0[64],  d_c0[64];
__device__ float d_a1[128], d_c1[128];
__device__ float d_a2[256], d_c2[256];
__device__ float d_a3[128], d_c3[128];
__device__ float d_wTc0[3*16*64];
__device__ float d_wTc1[64*16*128];
__device__ float d_wTc2[128*16*64];
__device__ float d_wTd0[4*168*4*256];
__device__ float d_wTd1[4*256*4*128];

// ---------------- packed f32x2 helpers ----------------
__device__ __forceinline__ unsigned long long pk2(float lo, float hi){
  unsigned long long r; asm("mov.b64 %0, {%1, %2};" : "=l"(r) : "f"(lo), "f"(hi)); return r;
}
__device__ __forceinline__ void fma2(unsigned long long& d, unsigned long long a, unsigned long long b){
  asm("fma.rn.f32x2 %0, %1, %2, %0;" : "+l"(d) : "l"(a), "l"(b));
}
__device__ __forceinline__ void unpk(unsigned long long v, float& lo, float& hi){
  asm("mov.b64 {%0, %1}, %2;" : "=f"(lo), "=f"(hi) : "l"(v));
}

// =====================================================================
// Weight transposes
// =====================================================================
__device__ __forceinline__ void tconv(const float* __restrict__ w, float* __restrict__ wT,
                                      int IC, int OC, int idx){
  int k = idx % 16; int ci = (idx/16) % IC; int co = idx/(16*IC);
  wT[(ci*16+k)*OC + co] = w[idx];
}
__device__ __forceinline__ void tdec(const float* __restrict__ w, float* __restrict__ wT,
                                     int IC, int OC, int idx){
  int kk = idx%16; int co = (idx/16)%OC; int ci = idx/(16*OC);
  int ky=kk>>2, kx=kk&3;
  int ry=(3-ky)&1, dd=(3-ky-ry)>>1;
  int rx=(3-kx)&1, ee=(3-kx-rx)>>1;
  wT[(((ry*2+rx)*IC+ci)*4 + dd*2+ee)*OC + co] = w[idx];
}
__global__ void transpose_convs(const float* w0, float* o0, const float* w1, float* o1,
                                const float* w2, float* o2){
  int idx = blockIdx.x*256 + threadIdx.x;
  if (idx < 3*64*16)   tconv(w0,o0,3,64,idx);
  if (idx < 64*128*16) tconv(w1,o1,64,128,idx);
  if (idx < 128*64*16) tconv(w2,o2,128,64,idx);
}
__global__ void transpose_deconvs(const float* w0, float* o0, const float* w1, float* o1){
  int idx = blockIdx.x*256+threadIdx.x;
  if (idx < 168*256*16) tdec(w0,o0,168,256,idx);
  if (idx < 256*128*16) tdec(w1,o1,256,128,idx);
}

// =====================================================================
// Strided conv k=4 s=2 p=1. Row register-cache: 18 values per (cc,ky),
// packed once, reused across 4 kx taps.
// =====================================================================
template<int IC, int OC, int IH, int IW, int OH, int OW, int OUT_CB,
         int TILE_OY, int CO_BLK, int CI_CHUNK, int NG_OX, int NG_CO,
         bool ACT_IN_LRELU, bool BIAS, bool TANH_OUT, bool REDUCE>
__global__ void __launch_bounds__(NG_CO*NG_OX*TILE_OY)
conv_s2_kernel(const float* __restrict__ in, const float* __restrict__ wT,
               const float* __restrict__ bias,
               const float* __restrict__ a_in, const float* __restrict__ c_in,
               float* __restrict__ out, float* __restrict__ stat)
{
  constexpr int NT    = NG_CO * NG_OX * TILE_OY;
  constexpr int CO_T  = CO_BLK / NG_CO;
  constexpr int CO_P  = CO_T / 2;
  constexpr int ROWS  = 2*TILE_OY + 2;
  constexpr int COLSP = IW + 4;
  constexpr int TOTAL_IN = CI_CHUNK*ROWS*COLSP;
  constexpr int NITER = (TOTAL_IN + NT - 1)/NT;
  constexpr int WLEN4 = CI_CHUNK*16*CO_BLK/4;
  static_assert(OW / NG_OX == 8, "");
  static_assert(CO_BLK == OC, "");
  static_assert((CO_P & (CO_P-1)) == 0, "");

  __shared__ __align__(16) float sIn[CI_CHUNK][ROWS][COLSP];
  __shared__ __align__(16) float sW [CI_CHUNK][16][CO_BLK];
  __shared__ float sRed[2*CO_BLK];

  const int tid   = threadIdx.x;
  const int co_g  = tid % NG_CO;
  const int ox_g  = (tid / NG_CO) % NG_OX;
  const int oy_l  = tid / (NG_CO * NG_OX);
  const int b     = blockIdx.z;
  const int oy0   = blockIdx.x * TILE_OY;
  const int iy0   = 2*oy0 - 1;
  const int ox0   = ox_g * 8;
  const int co_t0 = co_g * CO_T;

  int gOff[NITER]; int ccA[ACT_IN_LRELU ? NITER : 1];
  #pragma unroll
  for (int i=0;i<NITER;i++){
    int idx = tid + i*NT;
    int cc  = idx / (ROWS*COLSP);
    int rem = idx % (ROWS*COLSP);
    int r   = rem / COLSP, col = rem % COLSP;
    int iy  = iy0 + r, ix = col - 1;
    bool ok = (idx < TOTAL_IN) && ix >= 0 && ix < IW && iy >= 0 && iy < IH;
    gOff[i] = ok ? ((b*IC + cc)*IH + iy)*IW + ix : -1;
    if constexpr (ACT_IN_LRELU) ccA[i] = cc;
  }

  unsigned long long acc[8][CO_P];
  #pragma unroll
  for (int u=0;u<8;u++)
    #pragma unroll
    for (int j=0;j<CO_P;j++) acc[u][j] = 0ULL;

  float* sInF = &sIn[0][0][0];

  for (int ci0 = 0; ci0 < IC; ci0 += CI_CHUNK) {
    const int cBase = ci0*IH*IW;
    #pragma unroll
    for (int i=0;i<NITER;i++){
      int idx = tid + i*NT;
      if (idx < TOTAL_IN) {
        float v = 0.f;
        int go = gOff[i];
        if (go >= 0) {
          v = in[go + cBase];
          if constexpr (ACT_IN_LRELU) {
            float t = fmaf(a_in[ci0+ccA[i]], v, c_in[ci0+ccA[i]]);
            v = t > 0.f ? t : 0.2f*t;
          }
        }
        sInF[idx] = v;
      }
    }
    {
      const float4* ws = reinterpret_cast<const float4*>(wT + ci0*16*OC);
      float4* wd = reinterpret_cast<float4*>(&sW[0][0][0]);
      #pragma unroll
      for (int i = 0; i < (WLEN4 + NT - 1)/NT; i++) {
        int idx = tid + i*NT;
        if (idx < WLEN4) wd[idx] = ws[idx];
      }
    }
    __syncthreads();

    #pragma unroll
    for (int cc=0; cc<CI_CHUNK; cc++) {
      #pragma unroll
      for (int ky=0; ky<4; ky++) {
        const float* rowp = &sIn[cc][2*oy_l + ky][0] + 2*ox0;
        unsigned long long pv[18];
        {
          const float4* rp4 = reinterpret_cast<const float4*>(rowp);
          float4 q;
          q = rp4[0]; pv[0]=pk2(q.x,q.x); pv[1]=pk2(q.y,q.y); pv[2]=pk2(q.z,q.z); pv[3]=pk2(q.w,q.w);
          q = rp4[1]; pv[4]=pk2(q.x,q.x); pv[5]=pk2(q.y,q.y); pv[6]=pk2(q.z,q.z); pv[7]=pk2(q.w,q.w);
          q = rp4[2]; pv[8]=pk2(q.x,q.x); pv[9]=pk2(q.y,q.y); pv[10]=pk2(q.z,q.z); pv[11]=pk2(q.w,q.w);
          q = rp4[3]; pv[12]=pk2(q.x,q.x); pv[13]=pk2(q.y,q.y); pv[14]=pk2(q.z,q.z); pv[15]=pk2(q.w,q.w);
          float2 q2 = *reinterpret_cast<const float2*>(rowp + 16);
          pv[16]=pk2(q2.x,q2.x); pv[17]=pk2(q2.y,q2.y);
        }
        #pragma unroll
        for (int kx=0; kx<4; kx++) {
          const int k = ky*4 + kx;
          unsigned long long wv[CO_P];
          #pragma unroll
          for (int j=0;j<CO_P;j++){
            int p = (j + co_g) & (CO_P-1);
            wv[j] = *reinterpret_cast<const unsigned long long*>(&sW[cc][k][co_t0 + 2*p]);
          }
          #pragma unroll
          for (int u=0;u<8;u++)
            #pragma unroll
            for (int j=0;j<CO_P;j++) fma2(acc[u][j], pv[2*u+kx], wv[j]);
        }
      }
    }
    __syncthreads();
  }

  if constexpr (REDUCE) {
    for (int i = tid; i < 2*CO_BLK; i += NT) sRed[i] = 0.f;
    __syncthreads();
  }

  const int oy = oy0 + oy_l;
  #pragma unroll
  for (int j=0;j<CO_P;j++){
    int p = (j + co_g) & (CO_P-1);
    float v0[8], v1[8];
    #pragma unroll
    for (int u=0;u<8;u++) unpk(acc[u][j], v0[u], v1[u]);
    const int co = co_t0 + 2*p;
    if constexpr (BIAS) {
      float b0 = bias[co], b1 = bias[co+1];
      #pragma unroll
      for (int u=0;u<8;u++){ v0[u]+=b0; v1[u]+=b1; }
    }
    if constexpr (TANH_OUT) {
      #pragma unroll
      for (int u=0;u<8;u++){ v0[u]=tanhf(v0[u]); v1[u]=tanhf(v1[u]); }
    }
    float4* p0 = reinterpret_cast<float4*>(&out[((b*OUT_CB + co  )*OH + oy)*OW + ox0]);
    float4* p1 = reinterpret_cast<float4*>(&out[((b*OUT_CB + co+1)*OH + oy)*OW + ox0]);
    p0[0] = make_float4(v0[0],v0[1],v0[2],v0[3]);
    p0[1] = make_float4(v0[4],v0[5],v0[6],v0[7]);
    p1[0] = make_float4(v1[0],v1[1],v1[2],v1[3]);
    p1[1] = make_float4(v1[4],v1[5],v1[6],v1[7]);
    if constexpr (REDUCE) {
      float s0=0.f,q0=0.f,s1=0.f,q1=0.f;
      #pragma unroll
      for (int u=0;u<8;u++){ s0+=v0[u]; q0=fmaf(v0[u],v0[u],q0); s1+=v1[u]; q1=fmaf(v1[u],v1[u],q1); }
      atomicAdd(&sRed[co],          s0);
      atomicAdd(&sRed[CO_BLK+co],   q0);
      atomicAdd(&sRed[co+1],        s1);
      atomicAdd(&sRed[CO_BLK+co+1], q1);
    }
  }
  if constexpr (REDUCE) {
    __syncthreads();
    for (int i2 = tid; i2 < 2*CO_BLK; i2 += NT) {
      int off = (i2 < CO_BLK) ? 0 : OC;
      int cl  = (i2 < CO_BLK) ? i2 : (i2 - CO_BLK);
      atomicAdd(&stat[off + cl], sRed[i2]);
    }
  }
}

// =====================================================================
// Transposed conv via parity decomposition. Row cache: 9 values per
// (cc,dd), packed once, reused across both ee taps. COLSP padded to
// IW+4 so rows stay 16B-aligned for LDS.128.
// =====================================================================
template<int IC, int OC, int IH, int IW, int OUT_CB,
         int TILE_M, int CO_BLK, int CI_CHUNK, int NG_N, int NG_CO,
         bool ACT_IN_RELU, bool REDUCE>
__global__ void __launch_bounds__(NG_N*NG_CO*TILE_M)
deconv_kernel(const float* __restrict__ in, const float* __restrict__ wT,
              const float* __restrict__ a_in, const float* __restrict__ c_in,
              float* __restrict__ out, float* __restrict__ stat)
{
  constexpr int NT    = NG_N * NG_CO * TILE_M;
  constexpr int CO_T  = CO_BLK / NG_CO;
  constexpr int CO_P  = CO_T / 2;
  constexpr int ROWS  = TILE_M + 1;
  constexpr int COLSP = IW + 4;
  constexpr int TOTAL_IN = CI_CHUNK*ROWS*COLSP;
  constexpr int NITER = (TOTAL_IN + NT - 1)/NT;
  constexpr int WLEN4 = CI_CHUNK*4*CO_BLK/4;
  static_assert(IW / NG_N == 8, "");
  static_assert(CO_BLK == OC, "");
  static_assert((CO_P & (CO_P-1)) == 0, "");

  __shared__ __align__(16) float sIn[CI_CHUNK][ROWS][COLSP];
  __shared__ __align__(16) float sW [CI_CHUNK][4][CO_BLK];
  __shared__ float sRed[2*CO_BLK];

  const int tid    = threadIdx.x;
  const int n_g    = tid % NG_N;
  const int co_g   = (tid / NG_N) % NG_CO;
  const int m_l    = tid / (NG_N * NG_CO);
  const int m_tile = blockIdx.x;
  const int ry     = blockIdx.y >> 1, rx = blockIdx.y & 1;
  const int par    = blockIdx.y;
  const int b      = blockIdx.z;
  const int m0     = m_tile * TILE_M;
  const int n0     = n_g * 8;
  const int co_t0  = co_g * CO_T;

  int gOff[NITER]; int ccA[ACT_IN_RELU ? NITER : 1];
  #pragma unroll
  for (int i=0;i<NITER;i++){
    int idx = tid + i*NT;
    int cc  = idx / (ROWS*COLSP);
    int rem = idx % (ROWS*COLSP);
    int r   = rem / COLSP, col = rem % COLSP;
    int gy  = m0 + ry - 1 + r;
    int gx  = rx - 1 + col;
    bool ok = (idx < TOTAL_IN) && gx >= 0 && gx < IW && gy >= 0 && gy < IH;
    gOff[i] = ok ? ((b*IC + cc)*IH + gy)*IW + gx : -1;
    if constexpr (ACT_IN_RELU) ccA[i] = cc;
  }

  unsigned long long acc[8][CO_P];
  #pragma unroll
  for (int u=0;u<8;u++)
    #pragma unroll
    for (int j=0;j<CO_P;j++) acc[u][j] = 0ULL;

  float* sInF = &sIn[0][0][0];

  for (int ci0 = 0; ci0 < IC; ci0 += CI_CHUNK) {
    const int cBase = ci0*IH*IW;
    #pragma unroll
    for (int i=0;i<NITER;i++){
      int idx = tid + i*NT;
      if (idx < TOTAL_IN) {
        float v = 0.f;
        int go = gOff[i];
        if (go >= 0) {
          v = in[go + cBase];
          if constexpr (ACT_IN_RELU)
            v = fmaxf(fmaf(a_in[ci0+ccA[i]], v, c_in[ci0+ccA[i]]), 0.f);
        }
        sInF[idx] = v;
      }
    }
    {
      const float4* ws = reinterpret_cast<const float4*>(wT + (par*IC + ci0)*4*OC);
      float4* wd = reinterpret_cast<float4*>(&sW[0][0][0]);
      #pragma unroll
      for (int i = 0; i < (WLEN4 + NT - 1)/NT; i++) {
        int idx = tid + i*NT;
        if (idx < WLEN4) wd[idx] = ws[idx];
      }
    }
    __syncthreads();

    #pragma unroll
    for (int cc=0; cc<CI_CHUNK; cc++) {
      #pragma unroll
      for (int dd=0; dd<2; dd++) {
        const float* rowp = &sIn[cc][m_l + dd][0] + n0;
        unsigned long long pv[9];
        {
          const float4* rp4 = reinterpret_cast<const float4*>(rowp);
          float4 q;
          q = rp4[0]; pv[0]=pk2(q.x,q.x); pv[1]=pk2(q.y,q.y); pv[2]=pk2(q.z,q.z); pv[3]=pk2(q.w,q.w);
          q = rp4[1]; pv[4]=pk2(q.x,q.x); pv[5]=pk2(q.y,q.y); pv[6]=pk2(q.z,q.z); pv[7]=pk2(q.w,q.w);
          float c8 = rowp[8];
          pv[8]=pk2(c8,c8);
        }
        #pragma unroll
        for (int ee=0; ee<2; ee++) {
          const int t4 = dd*2 + ee;
          unsigned long long wv[CO_P];
          #pragma unroll
          for (int j=0;j<CO_P;j++){
            int p = (j + co_g) & (CO_P-1);
            wv[j] = *reinterpret_cast<const unsigned long long*>(&sW[cc][t4][co_t0 + 2*p]);
          }
          #pragma unroll
          for (int u=0;u<8;u++)
            #pragma unroll
            for (int j=0;j<CO_P;j++) fma2(acc[u][j], pv[u+ee], wv[j]);
        }
      }
    }
    __syncthreads();
  }

  if constexpr (REDUCE) {
    for (int i = tid; i < 2*CO_BLK; i += NT) sRed[i] = 0.f;
    __syncthreads();
  }

  const int oy = 2*(m0 + m_l) + ry;
  const int OW2 = 2*IW, OH2 = 2*IH;
  #pragma unroll
  for (int j=0;j<CO_P;j++){
    int p = (j + co_g) & (CO_P-1);
    const int co = co_t0 + 2*p;
    float* r0 = &out[((b*OUT_CB + co  )*OH2 + oy)*OW2 + rx];
    float* r1 = &out[((b*OUT_CB + co+1)*OH2 + oy)*OW2 + rx];
    float s0=0.f,q0=0.f,s1=0.f,q1=0.f;
    #pragma unroll
    for (int u=0;u<8;u++){
      float v0, v1; unpk(acc[u][j], v0, v1);
      r0[2*(n0+u)] = v0;
      r1[2*(n0+u)] = v1;
      if constexpr (REDUCE) { s0+=v0; q0=fmaf(v0,v0,q0); s1+=v1; q1=fmaf(v1,v1,q1); }
    }
    if constexpr (REDUCE) {
      atomicAdd(&sRed[co],          s0);
      atomicAdd(&sRed[CO_BLK+co],   q0);
      atomicAdd(&sRed[co+1],        s1);
      atomicAdd(&sRed[CO_BLK+co+1], q1);
    }
  }
  if constexpr (REDUCE) {
    __syncthreads();
    for (int i2 = tid; i2 < 2*CO_BLK; i2 += NT) {
      int off = (i2 < CO_BLK) ? 0 : OC;
      int cl  = (i2 < CO_BLK) ? i2 : (i2 - CO_BLK);
      atomicAdd(&stat[off + cl], sRed[i2]);
    }
  }
}

// =====================================================================
// Final deconv 128->3 with bias + tanh
// =====================================================================
__global__ void __launch_bounds__(128)
deconv2_kernel(const float* __restrict__ in, const float* __restrict__ w,
               const float* __restrict__ bias,
               const float* __restrict__ a_in, const float* __restrict__ c_in,
               float* __restrict__ out)
{
  constexpr int IC=128, IH=64, IW=64, TILE_M=16, CI=4, NG_N=8;
  constexpr int NT=128, ROWS=TILE_M+1, COLSP=IW+2;
  constexpr int TOTAL_IN = CI*ROWS*COLSP;
  constexpr int NITER = (TOTAL_IN + NT - 1)/NT;
  __shared__ float sIn[CI][ROWS][COLSP];
  __shared__ float sW[CI][4][4];

  const int tid = threadIdx.x;
  const int n_g = tid % NG_N;
  const int m_l = tid / NG_N;
  const int m0  = blockIdx.x * TILE_M;
  const int ry  = blockIdx.y >> 1, rx = blockIdx.y & 1;
  const int b   = blockIdx.z;
  const int n0  = n_g * 8;

  int gOff[NITER]; int ccA[NITER];
  #pragma unroll
  for (int i=0;i<NITER;i++){
    int idx = tid + i*NT;
    int cc  = idx / (ROWS*COLSP);
    int rem = idx % (ROWS*COLSP);
    int r   = rem / COLSP, col = rem % COLSP;
    int gy  = m0 + ry - 1 + r;
    int gx  = rx - 1 + col;
    bool ok = (idx < TOTAL_IN) && gx >= 0 && gx < IW && gy >= 0 && gy < IH;
    gOff[i] = ok ? ((b*IC + cc)*IH + gy)*IW + gx : -1;
    ccA[i]  = cc;
  }

  float acc[3][8];
  #pragma unroll
  for (int co=0;co<3;co++)
    #pragma unroll
    for (int u=0;u<8;u++) acc[co][u] = 0.f;

  float* sInF = &sIn[0][0][0];

  for (int ci0 = 0; ci0 < IC; ci0 += CI) {
    const int cBase = ci0*IH*IW;
    #pragma unroll
    for (int i=0;i<NITER;i++){
      int idx = tid + i*NT;
      if (idx < TOTAL_IN) {
        float v = 0.f;
        int go = gOff[i];
        if (go >= 0)
          v = fmaxf(fmaf(a_in[ci0+ccA[i]], in[go + cBase], c_in[ci0+ccA[i]]), 0.f);
        sInF[idx] = v;
      }
    }
    if (tid < 48) {
      int cc = tid / 12, t4 = (tid / 3) % 4, co = tid % 3;
      int dd = t4 >> 1, ee = t4 & 1;
      sW[cc][t4][co] = w[((ci0+cc)*3 + co)*16 + (3-ry-2*dd)*4 + (3-rx-2*ee)];
    }
    __syncthreads();

    #pragma unroll
    for (int cc=0; cc<CI; cc++) {
      #pragma unroll
      for (int t4=0;t4<4;t4++) {
        const int dd = t4 >> 1, ee = t4 & 1;
        float w0 = sW[cc][t4][0], w1 = sW[cc][t4][1], w2 = sW[cc][t4][2];
        const float* rowp = &sIn[cc][m_l + dd][0];
        #pragma unroll
        for (int u=0;u<8;u++) {
          float iv = rowp[n0 + u + ee];
          acc[0][u] = fmaf(iv, w0, acc[0][u]);
          acc[1][u] = fmaf(iv, w1, acc[1][u]);
          acc[2][u] = fmaf(iv, w2, acc[2][u]);
        }
      }
    }
    __syncthreads();
  }

  const int oy = 2*(m0 + m_l) + ry;
  #pragma unroll
  for (int co=0;co<3;co++){
    float bb = bias[co];
    float* rp = &out[((b*3 + co)*128 + oy)*128 + rx];
    #pragma unroll
    for (int u=0;u<8;u++)
      rp[2*(n0+u)] = tanhf(acc[co][u] + bb);
  }
}

// =====================================================================
__global__ void finalize_kernel(const float* __restrict__ stat, const float* __restrict__ g,
                                const float* __restrict__ be,
                                float* __restrict__ a, float* __restrict__ cv,
                                int C, float invN)
{
  int c = threadIdx.x + blockIdx.x*blockDim.x;
  if (c >= C) return;
  float mean = stat[c] * invN;
  float var  = stat[C + c] * invN - mean*mean;
  float av = g[c] * rsqrtf(var + 1e-5f);
  a[c] = av;
  cv[c] = be[c] - mean * av;
}

__global__ void zero_kernel(float* s0, float* s1, float* s2, float* s3)
{
  int t = threadIdx.x;
  if (t < 128) s0[t] = 0.f;
  if (t < 256) s1[t] = 0.f;
  if (t < 512) s2[t] = 0.f;
  if (t < 256) s3[t] = 0.f;
}

__global__ void pack_kernel(const float* __restrict__ Zl, const float* __restrict__ Zg,
                            float* __restrict__ Zbuf)
{
  int idx = blockIdx.x * 256 + threadIdx.x;
  const int nl = 64*32*256;
  if (idx < nl) {
    int b = idx / (32*256); int r = idx % (32*256);
    Zbuf[(b*168 + 64)*256 + r] = Zl[idx];
  }
  const int ng = 64*64*256;
  if (idx < ng) {
    int b = idx / (64*256); int r = idx % (64*256);
    Zbuf[(b*168 + 96)*256 + r] = Zg[idx];
  }
}

__global__ void wave_kernel(const float* __restrict__ Zg, const float* __restrict__ phi,
                            const float* __restrict__ lW, const float* __restrict__ lb,
                            const float* __restrict__ l1W, const float* __restrict__ l1b,
                            const float* __restrict__ l2W, const float* __restrict__ l2b,
                            float* __restrict__ Zbuf)
{
  const int b = blockIdx.x;
  const int t = threadIdx.x;  // 64
  __shared__ float zg[64], x[64], K[16];
  zg[t] = Zg[(b*64 + t)*256];
  __syncthreads();
  float acc = lb[t];
  #pragma unroll 8
  for (int g = 0; g < 64; g++) acc = fmaf(zg[g], lW[t*64+g], acc);
  x[t] = fmaxf(acc, 0.f);
  __syncthreads();
  if (t < 16) {
    int p = t & 7;
    const float* W  = (t < 8) ? l1W : l2W;
    const float* bb = (t < 8) ? l1b : l2b;
    float k = bb[p];
    #pragma unroll 8
    for (int h = 0; h < 64; h++) k = fmaf(x[h], W[p*64+h], k);
    K[t] = k;
  }
  __syncthreads();
  for (int idx = t; idx < 8*256; idx += 64) {
    int p = idx >> 8; int ij = idx & 255; int i = ij >> 4; int j = ij & 15;
    float wv = K[p]*(float)i + K[p+8]*(float)j + phi[b*8+p]*TWO_PI_F;
    Zbuf[(b*168 + 160 + p)*256 + ij] = sinf(wv);
  }
}

// =====================================================================
extern "C" void kernel_launch(void* const* d_in, const int* in_sizes, int n_in,
                              void* d_out, int out_size)
{
  const float* Zl   = (const float*)d_in[0];
  const float* Zg   = (const float*)d_in[1];
  const float* imgs = (const float*)d_in[2];
  const float* phi  = (const float*)d_in[3];
  const float* lW   = (const float*)d_in[4];
  const float* lb   = (const float*)d_in[5];
  const float* l1W  = (const float*)d_in[6];
  const float* l1b  = (const float*)d_in[7];
  const float* l2W  = (const float*)d_in[8];
  const float* l2b  = (const float*)d_in[9];
  const float* cw0  = (const float*)d_in[10];
  const float* cg0  = (const float*)d_in[12];
  const float* cbe0 = (const float*)d_in[13];
  const float* cw1  = (const float*)d_in[14];
  const float* cg1  = (const float*)d_in[16];
  const float* cbe1 = (const float*)d_in[17];
  const float* cw2  = (const float*)d_in[18];
  const float* cb2  = (const float*)d_in[19];
  const float* gw0  = (const float*)d_in[20];
  const float* gg0  = (const float*)d_in[22];
  const float* gbe0 = (const float*)d_in[23];
  const float* gw1  = (const float*)d_in[24];
  const float* gg1  = (const float*)d_in[26];
  const float* gbe1 = (const float*)d_in[27];
  const float* gw2  = (const float*)d_in[28];
  const float* gb2  = (const float*)d_in[29];
  float* out = (float*)d_out;

  float *h0,*h1,*Zb,*g0,*g1;
  float *s0,*s1,*s2,*s3;
  float *a0,*c0,*a1,*c1,*a2,*c2,*a3,*c3;
  float *wTc0,*wTc1,*wTc2,*wTd0,*wTd1;
  cudaGetSymbolAddress((void**)&h0, d_h0);
  cudaGetSymbolAddress((void**)&h1, d_h1);
  cudaGetSymbolAddress((void**)&Zb, d_Zbuf);
  cudaGetSymbolAddress((void**)&g0, d_g0);
  cudaGetSymbolAddress((void**)&g1, d_g1);
  cudaGetSymbolAddress((void**)&s0, d_stat0);
  cudaGetSymbolAddress((void**)&s1, d_stat1);
  cudaGetSymbolAddress((void**)&s2, d_stat2);
  cudaGetSymbolAddress((void**)&s3, d_stat3);
  cudaGetSymbolAddress((void**)&a0, d_a0); cudaGetSymbolAddress((void**)&c0, d_c0);
  cudaGetSymbolAddress((void**)&a1, d_a1); cudaGetSymbolAddress((void**)&c1, d_c1);
  cudaGetSymbolAddress((void**)&a2, d_a2); cudaGetSymbolAddress((void**)&c2, d_c2);
  cudaGetSymbolAddress((void**)&a3, d_a3); cudaGetSymbolAddress((void**)&c3, d_c3);
  cudaGetSymbolAddress((void**)&wTc0, d_wTc0);
  cudaGetSymbolAddress((void**)&wTc1, d_wTc1);
  cudaGetSymbolAddress((void**)&wTc2, d_wTc2);
  cudaGetSymbolAddress((void**)&wTd0, d_wTd0);
  cudaGetSymbolAddress((void**)&wTd1, d_wTd1);

  zero_kernel<<<1,512>>>(s0, s1, s2, s3);                          // 0
  transpose_convs<<<512,256>>>(cw0, wTc0, cw1, wTc1, cw2, wTc2);   // 1
  transpose_deconvs<<<2688,256>>>(gw0, wTd0, gw1, wTd1);           // 2

  // encoder (stats fused) — conv0 at capture index 3
  conv_s2_kernel<3,64,128,128,64,64, 64, 4,64,3,8,8, false,false,false,true>
      <<<dim3(16,1,64),256>>>(imgs, wTc0, nullptr, nullptr, nullptr, h0, s0);  // 3
  finalize_kernel<<<1,64>>>(s0, cg0, cbe0, a0, c0, 64, 1.f/(64.f*4096.f));
  conv_s2_kernel<64,128,64,64,32,32, 128, 4,128,2,4,16, true,false,false,true>
      <<<dim3(8,1,64),256>>>(h0, wTc1, nullptr, a0, c0, h1, s1);
  finalize_kernel<<<1,128>>>(s1, cg1, cbe1, a1, c1, 128, 1.f/(64.f*1024.f));
  conv_s2_kernel<128,64,32,32,16,16, 168, 8,64,4,2,16, true,true,true,false>
      <<<dim3(2,1,64),256>>>(h1, wTc2, cb2, a1, c1, Zb, nullptr);

  pack_kernel<<<4096,256>>>(Zl, Zg, Zb);
  wave_kernel<<<64,64>>>(Zg, phi, lW, lb, l1W, l1b, l2W, l2b, Zb);

  // generator (stats fused)
  deconv_kernel<168,256,16,16, 256, 4,256,8,2,32, false,true>
      <<<dim3(4,4,64),256>>>(Zb, wTd0, nullptr, nullptr, g0, s2);
  finalize_kernel<<<1,256>>>(s2, gg0, gbe0, a2, c2, 256, 1.f/(64.f*1024.f));
  deconv_kernel<256,128,32,32, 128, 8,128,8,4,16, true,true>
      <<<dim3(4,4,64),512>>>(g0, wTd1, a2, c2, g1, s3);
  finalize_kernel<<<1,128>>>(s3, gg1, gbe1, a3, c3, 128, 1.f/(64.f*4096.f));
  deconv2_kernel<<<dim3(4,4,64),128>>>(g1, gw2, gb2, a3, c3, out);
}

// round 11
// speedup vs baseline: 1.0298x; 1.0298x over previous
#include <cuda_runtime.h>
#include <math.h>

#define TWO_PI_F 6.2831853071795864769f

// ---------------- device scratch ----------------
__device__ float d_h0[64*64*64*64];
__device__ float d_h1[64*128*32*32];
__device__ float d_Zbuf[64*168*16*16];
__device__ float d_g0[64*256*32*32];
__device__ float d_g1[64*128*64*64];
__device__ float d_stat0[128];
__device__ float d_stat1[256];
__device__ float d_stat2[512];
__device__ float d_stat3[256];
__device__ float d_a0[64],  d_c0[64];
__device__ float d_a1[128], d_c1[128];
__device__ float d_a2[256], d_c2[256];
__device__ float d_a3[128], d_c3[128];
__device__ float d_wTc0[3*16*64];
__device__ float d_wTc1[64*16*128];
__device__ float d_wTc2[128*16*64];
__device__ float d_wTd0[4*168*4*256];
__device__ float d_wTd1[4*256*4*128];

// ---------------- packed f32x2 helpers ----------------
__device__ __forceinline__ unsigned long long pk2(float lo, float hi){
  unsigned long long r; asm("mov.b64 %0, {%1, %2};" : "=l"(r) : "f"(lo), "f"(hi)); return r;
}
__device__ __forceinline__ void fma2(unsigned long long& d, unsigned long long a, unsigned long long b){
  asm("fma.rn.f32x2 %0, %1, %2, %0;" : "+l"(d) : "l"(a), "l"(b));
}
__device__ __forceinline__ void unpk(unsigned long long v, float& lo, float& hi){
  asm("mov.b64 {%0, %1}, %2;" : "=f"(lo), "=f"(hi) : "l"(v));
}

// =====================================================================
// Weight transposes
// =====================================================================
__device__ __forceinline__ void tconv(const float* __restrict__ w, float* __restrict__ wT,
                                      int IC, int OC, int idx){
  int k = idx % 16; int ci = (idx/16) % IC; int co = idx/(16*IC);
  wT[(ci*16+k)*OC + co] = w[idx];
}
__device__ __forceinline__ void tdec(const float* __restrict__ w, float* __restrict__ wT,
                                     int IC, int OC, int idx){
  int kk = idx%16; int co = (idx/16)%OC; int ci = idx/(16*OC);
  int ky=kk>>2, kx=kk&3;
  int ry=(3-ky)&1, dd=(3-ky-ry)>>1;
  int rx=(3-kx)&1, ee=(3-kx-rx)>>1;
  wT[(((ry*2+rx)*IC+ci)*4 + dd*2+ee)*OC + co] = w[idx];
}
__global__ void transpose_convs(const float* w0, float* o0, const float* w1, float* o1,
                                const float* w2, float* o2){
  int idx = blockIdx.x*256 + threadIdx.x;
  if (idx < 3*64*16)   tconv(w0,o0,3,64,idx);
  if (idx < 64*128*16) tconv(w1,o1,64,128,idx);
  if (idx < 128*64*16) tconv(w2,o2,128,64,idx);
}
__global__ void transpose_deconvs(const float* w0, float* o0, const float* w1, float* o1){
  int idx = blockIdx.x*256+threadIdx.x;
  if (idx < 168*256*16) tdec(w0,o0,168,256,idx);
  if (idx < 256*128*16) tdec(w1,o1,256,128,idx);
}

// =====================================================================
// Strided conv k=4 s=2 p=1. Row register-cache when CO_P<=4 (reg-safe),
// direct loads otherwise.
// =====================================================================
template<int IC, int OC, int IH, int IW, int OH, int OW, int OUT_CB,
         int TILE_OY, int CO_BLK, int CI_CHUNK, int NG_OX, int NG_CO,
         bool ACT_IN_LRELU, bool BIAS, bool TANH_OUT, bool REDUCE>
__global__ void __launch_bounds__(NG_CO*NG_OX*TILE_OY)
conv_s2_kernel(const float* __restrict__ in, const float* __restrict__ wT,
               const float* __restrict__ bias,
               const float* __restrict__ a_in, const float* __restrict__ c_in,
               float* __restrict__ out, float* __restrict__ stat)
{
  constexpr int NT    = NG_CO * NG_OX * TILE_OY;
  constexpr int CO_T  = CO_BLK / NG_CO;
  constexpr int CO_P  = CO_T / 2;
  constexpr int ROWS  = 2*TILE_OY + 2;
  constexpr int COLSP = IW + 4;
  constexpr int TOTAL_IN = CI_CHUNK*ROWS*COLSP;
  constexpr int NITER = (TOTAL_IN + NT - 1)/NT;
  constexpr int WLEN4 = CI_CHUNK*16*CO_BLK/4;
  static_assert(OW / NG_OX == 8, "");
  static_assert(CO_BLK == OC, "");
  static_assert((CO_P & (CO_P-1)) == 0, "");

  __shared__ __align__(16) float sIn[CI_CHUNK][ROWS][COLSP];
  __shared__ __align__(16) float sW [CI_CHUNK][16][CO_BLK];
  __shared__ float sRed[2*CO_BLK];

  const int tid   = threadIdx.x;
  const int co_g  = tid % NG_CO;
  const int ox_g  = (tid / NG_CO) % NG_OX;
  const int oy_l  = tid / (NG_CO * NG_OX);
  const int b     = blockIdx.z;
  const int oy0   = blockIdx.x * TILE_OY;
  const int iy0   = 2*oy0 - 1;
  const int ox0   = ox_g * 8;
  const int co_t0 = co_g * CO_T;

  int gOff[NITER]; int ccA[ACT_IN_LRELU ? NITER : 1];
  #pragma unroll
  for (int i=0;i<NITER;i++){
    int idx = tid + i*NT;
    int cc  = idx / (ROWS*COLSP);
    int rem = idx % (ROWS*COLSP);
    int r   = rem / COLSP, col = rem % COLSP;
    int iy  = iy0 + r, ix = col - 1;
    bool ok = (idx < TOTAL_IN) && ix >= 0 && ix < IW && iy >= 0 && iy < IH;
    gOff[i] = ok ? ((b*IC + cc)*IH + iy)*IW + ix : -1;
    if constexpr (ACT_IN_LRELU) ccA[i] = cc;
  }

  unsigned long long acc[8][CO_P];
  #pragma unroll
  for (int u=0;u<8;u++)
    #pragma unroll
    for (int j=0;j<CO_P;j++) acc[u][j] = 0ULL;

  float* sInF = &sIn[0][0][0];

  for (int ci0 = 0; ci0 < IC; ci0 += CI_CHUNK) {
    const int cBase = ci0*IH*IW;
    #pragma unroll
    for (int i=0;i<NITER;i++){
      int idx = tid + i*NT;
      if (idx < TOTAL_IN) {
        float v = 0.f;
        int go = gOff[i];
        if (go >= 0) {
          v = in[go + cBase];
          if constexpr (ACT_IN_LRELU) {
            float t = fmaf(a_in[ci0+ccA[i]], v, c_in[ci0+ccA[i]]);
            v = t > 0.f ? t : 0.2f*t;
          }
        }
        sInF[idx] = v;
      }
    }
    {
      const float4* ws = reinterpret_cast<const float4*>(wT + ci0*16*OC);
      float4* wd = reinterpret_cast<float4*>(&sW[0][0][0]);
      #pragma unroll
      for (int i = 0; i < (WLEN4 + NT - 1)/NT; i++) {
        int idx = tid + i*NT;
        if (idx < WLEN4) wd[idx] = ws[idx];
      }
    }
    __syncthreads();

    #pragma unroll
    for (int cc=0; cc<CI_CHUNK; cc++) {
      if constexpr (CO_P <= 4) {
        // row register-cache: 18 values per (cc,ky), reused across 4 kx
        #pragma unroll
        for (int ky=0; ky<4; ky++) {
          const float* rowp = &sIn[cc][2*oy_l + ky][0] + 2*ox0;
          unsigned long long pv[18];
          {
            const float4* rp4 = reinterpret_cast<const float4*>(rowp);
            float4 q;
            q = rp4[0]; pv[0]=pk2(q.x,q.x); pv[1]=pk2(q.y,q.y); pv[2]=pk2(q.z,q.z); pv[3]=pk2(q.w,q.w);
            q = rp4[1]; pv[4]=pk2(q.x,q.x); pv[5]=pk2(q.y,q.y); pv[6]=pk2(q.z,q.z); pv[7]=pk2(q.w,q.w);
            q = rp4[2]; pv[8]=pk2(q.x,q.x); pv[9]=pk2(q.y,q.y); pv[10]=pk2(q.z,q.z); pv[11]=pk2(q.w,q.w);
            q = rp4[3]; pv[12]=pk2(q.x,q.x); pv[13]=pk2(q.y,q.y); pv[14]=pk2(q.z,q.z); pv[15]=pk2(q.w,q.w);
            float2 q2 = *reinterpret_cast<const float2*>(rowp + 16);
            pv[16]=pk2(q2.x,q2.x); pv[17]=pk2(q2.y,q2.y);
          }
          #pragma unroll
          for (int kx=0; kx<4; kx++) {
            const int k = ky*4 + kx;
            unsigned long long wv[CO_P];
            #pragma unroll
            for (int j=0;j<CO_P;j++){
              int p = (j + co_g) & (CO_P-1);
              wv[j] = *reinterpret_cast<const unsigned long long*>(&sW[cc][k][co_t0 + 2*p]);
            }
            #pragma unroll
            for (int u=0;u<8;u++)
              #pragma unroll
              for (int j=0;j<CO_P;j++) fma2(acc[u][j], pv[2*u+kx], wv[j]);
          }
        }
      } else {
        // direct loads (reg-heavy CO_P): proven round-8 form
        #pragma unroll
        for (int k=0;k<16;k++) {
          const int ky = k >> 2, kx = k & 3;
          unsigned long long wv[CO_P];
          #pragma unroll
          for (int j=0;j<CO_P;j++){
            int p = (j + co_g) & (CO_P-1);
            wv[j] = *reinterpret_cast<const unsigned long long*>(&sW[cc][k][co_t0 + 2*p]);
          }
          const float* rowp = &sIn[cc][2*oy_l + ky][0];
          #pragma unroll
          for (int u=0;u<8;u++) {
            float iv = rowp[2*(ox0+u) + kx];
            unsigned long long pv = pk2(iv, iv);
            #pragma unroll
            for (int j=0;j<CO_P;j++) fma2(acc[u][j], pv, wv[j]);
          }
        }
      }
    }
    __syncthreads();
  }

  if constexpr (REDUCE) {
    for (int i = tid; i < 2*CO_BLK; i += NT) sRed[i] = 0.f;
    __syncthreads();
  }

  const int oy = oy0 + oy_l;
  #pragma unroll
  for (int j=0;j<CO_P;j++){
    int p = (j + co_g) & (CO_P-1);
    float v0[8], v1[8];
    #pragma unroll
    for (int u=0;u<8;u++) unpk(acc[u][j], v0[u], v1[u]);
    const int co = co_t0 + 2*p;
    if constexpr (BIAS) {
      float b0 = bias[co], b1 = bias[co+1];
      #pragma unroll
      for (int u=0;u<8;u++){ v0[u]+=b0; v1[u]+=b1; }
    }
    if constexpr (TANH_OUT) {
      #pragma unroll
      for (int u=0;u<8;u++){ v0[u]=tanhf(v0[u]); v1[u]=tanhf(v1[u]); }
    }
    float4* p0 = reinterpret_cast<float4*>(&out[((b*OUT_CB + co  )*OH + oy)*OW + ox0]);
    float4* p1 = reinterpret_cast<float4*>(&out[((b*OUT_CB + co+1)*OH + oy)*OW + ox0]);
    p0[0] = make_float4(v0[0],v0[1],v0[2],v0[3]);
    p0[1] = make_float4(v0[4],v0[5],v0[6],v0[7]);
    p1[0] = make_float4(v1[0],v1[1],v1[2],v1[3]);
    p1[1] = make_float4(v1[4],v1[5],v1[6],v1[7]);
    if constexpr (REDUCE) {
      float s0=0.f,q0=0.f,s1=0.f,q1=0.f;
      #pragma unroll
      for (int u=0;u<8;u++){ s0+=v0[u]; q0=fmaf(v0[u],v0[u],q0); s1+=v1[u]; q1=fmaf(v1[u],v1[u],q1); }
      atomicAdd(&sRed[co],          s0);
      atomicAdd(&sRed[CO_BLK+co],   q0);
      atomicAdd(&sRed[co+1],        s1);
      atomicAdd(&sRed[CO_BLK+co+1], q1);
    }
  }
  if constexpr (REDUCE) {
    __syncthreads();
    for (int i2 = tid; i2 < 2*CO_BLK; i2 += NT) {
      int off = (i2 < CO_BLK) ? 0 : OC;
      int cl  = (i2 < CO_BLK) ? i2 : (i2 - CO_BLK);
      atomicAdd(&stat[off + cl], sRed[i2]);
    }
  }
}

// =====================================================================
// Transposed conv via parity decomposition. Row cache when CO_P<=4.
// =====================================================================
template<int IC, int OC, int IH, int IW, int OUT_CB,
         int TILE_M, int CO_BLK, int CI_CHUNK, int NG_N, int NG_CO,
         bool ACT_IN_RELU, bool REDUCE>
__global__ void __launch_bounds__(NG_N*NG_CO*TILE_M)
deconv_kernel(const float* __restrict__ in, const float* __restrict__ wT,
              const float* __restrict__ a_in, const float* __restrict__ c_in,
              float* __restrict__ out, float* __restrict__ stat)
{
  constexpr int NT    = NG_N * NG_CO * TILE_M;
  constexpr int CO_T  = CO_BLK / NG_CO;
  constexpr int CO_P  = CO_T / 2;
  constexpr int ROWS  = TILE_M + 1;
  constexpr int COLSP = IW + 4;
  constexpr int TOTAL_IN = CI_CHUNK*ROWS*COLSP;
  constexpr int NITER = (TOTAL_IN + NT - 1)/NT;
  constexpr int WLEN4 = CI_CHUNK*4*CO_BLK/4;
  static_assert(IW / NG_N == 8, "");
  static_assert(CO_BLK == OC, "");
  static_assert((CO_P & (CO_P-1)) == 0, "");

  __shared__ __align__(16) float sIn[CI_CHUNK][ROWS][COLSP];
  __shared__ __align__(16) float sW [CI_CHUNK][4][CO_BLK];
  __shared__ float sRed[2*CO_BLK];

  const int tid    = threadIdx.x;
  const int n_g    = tid % NG_N;
  const int co_g   = (tid / NG_N) % NG_CO;
  const int m_l    = tid / (NG_N * NG_CO);
  const int m_tile = blockIdx.x;
  const int ry     = blockIdx.y >> 1, rx = blockIdx.y & 1;
  const int par    = blockIdx.y;
  const int b      = blockIdx.z;
  const int m0     = m_tile * TILE_M;
  const int n0     = n_g * 8;
  const int co_t0  = co_g * CO_T;

  int gOff[NITER]; int ccA[ACT_IN_RELU ? NITER : 1];
  #pragma unroll
  for (int i=0;i<NITER;i++){
    int idx = tid + i*NT;
    int cc  = idx / (ROWS*COLSP);
    int rem = idx % (ROWS*COLSP);
    int r   = rem / COLSP, col = rem % COLSP;
    int gy  = m0 + ry - 1 + r;
    int gx  = rx - 1 + col;
    bool ok = (idx < TOTAL_IN) && gx >= 0 && gx < IW && gy >= 0 && gy < IH;
    gOff[i] = ok ? ((b*IC + cc)*IH + gy)*IW + gx : -1;
    if constexpr (ACT_IN_RELU) ccA[i] = cc;
  }

  unsigned long long acc[8][CO_P];
  #pragma unroll
  for (int u=0;u<8;u++)
    #pragma unroll
    for (int j=0;j<CO_P;j++) acc[u][j] = 0ULL;

  float* sInF = &sIn[0][0][0];

  for (int ci0 = 0; ci0 < IC; ci0 += CI_CHUNK) {
    const int cBase = ci0*IH*IW;
    #pragma unroll
    for (int i=0;i<NITER;i++){
      int idx = tid + i*NT;
      if (idx < TOTAL_IN) {
        float v = 0.f;
        int go = gOff[i];
        if (go >= 0) {
          v = in[go + cBase];
          if constexpr (ACT_IN_RELU)
            v = fmaxf(fmaf(a_in[ci0+ccA[i]], v, c_in[ci0+ccA[i]]), 0.f);
        }
        sInF[idx] = v;
      }
    }
    {
      const float4* ws = reinterpret_cast<const float4*>(wT + (par*IC + ci0)*4*OC);
      float4* wd = reinterpret_cast<float4*>(&sW[0][0][0]);
      #pragma unroll
      for (int i = 0; i < (WLEN4 + NT - 1)/NT; i++) {
        int idx = tid + i*NT;
        if (idx < WLEN4) wd[idx] = ws[idx];
      }
    }
    __syncthreads();

    #pragma unroll
    for (int cc=0; cc<CI_CHUNK; cc++) {
      if constexpr (CO_P <= 4) {
        #pragma unroll
        for (int dd=0; dd<2; dd++) {
          const float* rowp = &sIn[cc][m_l + dd][0] + n0;
          unsigned long long pv[9];
          {
            const float4* rp4 = reinterpret_cast<const float4*>(rowp);
            float4 q;
            q = rp4[0]; pv[0]=pk2(q.x,q.x); pv[1]=pk2(q.y,q.y); pv[2]=pk2(q.z,q.z); pv[3]=pk2(q.w,q.w);
            q = rp4[1]; pv[4]=pk2(q.x,q.x); pv[5]=pk2(q.y,q.y); pv[6]=pk2(q.z,q.z); pv[7]=pk2(q.w,q.w);
            float c8 = rowp[8];
            pv[8]=pk2(c8,c8);
          }
          #pragma unroll
          for (int ee=0; ee<2; ee++) {
            const int t4 = dd*2 + ee;
            unsigned long long wv[CO_P];
            #pragma unroll
            for (int j=0;j<CO_P;j++){
              int p = (j + co_g) & (CO_P-1);
              wv[j] = *reinterpret_cast<const unsigned long long*>(&sW[cc][t4][co_t0 + 2*p]);
            }
            #pragma unroll
            for (int u=0;u<8;u++)
              #pragma unroll
              for (int j=0;j<CO_P;j++) fma2(acc[u][j], pv[u+ee], wv[j]);
          }
        }
      } else {
        #pragma unroll
        for (int t4=0;t4<4;t4++) {
          const int dd = t4 >> 1, ee = t4 & 1;
          unsigned long long wv[CO_P];
          #pragma unroll
          for (int j=0;j<CO_P;j++){
            int p = (j + co_g) & (CO_P-1);
            wv[j] = *reinterpret_cast<const unsigned long long*>(&sW[cc][t4][co_t0 + 2*p]);
          }
          const float* rowp = &sIn[cc][m_l + dd][0];
          #pragma unroll
          for (int u=0;u<8;u++) {
            float iv = rowp[n0 + u + ee];
            unsigned long long pv = pk2(iv, iv);
            #pragma unroll
            for (int j=0;j<CO_P;j++) fma2(acc[u][j], pv, wv[j]);
          }
        }
      }
    }
    __syncthreads();
  }

  if constexpr (REDUCE) {
    for (int i = tid; i < 2*CO_BLK; i += NT) sRed[i] = 0.f;
    __syncthreads();
  }

  const int oy = 2*(m0 + m_l) + ry;
  const int OW2 = 2*IW, OH2 = 2*IH;
  #pragma unroll
  for (int j=0;j<CO_P;j++){
    int p = (j + co_g) & (CO_P-1);
    const int co = co_t0 + 2*p;
    float* r0 = &out[((b*OUT_CB + co  )*OH2 + oy)*OW2 + rx];
    float* r1 = &out[((b*OUT_CB + co+1)*OH2 + oy)*OW2 + rx];
    float s0=0.f,q0=0.f,s1=0.f,q1=0.f;
    #pragma unroll
    for (int u=0;u<8;u++){
      float v0, v1; unpk(acc[u][j], v0, v1);
      r0[2*(n0+u)] = v0;
      r1[2*(n0+u)] = v1;
      if constexpr (REDUCE) { s0+=v0; q0=fmaf(v0,v0,q0); s1+=v1; q1=fmaf(v1,v1,q1); }
    }
    if constexpr (REDUCE) {
      atomicAdd(&sRed[co],          s0);
      atomicAdd(&sRed[CO_BLK+co],   q0);
      atomicAdd(&sRed[co+1],        s1);
      atomicAdd(&sRed[CO_BLK+co+1], q1);
    }
  }
  if constexpr (REDUCE) {
    __syncthreads();
    for (int i2 = tid; i2 < 2*CO_BLK; i2 += NT) {
      int off = (i2 < CO_BLK) ? 0 : OC;
      int cl  = (i2 < CO_BLK) ? i2 : (i2 - CO_BLK);
      atomicAdd(&stat[off + cl], sRed[i2]);
    }
  }
}

// =====================================================================
// Final deconv 128->3 with bias + tanh
// =====================================================================
__global__ void __launch_bounds__(128)
deconv2_kernel(const float* __restrict__ in, const float* __restrict__ w,
               const float* __restrict__ bias,
               const float* __restrict__ a_in, const float* __restrict__ c_in,
               float* __restrict__ out)
{
  constexpr int IC=128, IH=64, IW=64, TILE_M=16, CI=4, NG_N=8;
  constexpr int NT=128, ROWS=TILE_M+1, COLSP=IW+2;
  constexpr int TOTAL_IN = CI*ROWS*COLSP;
  constexpr int NITER = (TOTAL_IN + NT - 1)/NT;
  __shared__ float sIn[CI][ROWS][COLSP];
  __shared__ float sW[CI][4][4];

  const int tid = threadIdx.x;
  const int n_g = tid % NG_N;
  const int m_l = tid / NG_N;
  const int m0  = blockIdx.x * TILE_M;
  const int ry  = blockIdx.y >> 1, rx = blockIdx.y & 1;
  const int b   = blockIdx.z;
  const int n0  = n_g * 8;

  int gOff[NITER]; int ccA[NITER];
  #pragma unroll
  for (int i=0;i<NITER;i++){
    int idx = tid + i*NT;
    int cc  = idx / (ROWS*COLSP);
    int rem = idx % (ROWS*COLSP);
    int r   = rem / COLSP, col = rem % COLSP;
    int gy  = m0 + ry - 1 + r;
    int gx  = rx - 1 + col;
    bool ok = (idx < TOTAL_IN) && gx >= 0 && gx < IW && gy >= 0 && gy < IH;
    gOff[i] = ok ? ((b*IC + cc)*IH + gy)*IW + gx : -1;
    ccA[i]  = cc;
  }

  float acc[3][8];
  #pragma unroll
  for (int co=0;co<3;co++)
    #pragma unroll
    for (int u=0;u<8;u++) acc[co][u] = 0.f;

  float* sInF = &sIn[0][0][0];

  for (int ci0 = 0; ci0 < IC; ci0 += CI) {
    const int cBase = ci0*IH*IW;
    #pragma unroll
    for (int i=0;i<NITER;i++){
      int idx = tid + i*NT;
      if (idx < TOTAL_IN) {
        float v = 0.f;
        int go = gOff[i];
        if (go >= 0)
          v = fmaxf(fmaf(a_in[ci0+ccA[i]], in[go + cBase], c_in[ci0+ccA[i]]), 0.f);
        sInF[idx] = v;
      }
    }
    if (tid < 48) {
      int cc = tid / 12, t4 = (tid / 3) % 4, co = tid % 3;
      int dd = t4 >> 1, ee = t4 & 1;
      sW[cc][t4][co] = w[((ci0+cc)*3 + co)*16 + (3-ry-2*dd)*4 + (3-rx-2*ee)];
    }
    __syncthreads();

    #pragma unroll
    for (int cc=0; cc<CI; cc++) {
      #pragma unroll
      for (int t4=0;t4<4;t4++) {
        const int dd = t4 >> 1, ee = t4 & 1;
        float w0 = sW[cc][t4][0], w1 = sW[cc][t4][1], w2 = sW[cc][t4][2];
        const float* rowp = &sIn[cc][m_l + dd][0];
        #pragma unroll
        for (int u=0;u<8;u++) {
          float iv = rowp[n0 + u + ee];
          acc[0][u] = fmaf(iv, w0, acc[0][u]);
          acc[1][u] = fmaf(iv, w1, acc[1][u]);
          acc[2][u] = fmaf(iv, w2, acc[2][u]);
        }
      }
    }
    __syncthreads();
  }

  const int oy = 2*(m0 + m_l) + ry;
  #pragma unroll
  for (int co=0;co<3;co++){
    float bb = bias[co];
    float* rp = &out[((b*3 + co)*128 + oy)*128 + rx];
    #pragma unroll
    for (int u=0;u<8;u++)
      rp[2*(n0+u)] = tanhf(acc[co][u] + bb);
  }
}

// =====================================================================
__global__ void finalize_kernel(const float* __restrict__ stat, const float* __restrict__ g,
                                const float* __restrict__ be,
                                float* __restrict__ a, float* __restrict__ cv,
                                int C, float invN)
{
  int c = threadIdx.x + blockIdx.x*blockDim.x;
  if (c >= C) return;
  float mean = stat[c] * invN;
  float var  = stat[C + c] * invN - mean*mean;
  float av = g[c] * rsqrtf(var + 1e-5f);
  a[c] = av;
  cv[c] = be[c] - mean * av;
}

__global__ void zero_kernel(float* s0, float* s1, float* s2, float* s3)
{
  int t = threadIdx.x;
  if (t < 128) s0[t] = 0.f;
  if (t < 256) s1[t] = 0.f;
  if (t < 512) s2[t] = 0.f;
  if (t < 256) s3[t] = 0.f;
}

__global__ void pack_kernel(const float* __restrict__ Zl, const float* __restrict__ Zg,
                            float* __restrict__ Zbuf)
{
  int idx = blockIdx.x * 256 + threadIdx.x;
  const int nl = 64*32*256;
  if (idx < nl) {
    int b = idx / (32*256); int r = idx % (32*256);
    Zbuf[(b*168 + 64)*256 + r] = Zl[idx];
  }
  const int ng = 64*64*256;
  if (idx < ng) {
    int b = idx / (64*256); int r = idx % (64*256);
    Zbuf[(b*168 + 96)*256 + r] = Zg[idx];
  }
}

__global__ void wave_kernel(const float* __restrict__ Zg, const float* __restrict__ phi,
                            const float* __restrict__ lW, const float* __restrict__ lb,
                            const float* __restrict__ l1W, const float* __restrict__ l1b,
                            const float* __restrict__ l2W, const float* __restrict__ l2b,
                            float* __restrict__ Zbuf)
{
  const int b = blockIdx.x;
  const int t = threadIdx.x;  // 64
  __shared__ float zg[64], x[64], K[16];
  zg[t] = Zg[(b*64 + t)*256];
  __syncthreads();
  float acc = lb[t];
  #pragma unroll 8
  for (int g = 0; g < 64; g++) acc = fmaf(zg[g], lW[t*64+g], acc);
  x[t] = fmaxf(acc, 0.f);
  __syncthreads();
  if (t < 16) {
    int p = t & 7;
    const float* W  = (t < 8) ? l1W : l2W;
    const float* bb = (t < 8) ? l1b : l2b;
    float k = bb[p];
    #pragma unroll 8
    for (int h = 0; h < 64; h++) k = fmaf(x[h], W[p*64+h], k);
    K[t] = k;
  }
  __syncthreads();
  for (int idx = t; idx < 8*256; idx += 64) {
    int p = idx >> 8; int ij = idx & 255; int i = ij >> 4; int j = ij & 15;
    float wv = K[p]*(float)i + K[p+8]*(float)j + phi[b*8+p]*TWO_PI_F;
    Zbuf[(b*168 + 160 + p)*256 + ij] = sinf(wv);
  }
}

// =====================================================================
extern "C" void kernel_launch(void* const* d_in, const int* in_sizes, int n_in,
                              void* d_out, int out_size)
{
  const float* Zl   = (const float*)d_in[0];
  const float* Zg   = (const float*)d_in[1];
  const float* imgs = (const float*)d_in[2];
  const float* phi  = (const float*)d_in[3];
  const float* lW   = (const float*)d_in[4];
  const float* lb   = (const float*)d_in[5];
  const float* l1W  = (const float*)d_in[6];
  const float* l1b  = (const float*)d_in[7];
  const float* l2W  = (const float*)d_in[8];
  const float* l2b  = (const float*)d_in[9];
  const float* cw0  = (const float*)d_in[10];
  const float* cg0  = (const float*)d_in[12];
  const float* cbe0 = (const float*)d_in[13];
  const float* cw1  = (const float*)d_in[14];
  const float* cg1  = (const float*)d_in[16];
  const float* cbe1 = (const float*)d_in[17];
  const float* cw2  = (const float*)d_in[18];
  const float* cb2  = (const float*)d_in[19];
  const float* gw0  = (const float*)d_in[20];
  const float* gg0  = (const float*)d_in[22];
  const float* gbe0 = (const float*)d_in[23];
  const float* gw1  = (const float*)d_in[24];
  const float* gg1  = (const float*)d_in[26];
  const float* gbe1 = (const float*)d_in[27];
  const float* gw2  = (const float*)d_in[28];
  const float* gb2  = (const float*)d_in[29];
  float* out = (float*)d_out;

  float *h0,*h1,*Zb,*g0,*g1;
  float *s0,*s1,*s2,*s3;
  float *a0,*c0,*a1,*c1,*a2,*c2,*a3,*c3;
  float *wTc0,*wTc1,*wTc2,*wTd0,*wTd1;
  cudaGetSymbolAddress((void**)&h0, d_h0);
  cudaGetSymbolAddress((void**)&h1, d_h1);
  cudaGetSymbolAddress((void**)&Zb, d_Zbuf);
  cudaGetSymbolAddress((void**)&g0, d_g0);
  cudaGetSymbolAddress((void**)&g1, d_g1);
  cudaGetSymbolAddress((void**)&s0, d_stat0);
  cudaGetSymbolAddress((void**)&s1, d_stat1);
  cudaGetSymbolAddress((void**)&s2, d_stat2);
  cudaGetSymbolAddress((void**)&s3, d_stat3);
  cudaGetSymbolAddress((void**)&a0, d_a0); cudaGetSymbolAddress((void**)&c0, d_c0);
  cudaGetSymbolAddress((void**)&a1, d_a1); cudaGetSymbolAddress((void**)&c1, d_c1);
  cudaGetSymbolAddress((void**)&a2, d_a2); cudaGetSymbolAddress((void**)&c2, d_c2);
  cudaGetSymbolAddress((void**)&a3, d_a3); cudaGetSymbolAddress((void**)&c3, d_c3);
  cudaGetSymbolAddress((void**)&wTc0, d_wTc0);
  cudaGetSymbolAddress((void**)&wTc1, d_wTc1);
  cudaGetSymbolAddress((void**)&wTc2, d_wTc2);
  cudaGetSymbolAddress((void**)&wTd0, d_wTd0);
  cudaGetSymbolAddress((void**)&wTd1, d_wTd1);

  zero_kernel<<<1,512>>>(s0, s1, s2, s3);                          // 0
  transpose_convs<<<512,256>>>(cw0, wTc0, cw1, wTc1, cw2, wTc2);   // 1
  transpose_deconvs<<<2688,256>>>(gw0, wTd0, gw1, wTd1);           // 2

  // encoder (stats fused)
  conv_s2_kernel<3,64,128,128,64,64, 64, 4,64,3,8,8, false,false,false,true>
      <<<dim3(16,1,64),256>>>(imgs, wTc0, nullptr, nullptr, nullptr, h0, s0);  // 3
  finalize_kernel<<<1,64>>>(s0, cg0, cbe0, a0, c0, 64, 1.f/(64.f*4096.f));
  conv_s2_kernel<64,128,64,64,32,32, 128, 8,128,2,4,8, true,false,false,true>
      <<<dim3(4,1,64),256>>>(h0, wTc1, nullptr, a0, c0, h1, s1);
  finalize_kernel<<<1,128>>>(s1, cg1, cbe1, a1, c1, 128, 1.f/(64.f*1024.f));
  conv_s2_kernel<128,64,32,32,16,16, 168, 8,64,4,2,16, true,true,true,false>
      <<<dim3(2,1,64),256>>>(h1, wTc2, cb2, a1, c1, Zb, nullptr);

  pack_kernel<<<4096,256>>>(Zl, Zg, Zb);
  wave_kernel<<<64,64>>>(Zg, phi, lW, lb, l1W, l1b, l2W, l2b, Zb);

  // generator (stats fused)
  deconv_kernel<168,256,16,16, 256, 8,256,8,2,16, false,true>
      <<<dim3(2,4,64),256>>>(Zb, wTd0, nullptr, nullptr, g0, s2);
  finalize_kernel<<<1,256>>>(s2, gg0, gbe0, a2, c2, 256, 1.f/(64.f*1024.f));
  deconv_kernel<256,128,32,32, 128, 8,128,8,4,16, true,true>
      <<<dim3(4,4,64),512>>>(g0, wTd1, a2, c2, g1, s3);
  finalize_kernel<<<1,128>>>(s3, gg1, gbe1, a3, c3, 128, 1.f/(64.f*4096.f));
  deconv2_kernel<<<dim3(4,4,64),128>>>(g1, gw2, gb2, a3, c3, out);
}

// round 12
// speedup vs baseline: 1.0682x; 1.0373x over previous
#include <cuda_runtime.h>
#include <math.h>

#define TWO_PI_F 6.2831853071795864769f

// ---------------- device scratch ----------------
__device__ float d_h0[64*64*64*64];
__device__ float d_h1[64*128*32*32];
__device__ float d_Zbuf[64*168*16*16];
__device__ float d_g0[64*256*32*32];
__device__ float d_g1[64*128*64*64];
__device__ float d_stat0[128];
__device__ float d_stat1[256];
__device__ float d_stat2[512];
__device__ float d_stat3[256];
__device__ float d_a0[64],  d_c0[64];
__device__ float d_a1[128], d_c1[128];
__device__ float d_a2[256], d_c2[256];
__device__ float d_a3[128], d_c3[128];
__device__ float d_wTc0[3*16*64];
__device__ float d_wTc1[64*16*128];
__device__ float d_wTc2[128*16*64];
__device__ float d_wTd0[4*168*4*256];
__device__ float d_wTd1[4*256*4*128];

// ---------------- packed f32x2 helpers ----------------
__device__ __forceinline__ unsigned long long pk2(float lo, float hi){
  unsigned long long r; asm("mov.b64 %0, {%1, %2};" : "=l"(r) : "f"(lo), "f"(hi)); return r;
}
__device__ __forceinline__ void fma2(unsigned long long& d, unsigned long long a, unsigned long long b){
  asm("fma.rn.f32x2 %0, %1, %2, %0;" : "+l"(d) : "l"(a), "l"(b));
}
__device__ __forceinline__ void unpk(unsigned long long v, float& lo, float& hi){
  asm("mov.b64 {%0, %1}, %2;" : "=f"(lo), "=f"(hi) : "l"(v));
}

// =====================================================================
// Weight transposes
// =====================================================================
__device__ __forceinline__ void tconv(const float* __restrict__ w, float* __restrict__ wT,
                                      int IC, int OC, int idx){
  int k = idx % 16; int ci = (idx/16) % IC; int co = idx/(16*IC);
  wT[(ci*16+k)*OC + co] = w[idx];
}
__device__ __forceinline__ void tdec(const float* __restrict__ w, float* __restrict__ wT,
                                     int IC, int OC, int idx){
  int kk = idx%16; int co = (idx/16)%OC; int ci = idx/(16*OC);
  int ky=kk>>2, kx=kk&3;
  int ry=(3-ky)&1, dd=(3-ky-ry)>>1;
  int rx=(3-kx)&1, ee=(3-kx-rx)>>1;
  wT[(((ry*2+rx)*IC+ci)*4 + dd*2+ee)*OC + co] = w[idx];
}
__global__ void transpose_convs(const float* w0, float* o0, const float* w1, float* o1,
                                const float* w2, float* o2){
  int idx = blockIdx.x*256 + threadIdx.x;
  if (idx < 3*64*16)   tconv(w0,o0,3,64,idx);
  if (idx < 64*128*16) tconv(w1,o1,64,128,idx);
  if (idx < 128*64*16) tconv(w2,o2,128,64,idx);
}
__global__ void transpose_deconvs(const float* w0, float* o0, const float* w1, float* o1){
  int idx = blockIdx.x*256+threadIdx.x;
  if (idx < 168*256*16) tdec(w0,o0,168,256,idx);
  if (idx < 256*128*16) tdec(w1,o1,256,128,idx);
}

// =====================================================================
// Strided conv k=4 s=2 p=1. ROWCACHE only where regs allow (CO_P small).
// =====================================================================
template<int IC, int OC, int IH, int IW, int OH, int OW, int OUT_CB,
         int TILE_OY, int CO_BLK, int CI_CHUNK, int NG_OX, int NG_CO,
         bool ROWCACHE, bool ACT_IN_LRELU, bool BIAS, bool TANH_OUT, bool REDUCE>
__global__ void __launch_bounds__(NG_CO*NG_OX*TILE_OY)
conv_s2_kernel(const float* __restrict__ in, const float* __restrict__ wT,
               const float* __restrict__ bias,
               const float* __restrict__ a_in, const float* __restrict__ c_in,
               float* __restrict__ out, float* __restrict__ stat)
{
  constexpr int NT    = NG_CO * NG_OX * TILE_OY;
  constexpr int CO_T  = CO_BLK / NG_CO;
  constexpr int CO_P  = CO_T / 2;
  constexpr int ROWS  = 2*TILE_OY + 2;
  constexpr int COLSP = IW + 4;
  constexpr int TOTAL_IN = CI_CHUNK*ROWS*COLSP;
  constexpr int NITER = (TOTAL_IN + NT - 1)/NT;
  constexpr int WLEN4 = CI_CHUNK*16*CO_BLK/4;
  static_assert(OW / NG_OX == 8, "");
  static_assert(CO_BLK == OC, "");
  static_assert((CO_P & (CO_P-1)) == 0, "");
  static_assert(!ROWCACHE || CO_P <= 4, "");

  __shared__ __align__(16) float sIn[CI_CHUNK][ROWS][COLSP];
  __shared__ __align__(16) float sW [CI_CHUNK][16][CO_BLK];
  __shared__ float sRed[2*CO_BLK];

  const int tid   = threadIdx.x;
  const int co_g  = tid % NG_CO;
  const int ox_g  = (tid / NG_CO) % NG_OX;
  const int oy_l  = tid / (NG_CO * NG_OX);
  const int b     = blockIdx.z;
  const int oy0   = blockIdx.x * TILE_OY;
  const int iy0   = 2*oy0 - 1;
  const int ox0   = ox_g * 8;
  const int co_t0 = co_g * CO_T;

  int gOff[NITER]; int ccA[ACT_IN_LRELU ? NITER : 1];
  #pragma unroll
  for (int i=0;i<NITER;i++){
    int idx = tid + i*NT;
    int cc  = idx / (ROWS*COLSP);
    int rem = idx % (ROWS*COLSP);
    int r   = rem / COLSP, col = rem % COLSP;
    int iy  = iy0 + r, ix = col - 1;
    bool ok = (idx < TOTAL_IN) && ix >= 0 && ix < IW && iy >= 0 && iy < IH;
    gOff[i] = ok ? ((b*IC + cc)*IH + iy)*IW + ix : -1;
    if constexpr (ACT_IN_LRELU) ccA[i] = cc;
  }

  unsigned long long acc[8][CO_P];
  #pragma unroll
  for (int u=0;u<8;u++)
    #pragma unroll
    for (int j=0;j<CO_P;j++) acc[u][j] = 0ULL;

  float* sInF = &sIn[0][0][0];

  for (int ci0 = 0; ci0 < IC; ci0 += CI_CHUNK) {
    const int cBase = ci0*IH*IW;
    #pragma unroll
    for (int i=0;i<NITER;i++){
      int idx = tid + i*NT;
      if (idx < TOTAL_IN) {
        float v = 0.f;
        int go = gOff[i];
        if (go >= 0) {
          v = in[go + cBase];
          if constexpr (ACT_IN_LRELU) {
            float t = fmaf(a_in[ci0+ccA[i]], v, c_in[ci0+ccA[i]]);
            v = t > 0.f ? t : 0.2f*t;
          }
        }
        sInF[idx] = v;
      }
    }
    {
      const float4* ws = reinterpret_cast<const float4*>(wT + ci0*16*OC);
      float4* wd = reinterpret_cast<float4*>(&sW[0][0][0]);
      #pragma unroll
      for (int i = 0; i < (WLEN4 + NT - 1)/NT; i++) {
        int idx = tid + i*NT;
        if (idx < WLEN4) wd[idx] = ws[idx];
      }
    }
    __syncthreads();

    #pragma unroll
    for (int cc=0; cc<CI_CHUNK; cc++) {
      if constexpr (ROWCACHE) {
        #pragma unroll
        for (int ky=0; ky<4; ky++) {
          const float* rowp = &sIn[cc][2*oy_l + ky][0] + 2*ox0;
          unsigned long long pv[18];
          {
            const float4* rp4 = reinterpret_cast<const float4*>(rowp);
            float4 q;
            q = rp4[0]; pv[0]=pk2(q.x,q.x); pv[1]=pk2(q.y,q.y); pv[2]=pk2(q.z,q.z); pv[3]=pk2(q.w,q.w);
            q = rp4[1]; pv[4]=pk2(q.x,q.x); pv[5]=pk2(q.y,q.y); pv[6]=pk2(q.z,q.z); pv[7]=pk2(q.w,q.w);
            q = rp4[2]; pv[8]=pk2(q.x,q.x); pv[9]=pk2(q.y,q.y); pv[10]=pk2(q.z,q.z); pv[11]=pk2(q.w,q.w);
            q = rp4[3]; pv[12]=pk2(q.x,q.x); pv[13]=pk2(q.y,q.y); pv[14]=pk2(q.z,q.z); pv[15]=pk2(q.w,q.w);
            float2 q2 = *reinterpret_cast<const float2*>(rowp + 16);
            pv[16]=pk2(q2.x,q2.x); pv[17]=pk2(q2.y,q2.y);
          }
          #pragma unroll
          for (int kx=0; kx<4; kx++) {
            const int k = ky*4 + kx;
            unsigned long long wv[CO_P];
            #pragma unroll
            for (int j=0;j<CO_P;j++){
              int p = (j + co_g) & (CO_P-1);
              wv[j] = *reinterpret_cast<const unsigned long long*>(&sW[cc][k][co_t0 + 2*p]);
            }
            #pragma unroll
            for (int u=0;u<8;u++)
              #pragma unroll
              for (int j=0;j<CO_P;j++) fma2(acc[u][j], pv[2*u+kx], wv[j]);
          }
        }
      } else {
        #pragma unroll
        for (int k=0;k<16;k++) {
          const int ky = k >> 2, kx = k & 3;
          unsigned long long wv[CO_P];
          #pragma unroll
          for (int j=0;j<CO_P;j++){
            int p = (j + co_g) & (CO_P-1);
            wv[j] = *reinterpret_cast<const unsigned long long*>(&sW[cc][k][co_t0 + 2*p]);
          }
          const float* rowp = &sIn[cc][2*oy_l + ky][0];
          #pragma unroll
          for (int u=0;u<8;u++) {
            float iv = rowp[2*(ox0+u) + kx];
            unsigned long long pv = pk2(iv, iv);
            #pragma unroll
            for (int j=0;j<CO_P;j++) fma2(acc[u][j], pv, wv[j]);
          }
        }
      }
    }
    __syncthreads();
  }

  if constexpr (REDUCE) {
    for (int i = tid; i < 2*CO_BLK; i += NT) sRed[i] = 0.f;
    __syncthreads();
  }

  const int oy = oy0 + oy_l;
  #pragma unroll
  for (int j=0;j<CO_P;j++){
    int p = (j + co_g) & (CO_P-1);
    float v0[8], v1[8];
    #pragma unroll
    for (int u=0;u<8;u++) unpk(acc[u][j], v0[u], v1[u]);
    const int co = co_t0 + 2*p;
    if constexpr (BIAS) {
      float b0 = bias[co], b1 = bias[co+1];
      #pragma unroll
      for (int u=0;u<8;u++){ v0[u]+=b0; v1[u]+=b1; }
    }
    if constexpr (TANH_OUT) {
      #pragma unroll
      for (int u=0;u<8;u++){ v0[u]=tanhf(v0[u]); v1[u]=tanhf(v1[u]); }
    }
    float4* p0 = reinterpret_cast<float4*>(&out[((b*OUT_CB + co  )*OH + oy)*OW + ox0]);
    float4* p1 = reinterpret_cast<float4*>(&out[((b*OUT_CB + co+1)*OH + oy)*OW + ox0]);
    p0[0] = make_float4(v0[0],v0[1],v0[2],v0[3]);
    p0[1] = make_float4(v0[4],v0[5],v0[6],v0[7]);
    p1[0] = make_float4(v1[0],v1[1],v1[2],v1[3]);
    p1[1] = make_float4(v1[4],v1[5],v1[6],v1[7]);
    if constexpr (REDUCE) {
      float s0=0.f,q0=0.f,s1=0.f,q1=0.f;
      #pragma unroll
      for (int u=0;u<8;u++){ s0+=v0[u]; q0=fmaf(v0[u],v0[u],q0); s1+=v1[u]; q1=fmaf(v1[u],v1[u],q1); }
      atomicAdd(&sRed[co],          s0);
      atomicAdd(&sRed[CO_BLK+co],   q0);
      atomicAdd(&sRed[co+1],        s1);
      atomicAdd(&sRed[CO_BLK+co+1], q1);
    }
  }
  if constexpr (REDUCE) {
    __syncthreads();
    for (int i2 = tid; i2 < 2*CO_BLK; i2 += NT) {
      int off = (i2 < CO_BLK) ? 0 : OC;
      int cl  = (i2 < CO_BLK) ? i2 : (i2 - CO_BLK);
      atomicAdd(&stat[off + cl], sRed[i2]);
    }
  }
}

// =====================================================================
// Transposed conv k=4 s=2 p=1 via parity decomposition (R8 direct form).
// =====================================================================
template<int IC, int OC, int IH, int IW, int OUT_CB,
         int TILE_M, int CO_BLK, int CI_CHUNK, int NG_N, int NG_CO,
         bool ACT_IN_RELU, bool REDUCE>
__global__ void __launch_bounds__(NG_N*NG_CO*TILE_M)
deconv_kernel(const float* __restrict__ in, const float* __restrict__ wT,
              const float* __restrict__ a_in, const float* __restrict__ c_in,
              float* __restrict__ out, float* __restrict__ stat)
{
  constexpr int NT    = NG_N * NG_CO * TILE_M;
  constexpr int CO_T  = CO_BLK / NG_CO;
  constexpr int CO_P  = CO_T / 2;
  constexpr int ROWS  = TILE_M + 1;
  constexpr int COLSP = IW + 2;
  constexpr int TOTAL_IN = CI_CHUNK*ROWS*COLSP;
  constexpr int NITER = (TOTAL_IN + NT - 1)/NT;
  constexpr int WLEN4 = CI_CHUNK*4*CO_BLK/4;
  static_assert(IW / NG_N == 8, "");
  static_assert(CO_BLK == OC, "");
  static_assert((CO_P & (CO_P-1)) == 0, "");

  __shared__ __align__(16) float sIn[CI_CHUNK][ROWS][COLSP];
  __shared__ __align__(16) float sW [CI_CHUNK][4][CO_BLK];
  __shared__ float sRed[2*CO_BLK];

  const int tid    = threadIdx.x;
  const int n_g    = tid % NG_N;
  const int co_g   = (tid / NG_N) % NG_CO;
  const int m_l    = tid / (NG_N * NG_CO);
  const int m_tile = blockIdx.x;
  const int ry     = blockIdx.y >> 1, rx = blockIdx.y & 1;
  const int par    = blockIdx.y;
  const int b      = blockIdx.z;
  const int m0     = m_tile * TILE_M;
  const int n0     = n_g * 8;
  const int co_t0  = co_g * CO_T;

  int gOff[NITER]; int ccA[ACT_IN_RELU ? NITER : 1];
  #pragma unroll
  for (int i=0;i<NITER;i++){
    int idx = tid + i*NT;
    int cc  = idx / (ROWS*COLSP);
    int rem = idx % (ROWS*COLSP);
    int r   = rem / COLSP, col = rem % COLSP;
    int gy  = m0 + ry - 1 + r;
    int gx  = rx - 1 + col;
    bool ok = (idx < TOTAL_IN) && gx >= 0 && gx < IW && gy >= 0 && gy < IH;
    gOff[i] = ok ? ((b*IC + cc)*IH + gy)*IW + gx : -1;
    if constexpr (ACT_IN_RELU) ccA[i] = cc;
  }

  unsigned long long acc[8][CO_P];
  #pragma unroll
  for (int u=0;u<8;u++)
    #pragma unroll
    for (int j=0;j<CO_P;j++) acc[u][j] = 0ULL;

  float* sInF = &sIn[0][0][0];

  for (int ci0 = 0; ci0 < IC; ci0 += CI_CHUNK) {
    const int cBase = ci0*IH*IW;
    #pragma unroll
    for (int i=0;i<NITER;i++){
      int idx = tid + i*NT;
      if (idx < TOTAL_IN) {
        float v = 0.f;
        int go = gOff[i];
        if (go >= 0) {
          v = in[go + cBase];
          if constexpr (ACT_IN_RELU)
            v = fmaxf(fmaf(a_in[ci0+ccA[i]], v, c_in[ci0+ccA[i]]), 0.f);
        }
        sInF[idx] = v;
      }
    }
    {
      const float4* ws = reinterpret_cast<const float4*>(wT + (par*IC + ci0)*4*OC);
      float4* wd = reinterpret_cast<float4*>(&sW[0][0][0]);
      #pragma unroll
      for (int i = 0; i < (WLEN4 + NT - 1)/NT; i++) {
        int idx = tid + i*NT;
        if (idx < WLEN4) wd[idx] = ws[idx];
      }
    }
    __syncthreads();

    #pragma unroll
    for (int cc=0; cc<CI_CHUNK; cc++) {
      #pragma unroll
      for (int t4=0;t4<4;t4++) {
        const int dd = t4 >> 1, ee = t4 & 1;
        unsigned long long wv[CO_P];
        #pragma unroll
        for (int j=0;j<CO_P;j++){
          int p = (j + co_g) & (CO_P-1);
          wv[j] = *reinterpret_cast<const unsigned long long*>(&sW[cc][t4][co_t0 + 2*p]);
        }
        const float* rowp = &sIn[cc][m_l + dd][0];
        #pragma unroll
        for (int u=0;u<8;u++) {
          float iv = rowp[n0 + u + ee];
          unsigned long long pv = pk2(iv, iv);
          #pragma unroll
          for (int j=0;j<CO_P;j++) fma2(acc[u][j], pv, wv[j]);
        }
      }
    }
    __syncthreads();
  }

  if constexpr (REDUCE) {
    for (int i = tid; i < 2*CO_BLK; i += NT) sRed[i] = 0.f;
    __syncthreads();
  }

  const int oy = 2*(m0 + m_l) + ry;
  const int OW2 = 2*IW, OH2 = 2*IH;
  #pragma unroll
  for (int j=0;j<CO_P;j++){
    int p = (j + co_g) & (CO_P-1);
    const int co = co_t0 + 2*p;
    float* r0 = &out[((b*OUT_CB + co  )*OH2 + oy)*OW2 + rx];
    float* r1 = &out[((b*OUT_CB + co+1)*OH2 + oy)*OW2 + rx];
    float s0=0.f,q0=0.f,s1=0.f,q1=0.f;
    #pragma unroll
    for (int u=0;u<8;u++){
      float v0, v1; unpk(acc[u][j], v0, v1);
      r0[2*(n0+u)] = v0;
      r1[2*(n0+u)] = v1;
      if constexpr (REDUCE) { s0+=v0; q0=fmaf(v0,v0,q0); s1+=v1; q1=fmaf(v1,v1,q1); }
    }
    if constexpr (REDUCE) {
      atomicAdd(&sRed[co],          s0);
      atomicAdd(&sRed[CO_BLK+co],   q0);
      atomicAdd(&sRed[co+1],        s1);
      atomicAdd(&sRed[CO_BLK+co+1], q1);
    }
  }
  if constexpr (REDUCE) {
    __syncthreads();
    for (int i2 = tid; i2 < 2*CO_BLK; i2 += NT) {
      int off = (i2 < CO_BLK) ? 0 : OC;
      int cl  = (i2 < CO_BLK) ? i2 : (i2 - CO_BLK);
      atomicAdd(&stat[off + cl], sRed[i2]);
    }
  }
}

// =====================================================================
// Final deconv 128->3 with bias + tanh
// =====================================================================
__global__ void __launch_bounds__(128)
deconv2_kernel(const float* __restrict__ in, const float* __restrict__ w,
               const float* __restrict__ bias,
               const float* __restrict__ a_in, const float* __restrict__ c_in,
               float* __restrict__ out)
{
  constexpr int IC=128, IH=64, IW=64, TILE_M=16, CI=4, NG_N=8;
  constexpr int NT=128, ROWS=TILE_M+1, COLSP=IW+2;
  constexpr int TOTAL_IN = CI*ROWS*COLSP;
  constexpr int NITER = (TOTAL_IN + NT - 1)/NT;
  __shared__ float sIn[CI][ROWS][COLSP];
  __shared__ float sW[CI][4][4];

  const int tid = threadIdx.x;
  const int n_g = tid % NG_N;
  const int m_l = tid / NG_N;
  const int m0  = blockIdx.x * TILE_M;
  const int ry  = blockIdx.y >> 1, rx = blockIdx.y & 1;
  const int b   = blockIdx.z;
  const int n0  = n_g * 8;

  int gOff[NITER]; int ccA[NITER];
  #pragma unroll
  for (int i=0;i<NITER;i++){
    int idx = tid + i*NT;
    int cc  = idx / (ROWS*COLSP);
    int rem = idx % (ROWS*COLSP);
    int r   = rem / COLSP, col = rem % COLSP;
    int gy  = m0 + ry - 1 + r;
    int gx  = rx - 1 + col;
    bool ok = (idx < TOTAL_IN) && gx >= 0 && gx < IW && gy >= 0 && gy < IH;
    gOff[i] = ok ? ((b*IC + cc)*IH + gy)*IW + gx : -1;
    ccA[i]  = cc;
  }

  float acc[3][8];
  #pragma unroll
  for (int co=0;co<3;co++)
    #pragma unroll
    for (int u=0;u<8;u++) acc[co][u] = 0.f;

  float* sInF = &sIn[0][0][0];

  for (int ci0 = 0; ci0 < IC; ci0 += CI) {
    const int cBase = ci0*IH*IW;
    #pragma unroll
    for (int i=0;i<NITER;i++){
      int idx = tid + i*NT;
      if (idx < TOTAL_IN) {
        float v = 0.f;
        int go = gOff[i];
        if (go >= 0)
          v = fmaxf(fmaf(a_in[ci0+ccA[i]], in[go + cBase], c_in[ci0+ccA[i]]), 0.f);
        sInF[idx] = v;
      }
    }
    if (tid < 48) {
      int cc = tid / 12, t4 = (tid / 3) % 4, co = tid % 3;
      int dd = t4 >> 1, ee = t4 & 1;
      sW[cc][t4][co] = w[((ci0+cc)*3 + co)*16 + (3-ry-2*dd)*4 + (3-rx-2*ee)];
    }
    __syncthreads();

    #pragma unroll
    for (int cc=0; cc<CI; cc++) {
      #pragma unroll
      for (int t4=0;t4<4;t4++) {
        const int dd = t4 >> 1, ee = t4 & 1;
        float w0 = sW[cc][t4][0], w1 = sW[cc][t4][1], w2 = sW[cc][t4][2];
        const float* rowp = &sIn[cc][m_l + dd][0];
        #pragma unroll
        for (int u=0;u<8;u++) {
          float iv = rowp[n0 + u + ee];
          acc[0][u] = fmaf(iv, w0, acc[0][u]);
          acc[1][u] = fmaf(iv, w1, acc[1][u]);
          acc[2][u] = fmaf(iv, w2, acc[2][u]);
        }
      }
    }
    __syncthreads();
  }

  const int oy = 2*(m0 + m_l) + ry;
  #pragma unroll
  for (int co=0;co<3;co++){
    float bb = bias[co];
    float* rp = &out[((b*3 + co)*128 + oy)*128 + rx];
    #pragma unroll
    for (int u=0;u<8;u++)
      rp[2*(n0+u)] = tanhf(acc[co][u] + bb);
  }
}

// =====================================================================
__global__ void finalize_kernel(const float* __restrict__ stat, const float* __restrict__ g,
                                const float* __restrict__ be,
                                float* __restrict__ a, float* __restrict__ cv,
                                int C, float invN)
{
  int c = threadIdx.x + blockIdx.x*blockDim.x;
  if (c >= C) return;
  float mean = stat[c] * invN;
  float var  = stat[C + c] * invN - mean*mean;
  float av = g[c] * rsqrtf(var + 1e-5f);
  a[c] = av;
  cv[c] = be[c] - mean * av;
}

__global__ void zero_kernel(float* s0, float* s1, float* s2, float* s3)
{
  int t = threadIdx.x;
  if (t < 128) s0[t] = 0.f;
  if (t < 256) s1[t] = 0.f;
  if (t < 512) s2[t] = 0.f;
  if (t < 256) s3[t] = 0.f;
}

__global__ void pack_kernel(const float* __restrict__ Zl, const float* __restrict__ Zg,
                            float* __restrict__ Zbuf)
{
  int idx = blockIdx.x * 256 + threadIdx.x;
  const int nl = 64*32*256;
  if (idx < nl) {
    int b = idx / (32*256); int r = idx % (32*256);
    Zbuf[(b*168 + 64)*256 + r] = Zl[idx];
  }
  const int ng = 64*64*256;
  if (idx < ng) {
    int b = idx / (64*256); int r = idx % (64*256);
    Zbuf[(b*168 + 96)*256 + r] = Zg[idx];
  }
}

__global__ void wave_kernel(const float* __restrict__ Zg, const float* __restrict__ phi,
                            const float* __restrict__ lW, const float* __restrict__ lb,
                            const float* __restrict__ l1W, const float* __restrict__ l1b,
                            const float* __restrict__ l2W, const float* __restrict__ l2b,
                            float* __restrict__ Zbuf)
{
  const int b = blockIdx.x;
  const int t = threadIdx.x;  // 64
  __shared__ float zg[64], x[64], K[16];
  zg[t] = Zg[(b*64 + t)*256];
  __syncthreads();
  float acc = lb[t];
  #pragma unroll 8
  for (int g = 0; g < 64; g++) acc = fmaf(zg[g], lW[t*64+g], acc);
  x[t] = fmaxf(acc, 0.f);
  __syncthreads();
  if (t < 16) {
    int p = t & 7;
    const float* W  = (t < 8) ? l1W : l2W;
    const float* bb = (t < 8) ? l1b : l2b;
    float k = bb[p];
    #pragma unroll 8
    for (int h = 0; h < 64; h++) k = fmaf(x[h], W[p*64+h], k);
    K[t] = k;
  }
  __syncthreads();
  for (int idx = t; idx < 8*256; idx += 64) {
    int p = idx >> 8; int ij = idx & 255; int i = ij >> 4; int j = ij & 15;
    float wv = K[p]*(float)i + K[p+8]*(float)j + phi[b*8+p]*TWO_PI_F;
    Zbuf[(b*168 + 160 + p)*256 + ij] = sinf(wv);
  }
}

// =====================================================================
extern "C" void kernel_launch(void* const* d_in, const int* in_sizes, int n_in,
                              void* d_out, int out_size)
{
  const float* Zl   = (const float*)d_in[0];
  const float* Zg   = (const float*)d_in[1];
  const float* imgs = (const float*)d_in[2];
  const float* phi  = (const float*)d_in[3];
  const float* lW   = (const float*)d_in[4];
  const float* lb   = (const float*)d_in[5];
  const float* l1W  = (const float*)d_in[6];
  const float* l1b  = (const float*)d_in[7];
  const float* l2W  = (const float*)d_in[8];
  const float* l2b  = (const float*)d_in[9];
  const float* cw0  = (const float*)d_in[10];
  const float* cg0  = (const float*)d_in[12];
  const float* cbe0 = (const float*)d_in[13];
  const float* cw1  = (const float*)d_in[14];
  const float* cg1  = (const float*)d_in[16];
  const float* cbe1 = (const float*)d_in[17];
  const float* cw2  = (const float*)d_in[18];
  const float* cb2  = (const float*)d_in[19];
  const float* gw0  = (const float*)d_in[20];
  const float* gg0  = (const float*)d_in[22];
  const float* gbe0 = (const float*)d_in[23];
  const float* gw1  = (const float*)d_in[24];
  const float* gg1  = (const float*)d_in[26];
  const float* gbe1 = (const float*)d_in[27];
  const float* gw2  = (const float*)d_in[28];
  const float* gb2  = (const float*)d_in[29];
  float* out = (float*)d_out;

  float *h0,*h1,*Zb,*g0,*g1;
  float *s0,*s1,*s2,*s3;
  float *a0,*c0,*a1,*c1,*a2,*c2,*a3,*c3;
  float *wTc0,*wTc1,*wTc2,*wTd0,*wTd1;
  cudaGetSymbolAddress((void**)&h0, d_h0);
  cudaGetSymbolAddress((void**)&h1, d_h1);
  cudaGetSymbolAddress((void**)&Zb, d_Zbuf);
  cudaGetSymbolAddress((void**)&g0, d_g0);
  cudaGetSymbolAddress((void**)&g1, d_g1);
  cudaGetSymbolAddress((void**)&s0, d_stat0);
  cudaGetSymbolAddress((void**)&s1, d_stat1);
  cudaGetSymbolAddress((void**)&s2, d_stat2);
  cudaGetSymbolAddress((void**)&s3, d_stat3);
  cudaGetSymbolAddress((void**)&a0, d_a0); cudaGetSymbolAddress((void**)&c0, d_c0);
  cudaGetSymbolAddress((void**)&a1, d_a1); cudaGetSymbolAddress((void**)&c1, d_c1);
  cudaGetSymbolAddress((void**)&a2, d_a2); cudaGetSymbolAddress((void**)&c2, d_c2);
  cudaGetSymbolAddress((void**)&a3, d_a3); cudaGetSymbolAddress((void**)&c3, d_c3);
  cudaGetSymbolAddress((void**)&wTc0, d_wTc0);
  cudaGetSymbolAddress((void**)&wTc1, d_wTc1);
  cudaGetSymbolAddress((void**)&wTc2, d_wTc2);
  cudaGetSymbolAddress((void**)&wTd0, d_wTd0);
  cudaGetSymbolAddress((void**)&wTd1, d_wTd1);

  zero_kernel<<<1,512>>>(s0, s1, s2, s3);                          // 0
  transpose_convs<<<512,256>>>(cw0, wTc0, cw1, wTc1, cw2, wTc2);   // 1
  transpose_deconvs<<<2688,256>>>(gw0, wTd0, gw1, wTd1);           // 2

  // encoder (stats fused) — conv0 at capture slot 3
  conv_s2_kernel<3,64,128,128,64,64, 64, 4,64,3,8,8, true, false,false,false,true>
      <<<dim3(16,1,64),256>>>(imgs, wTc0, nullptr, nullptr, nullptr, h0, s0);  // 3
  finalize_kernel<<<1,64>>>(s0, cg0, cbe0, a0, c0, 64, 1.f/(64.f*4096.f));
  conv_s2_kernel<64,128,64,64,32,32, 128, 8,128,2,4,8, false, true,false,false,true>
      <<<dim3(4,1,64),256>>>(h0, wTc1, nullptr, a0, c0, h1, s1);
  finalize_kernel<<<1,128>>>(s1, cg1, cbe1, a1, c1, 128, 1.f/(64.f*1024.f));
  conv_s2_kernel<128,64,32,32,16,16, 168, 8,64,4,2,16, true, true,true,true,false>
      <<<dim3(2,1,64),256>>>(h1, wTc2, cb2, a1, c1, Zb, nullptr);

  pack_kernel<<<4096,256>>>(Zl, Zg, Zb);
  wave_kernel<<<64,64>>>(Zg, phi, lW, lb, l1W, l1b, l2W, l2b, Zb);

  // generator (stats fused) — R8 configs exactly
  deconv_kernel<168,256,16,16, 256, 8,256,8,2,16, false,true>
      <<<dim3(2,4,64),256>>>(Zb, wTd0, nullptr, nullptr, g0, s2);
  finalize_kernel<<<1,256>>>(s2, gg0, gbe0, a2, c2, 256, 1.f/(64.f*1024.f));
  deconv_kernel<256,128,32,32, 128, 8,128,8,4,16, true,true>
      <<<dim3(4,4,64),512>>>(g0, wTd1, a2, c2, g1, s3);
  finalize_kernel<<<1,128>>>(s3, gg1, gbe1, a3, c3, 128, 1.f/(64.f*4096.f));
  deconv2_kernel<<<dim3(4,4,64),128>>>(g1, gw2, gb2, a3, c3, out);
}

// round 13
// speedup vs baseline: 1.0898x; 1.0202x over previous
#include <cuda_runtime.h>
#include <math.h>

#define TWO_PI_F 6.2831853071795864769f

// ---------------- device scratch ----------------
__device__ float d_h0[64*64*64*64];
__device__ float d_h1[64*128*32*32];
__device__ float d_Zbuf[64*168*16*16];
__device__ float d_g0[64*256*32*32];
__device__ float d_g1[64*128*64*64];
__device__ float d_stat0[128];
__device__ float d_stat1[256];
__device__ float d_stat2[512];
__device__ float d_stat3[256];
__device__ float d_a0[64],  d_c0[64];
__device__ float d_a1[128], d_c1[128];
__device__ float d_a2[256], d_c2[256];
__device__ float d_a3[128], d_c3[128];
__device__ float d_wTc0[3*16*64];
__device__ float d_wTc1[64*16*128];
__device__ float d_wTc2[128*16*64];
__device__ float d_wTd0[4*168*4*256];
__device__ float d_wTd1[4*256*4*128];

// ---------------- packed f32x2 helpers ----------------
__device__ __forceinline__ unsigned long long pk2(float lo, float hi){
  unsigned long long r; asm("mov.b64 %0, {%1, %2};" : "=l"(r) : "f"(lo), "f"(hi)); return r;
}
__device__ __forceinline__ void fma2(unsigned long long& d, unsigned long long a, unsigned long long b){
  asm("fma.rn.f32x2 %0, %1, %2, %0;" : "+l"(d) : "l"(a), "l"(b));
}
__device__ __forceinline__ void unpk(unsigned long long v, float& lo, float& hi){
  asm("mov.b64 {%0, %1}, %2;" : "=f"(lo), "=f"(hi) : "l"(v));
}

// =====================================================================
// Weight transposes
// =====================================================================
__device__ __forceinline__ void tconv(const float* __restrict__ w, float* __restrict__ wT,
                                      int IC, int OC, int idx){
  int k = idx % 16; int ci = (idx/16) % IC; int co = idx/(16*IC);
  wT[(ci*16+k)*OC + co] = w[idx];
}
__device__ __forceinline__ void tdec(const float* __restrict__ w, float* __restrict__ wT,
                                     int IC, int OC, int idx){
  int kk = idx%16; int co = (idx/16)%OC; int ci = idx/(16*OC);
  int ky=kk>>2, kx=kk&3;
  int ry=(3-ky)&1, dd=(3-ky-ry)>>1;
  int rx=(3-kx)&1, ee=(3-kx-rx)>>1;
  wT[(((ry*2+rx)*IC+ci)*4 + dd*2+ee)*OC + co] = w[idx];
}
__global__ void transpose_convs(const float* w0, float* o0, const float* w1, float* o1,
                                const float* w2, float* o2){
  int idx = blockIdx.x*256 + threadIdx.x;
  if (idx < 3*64*16)   tconv(w0,o0,3,64,idx);
  if (idx < 64*128*16) tconv(w1,o1,64,128,idx);
  if (idx < 128*64*16) tconv(w2,o2,128,64,idx);
}
__global__ void transpose_deconvs(const float* w0, float* o0, const float* w1, float* o1){
  int idx = blockIdx.x*256+threadIdx.x;
  if (idx < 168*256*16) tdec(w0,o0,168,256,idx);
  if (idx < 256*128*16) tdec(w1,o1,256,128,idx);
}

// =====================================================================
// Strided conv k=4 s=2 p=1. ROWCACHE only where regs allow (CO_P small).
// =====================================================================
template<int IC, int OC, int IH, int IW, int OH, int OW, int OUT_CB,
         int TILE_OY, int CO_BLK, int CI_CHUNK, int NG_OX, int NG_CO,
         bool ROWCACHE, bool ACT_IN_LRELU, bool BIAS, bool TANH_OUT, bool REDUCE>
__global__ void __launch_bounds__(NG_CO*NG_OX*TILE_OY)
conv_s2_kernel(const float* __restrict__ in, const float* __restrict__ wT,
               const float* __restrict__ bias,
               const float* __restrict__ a_in, const float* __restrict__ c_in,
               float* __restrict__ out, float* __restrict__ stat)
{
  constexpr int NT    = NG_CO * NG_OX * TILE_OY;
  constexpr int CO_T  = CO_BLK / NG_CO;
  constexpr int CO_P  = CO_T / 2;
  constexpr int ROWS  = 2*TILE_OY + 2;
  constexpr int COLSP = IW + 4;
  constexpr int TOTAL_IN = CI_CHUNK*ROWS*COLSP;
  constexpr int NITER = (TOTAL_IN + NT - 1)/NT;
  constexpr int WLEN4 = CI_CHUNK*16*CO_BLK/4;
  static_assert(OW / NG_OX == 8, "");
  static_assert(CO_BLK == OC, "");
  static_assert((CO_P & (CO_P-1)) == 0, "");
  static_assert(!ROWCACHE || CO_P <= 4, "");

  __shared__ __align__(16) float sIn[CI_CHUNK][ROWS][COLSP];
  __shared__ __align__(16) float sW [CI_CHUNK][16][CO_BLK];
  __shared__ float sRed[2*CO_BLK];

  const int tid   = threadIdx.x;
  const int co_g  = tid % NG_CO;
  const int ox_g  = (tid / NG_CO) % NG_OX;
  const int oy_l  = tid / (NG_CO * NG_OX);
  const int b     = blockIdx.z;
  const int oy0   = blockIdx.x * TILE_OY;
  const int iy0   = 2*oy0 - 1;
  const int ox0   = ox_g * 8;
  const int co_t0 = co_g * CO_T;

  int gOff[NITER]; int ccA[ACT_IN_LRELU ? NITER : 1];
  #pragma unroll
  for (int i=0;i<NITER;i++){
    int idx = tid + i*NT;
    int cc  = idx / (ROWS*COLSP);
    int rem = idx % (ROWS*COLSP);
    int r   = rem / COLSP, col = rem % COLSP;
    int iy  = iy0 + r, ix = col - 1;
    bool ok = (idx < TOTAL_IN) && ix >= 0 && ix < IW && iy >= 0 && iy < IH;
    gOff[i] = ok ? ((b*IC + cc)*IH + iy)*IW + ix : -1;
    if constexpr (ACT_IN_LRELU) ccA[i] = cc;
  }

  unsigned long long acc[8][CO_P];
  #pragma unroll
  for (int u=0;u<8;u++)
    #pragma unroll
    for (int j=0;j<CO_P;j++) acc[u][j] = 0ULL;

  float* sInF = &sIn[0][0][0];

  for (int ci0 = 0; ci0 < IC; ci0 += CI_CHUNK) {
    const int cBase = ci0*IH*IW;
    #pragma unroll
    for (int i=0;i<NITER;i++){
      int idx = tid + i*NT;
      if (idx < TOTAL_IN) {
        float v = 0.f;
        int go = gOff[i];
        if (go >= 0) {
          v = in[go + cBase];
          if constexpr (ACT_IN_LRELU) {
            float t = fmaf(a_in[ci0+ccA[i]], v, c_in[ci0+ccA[i]]);
            v = t > 0.f ? t : 0.2f*t;
          }
        }
        sInF[idx] = v;
      }
    }
    {
      const float4* ws = reinterpret_cast<const float4*>(wT + ci0*16*OC);
      float4* wd = reinterpret_cast<float4*>(&sW[0][0][0]);
      #pragma unroll
      for (int i = 0; i < (WLEN4 + NT - 1)/NT; i++) {
        int idx = tid + i*NT;
        if (idx < WLEN4) wd[idx] = ws[idx];
      }
    }
    __syncthreads();

    #pragma unroll
    for (int cc=0; cc<CI_CHUNK; cc++) {
      if constexpr (ROWCACHE) {
        #pragma unroll
        for (int ky=0; ky<4; ky++) {
          const float* rowp = &sIn[cc][2*oy_l + ky][0] + 2*ox0;
          unsigned long long pv[18];
          {
            const float4* rp4 = reinterpret_cast<const float4*>(rowp);
            float4 q;
            q = rp4[0]; pv[0]=pk2(q.x,q.x); pv[1]=pk2(q.y,q.y); pv[2]=pk2(q.z,q.z); pv[3]=pk2(q.w,q.w);
            q = rp4[1]; pv[4]=pk2(q.x,q.x); pv[5]=pk2(q.y,q.y); pv[6]=pk2(q.z,q.z); pv[7]=pk2(q.w,q.w);
            q = rp4[2]; pv[8]=pk2(q.x,q.x); pv[9]=pk2(q.y,q.y); pv[10]=pk2(q.z,q.z); pv[11]=pk2(q.w,q.w);
            q = rp4[3]; pv[12]=pk2(q.x,q.x); pv[13]=pk2(q.y,q.y); pv[14]=pk2(q.z,q.z); pv[15]=pk2(q.w,q.w);
            float2 q2 = *reinterpret_cast<const float2*>(rowp + 16);
            pv[16]=pk2(q2.x,q2.x); pv[17]=pk2(q2.y,q2.y);
          }
          #pragma unroll
          for (int kx=0; kx<4; kx++) {
            const int k = ky*4 + kx;
            unsigned long long wv[CO_P];
            #pragma unroll
            for (int j=0;j<CO_P;j++){
              int p = (j + co_g) & (CO_P-1);
              wv[j] = *reinterpret_cast<const unsigned long long*>(&sW[cc][k][co_t0 + 2*p]);
            }
            #pragma unroll
            for (int u=0;u<8;u++)
              #pragma unroll
              for (int j=0;j<CO_P;j++) fma2(acc[u][j], pv[2*u+kx], wv[j]);
          }
        }
      } else {
        #pragma unroll
        for (int k=0;k<16;k++) {
          const int ky = k >> 2, kx = k & 3;
          unsigned long long wv[CO_P];
          #pragma unroll
          for (int j=0;j<CO_P;j++){
            int p = (j + co_g) & (CO_P-1);
            wv[j] = *reinterpret_cast<const unsigned long long*>(&sW[cc][k][co_t0 + 2*p]);
          }
          const float* rowp = &sIn[cc][2*oy_l + ky][0];
          #pragma unroll
          for (int u=0;u<8;u++) {
            float iv = rowp[2*(ox0+u) + kx];
            unsigned long long pv = pk2(iv, iv);
            #pragma unroll
            for (int j=0;j<CO_P;j++) fma2(acc[u][j], pv, wv[j]);
          }
        }
      }
    }
    __syncthreads();
  }

  if constexpr (REDUCE) {
    for (int i = tid; i < 2*CO_BLK; i += NT) sRed[i] = 0.f;
    __syncthreads();
  }

  const int oy = oy0 + oy_l;
  #pragma unroll
  for (int j=0;j<CO_P;j++){
    int p = (j + co_g) & (CO_P-1);
    float v0[8], v1[8];
    #pragma unroll
    for (int u=0;u<8;u++) unpk(acc[u][j], v0[u], v1[u]);
    const int co = co_t0 + 2*p;
    if constexpr (BIAS) {
      float b0 = bias[co], b1 = bias[co+1];
      #pragma unroll
      for (int u=0;u<8;u++){ v0[u]+=b0; v1[u]+=b1; }
    }
    if constexpr (TANH_OUT) {
      #pragma unroll
      for (int u=0;u<8;u++){ v0[u]=tanhf(v0[u]); v1[u]=tanhf(v1[u]); }
    }
    float4* p0 = reinterpret_cast<float4*>(&out[((b*OUT_CB + co  )*OH + oy)*OW + ox0]);
    float4* p1 = reinterpret_cast<float4*>(&out[((b*OUT_CB + co+1)*OH + oy)*OW + ox0]);
    p0[0] = make_float4(v0[0],v0[1],v0[2],v0[3]);
    p0[1] = make_float4(v0[4],v0[5],v0[6],v0[7]);
    p1[0] = make_float4(v1[0],v1[1],v1[2],v1[3]);
    p1[1] = make_float4(v1[4],v1[5],v1[6],v1[7]);
    if constexpr (REDUCE) {
      float s0=0.f,q0=0.f,s1=0.f,q1=0.f;
      #pragma unroll
      for (int u=0;u<8;u++){ s0+=v0[u]; q0=fmaf(v0[u],v0[u],q0); s1+=v1[u]; q1=fmaf(v1[u],v1[u],q1); }
      atomicAdd(&sRed[co],          s0);
      atomicAdd(&sRed[CO_BLK+co],   q0);
      atomicAdd(&sRed[co+1],        s1);
      atomicAdd(&sRed[CO_BLK+co+1], q1);
    }
  }
  if constexpr (REDUCE) {
    __syncthreads();
    for (int i2 = tid; i2 < 2*CO_BLK; i2 += NT) {
      int off = (i2 < CO_BLK) ? 0 : OC;
      int cl  = (i2 < CO_BLK) ? i2 : (i2 - CO_BLK);
      atomicAdd(&stat[off + cl], sRed[i2]);
    }
  }
}

// =====================================================================
// Transposed conv k=4 s=2 p=1 via parity decomposition.
// PREFETCH: register double-buffer of next chunk (LDG overlapped with
// compute; STS then latency-free). Applied only where reg headroom exists.
// =====================================================================
template<int IC, int OC, int IH, int IW, int OUT_CB,
         int TILE_M, int CO_BLK, int CI_CHUNK, int NG_N, int NG_CO,
         bool PREFETCH, bool ACT_IN_RELU, bool REDUCE>
__global__ void __launch_bounds__(NG_N*NG_CO*TILE_M)
deconv_kernel(const float* __restrict__ in, const float* __restrict__ wT,
              const float* __restrict__ a_in, const float* __restrict__ c_in,
              float* __restrict__ out, float* __restrict__ stat)
{
  constexpr int NT    = NG_N * NG_CO * TILE_M;
  constexpr int CO_T  = CO_BLK / NG_CO;
  constexpr int CO_P  = CO_T / 2;
  constexpr int ROWS  = TILE_M + 1;
  constexpr int COLSP = IW + 2;
  constexpr int TOTAL_IN = CI_CHUNK*ROWS*COLSP;
  constexpr int NITER = (TOTAL_IN + NT - 1)/NT;
  constexpr int WLEN4 = CI_CHUNK*4*CO_BLK/4;
  constexpr int NW    = (WLEN4 + NT - 1)/NT;
  static_assert(IW / NG_N == 8, "");
  static_assert(CO_BLK == OC, "");
  static_assert((CO_P & (CO_P-1)) == 0, "");

  __shared__ __align__(16) float sIn[CI_CHUNK][ROWS][COLSP];
  __shared__ __align__(16) float sW [CI_CHUNK][4][CO_BLK];
  __shared__ float sRed[2*CO_BLK];

  const int tid    = threadIdx.x;
  const int n_g    = tid % NG_N;
  const int co_g   = (tid / NG_N) % NG_CO;
  const int m_l    = tid / (NG_N * NG_CO);
  const int m_tile = blockIdx.x;
  const int ry     = blockIdx.y >> 1, rx = blockIdx.y & 1;
  const int par    = blockIdx.y;
  const int b      = blockIdx.z;
  const int m0     = m_tile * TILE_M;
  const int n0     = n_g * 8;
  const int co_t0  = co_g * CO_T;

  int gOff[NITER]; int ccA[ACT_IN_RELU ? NITER : 1];
  #pragma unroll
  for (int i=0;i<NITER;i++){
    int idx = tid + i*NT;
    int cc  = idx / (ROWS*COLSP);
    int rem = idx % (ROWS*COLSP);
    int r   = rem / COLSP, col = rem % COLSP;
    int gy  = m0 + ry - 1 + r;
    int gx  = rx - 1 + col;
    bool ok = (idx < TOTAL_IN) && gx >= 0 && gx < IW && gy >= 0 && gy < IH;
    gOff[i] = ok ? ((b*IC + cc)*IH + gy)*IW + gx : -1;
    if constexpr (ACT_IN_RELU) ccA[i] = cc;
  }

  unsigned long long acc[8][CO_P];
  #pragma unroll
  for (int u=0;u<8;u++)
    #pragma unroll
    for (int j=0;j<CO_P;j++) acc[u][j] = 0ULL;

  float* sInF = &sIn[0][0][0];
  float4* wd  = reinterpret_cast<float4*>(&sW[0][0][0]);

  auto ldin = [&](int ci0, float (&vin)[NITER]){
    const int cBase = ci0*IH*IW;
    #pragma unroll
    for (int i=0;i<NITER;i++){
      float v = 0.f;
      int go = gOff[i];
      if (go >= 0) {
        v = in[go + cBase];
        if constexpr (ACT_IN_RELU)
          v = fmaxf(fmaf(a_in[ci0+ccA[i]], v, c_in[ci0+ccA[i]]), 0.f);
      }
      vin[i] = v;
    }
  };
  auto ldw = [&](int ci0, float4 (&vw)[NW]){
    const float4* ws = reinterpret_cast<const float4*>(wT + (par*IC + ci0)*4*OC);
    #pragma unroll
    for (int i=0;i<NW;i++){
      int idx = tid + i*NT;
      if (idx < WLEN4) vw[i] = ws[idx];
    }
  };

  float vin[PREFETCH ? NITER : 1];
  float4 vw[PREFETCH ? NW : 1];
  if constexpr (PREFETCH) {
    float (&vinR)[NITER] = reinterpret_cast<float(&)[NITER]>(vin);
    float4 (&vwR)[NW] = reinterpret_cast<float4(&)[NW]>(vw);
    ldin(0, vinR); ldw(0, vwR);
  }

  for (int ci0 = 0; ci0 < IC; ci0 += CI_CHUNK) {
    if constexpr (PREFETCH) {
      float (&vinR)[NITER] = reinterpret_cast<float(&)[NITER]>(vin);
      float4 (&vwR)[NW] = reinterpret_cast<float4(&)[NW]>(vw);
      #pragma unroll
      for (int i=0;i<NITER;i++){
        int idx = tid + i*NT;
        if (idx < TOTAL_IN) sInF[idx] = vinR[i];
      }
      #pragma unroll
      for (int i=0;i<NW;i++){
        int idx = tid + i*NT;
        if (idx < WLEN4) wd[idx] = vwR[i];
      }
      __syncthreads();
      if (ci0 + CI_CHUNK < IC) { ldin(ci0+CI_CHUNK, vinR); ldw(ci0+CI_CHUNK, vwR); }
    } else {
      const int cBase = ci0*IH*IW;
      #pragma unroll
      for (int i=0;i<NITER;i++){
        int idx = tid + i*NT;
        if (idx < TOTAL_IN) {
          float v = 0.f;
          int go = gOff[i];
          if (go >= 0) {
            v = in[go + cBase];
            if constexpr (ACT_IN_RELU)
              v = fmaxf(fmaf(a_in[ci0+ccA[i]], v, c_in[ci0+ccA[i]]), 0.f);
          }
          sInF[idx] = v;
        }
      }
      const float4* ws = reinterpret_cast<const float4*>(wT + (par*IC + ci0)*4*OC);
      #pragma unroll
      for (int i = 0; i < NW; i++) {
        int idx = tid + i*NT;
        if (idx < WLEN4) wd[idx] = ws[idx];
      }
      __syncthreads();
    }

    #pragma unroll
    for (int cc=0; cc<CI_CHUNK; cc++) {
      #pragma unroll
      for (int t4=0;t4<4;t4++) {
        const int dd = t4 >> 1, ee = t4 & 1;
        unsigned long long wv[CO_P];
        #pragma unroll
        for (int j=0;j<CO_P;j++){
          int p = (j + co_g) & (CO_P-1);
          wv[j] = *reinterpret_cast<const unsigned long long*>(&sW[cc][t4][co_t0 + 2*p]);
        }
        const float* rowp = &sIn[cc][m_l + dd][0];
        #pragma unroll
        for (int u=0;u<8;u++) {
          float iv = rowp[n0 + u + ee];
          unsigned long long pv = pk2(iv, iv);
          #pragma unroll
          for (int j=0;j<CO_P;j++) fma2(acc[u][j], pv, wv[j]);
        }
      }
    }
    __syncthreads();
  }

  if constexpr (REDUCE) {
    for (int i = tid; i < 2*CO_BLK; i += NT) sRed[i] = 0.f;
    __syncthreads();
  }

  const int oy = 2*(m0 + m_l) + ry;
  const int OW2 = 2*IW, OH2 = 2*IH;
  #pragma unroll
  for (int j=0;j<CO_P;j++){
    int p = (j + co_g) & (CO_P-1);
    const int co = co_t0 + 2*p;
    float* r0 = &out[((b*OUT_CB + co  )*OH2 + oy)*OW2 + rx];
    float* r1 = &out[((b*OUT_CB + co+1)*OH2 + oy)*OW2 + rx];
    float s0=0.f,q0=0.f,s1=0.f,q1=0.f;
    #pragma unroll
    for (int u=0;u<8;u++){
      float v0, v1; unpk(acc[u][j], v0, v1);
      r0[2*(n0+u)] = v0;
      r1[2*(n0+u)] = v1;
      if constexpr (REDUCE) { s0+=v0; q0=fmaf(v0,v0,q0); s1+=v1; q1=fmaf(v1,v1,q1); }
    }
    if constexpr (REDUCE) {
      atomicAdd(&sRed[co],          s0);
      atomicAdd(&sRed[CO_BLK+co],   q0);
      atomicAdd(&sRed[co+1],        s1);
      atomicAdd(&sRed[CO_BLK+co+1], q1);
    }
  }
  if constexpr (REDUCE) {
    __syncthreads();
    for (int i2 = tid; i2 < 2*CO_BLK; i2 += NT) {
      int off = (i2 < CO_BLK) ? 0 : OC;
      int cl  = (i2 < CO_BLK) ? i2 : (i2 - CO_BLK);
      atomicAdd(&stat[off + cl], sRed[i2]);
    }
  }
}

// =====================================================================
// Final deconv 128->3 with bias + tanh
// =====================================================================
__global__ void __launch_bounds__(128)
deconv2_kernel(const float* __restrict__ in, const float* __restrict__ w,
               const float* __restrict__ bias,
               const float* __restrict__ a_in, const float* __restrict__ c_in,
               float* __restrict__ out)
{
  constexpr int IC=128, IH=64, IW=64, TILE_M=16, CI=4, NG_N=8;
  constexpr int NT=128, ROWS=TILE_M+1, COLSP=IW+2;
  constexpr int TOTAL_IN = CI*ROWS*COLSP;
  constexpr int NITER = (TOTAL_IN + NT - 1)/NT;
  __shared__ float sIn[CI][ROWS][COLSP];
  __shared__ float sW[CI][4][4];

  const int tid = threadIdx.x;
  const int n_g = tid % NG_N;
  const int m_l = tid / NG_N;
  const int m0  = blockIdx.x * TILE_M;
  const int ry  = blockIdx.y >> 1, rx = blockIdx.y & 1;
  const int b   = blockIdx.z;
  const int n0  = n_g * 8;

  int gOff[NITER]; int ccA[NITER];
  #pragma unroll
  for (int i=0;i<NITER;i++){
    int idx = tid + i*NT;
    int cc  = idx / (ROWS*COLSP);
    int rem = idx % (ROWS*COLSP);
    int r   = rem / COLSP, col = rem % COLSP;
    int gy  = m0 + ry - 1 + r;
    int gx  = rx - 1 + col;
    bool ok = (idx < TOTAL_IN) && gx >= 0 && gx < IW && gy >= 0 && gy < IH;
    gOff[i] = ok ? ((b*IC + cc)*IH + gy)*IW + gx : -1;
    ccA[i]  = cc;
  }

  float acc[3][8];
  #pragma unroll
  for (int co=0;co<3;co++)
    #pragma unroll
    for (int u=0;u<8;u++) acc[co][u] = 0.f;

  float* sInF = &sIn[0][0][0];

  for (int ci0 = 0; ci0 < IC; ci0 += CI) {
    const int cBase = ci0*IH*IW;
    #pragma unroll
    for (int i=0;i<NITER;i++){
      int idx = tid + i*NT;
      if (idx < TOTAL_IN) {
        float v = 0.f;
        int go = gOff[i];
        if (go >= 0)
          v = fmaxf(fmaf(a_in[ci0+ccA[i]], in[go + cBase], c_in[ci0+ccA[i]]), 0.f);
        sInF[idx] = v;
      }
    }
    if (tid < 48) {
      int cc = tid / 12, t4 = (tid / 3) % 4, co = tid % 3;
      int dd = t4 >> 1, ee = t4 & 1;
      sW[cc][t4][co] = w[((ci0+cc)*3 + co)*16 + (3-ry-2*dd)*4 + (3-rx-2*ee)];
    }
    __syncthreads();

    #pragma unroll
    for (int cc=0; cc<CI; cc++) {
      #pragma unroll
      for (int t4=0;t4<4;t4++) {
        const int dd = t4 >> 1, ee = t4 & 1;
        float w0 = sW[cc][t4][0], w1 = sW[cc][t4][1], w2 = sW[cc][t4][2];
        const float* rowp = &sIn[cc][m_l + dd][0];
        #pragma unroll
        for (int u=0;u<8;u++) {
          float iv = rowp[n0 + u + ee];
          acc[0][u] = fmaf(iv, w0, acc[0][u]);
          acc[1][u] = fmaf(iv, w1, acc[1][u]);
          acc[2][u] = fmaf(iv, w2, acc[2][u]);
        }
      }
    }
    __syncthreads();
  }

  const int oy = 2*(m0 + m_l) + ry;
  #pragma unroll
  for (int co=0;co<3;co++){
    float bb = bias[co];
    float* rp = &out[((b*3 + co)*128 + oy)*128 + rx];
    #pragma unroll
    for (int u=0;u<8;u++)
      rp[2*(n0+u)] = tanhf(acc[co][u] + bb);
  }
}

// =====================================================================
__global__ void finalize_kernel(const float* __restrict__ stat, const float* __restrict__ g,
                                const float* __restrict__ be,
                                float* __restrict__ a, float* __restrict__ cv,
                                int C, float invN)
{
  int c = threadIdx.x + blockIdx.x*blockDim.x;
  if (c >= C) return;
  float mean = stat[c] * invN;
  float var  = stat[C + c] * invN - mean*mean;
  float av = g[c] * rsqrtf(var + 1e-5f);
  a[c] = av;
  cv[c] = be[c] - mean * av;
}

__global__ void zero_kernel(float* s0, float* s1, float* s2, float* s3)
{
  int t = threadIdx.x;
  if (t < 128) s0[t] = 0.f;
  if (t < 256) s1[t] = 0.f;
  if (t < 512) s2[t] = 0.f;
  if (t < 256) s3[t] = 0.f;
}

__global__ void pack_kernel(const float* __restrict__ Zl, const float* __restrict__ Zg,
                            float* __restrict__ Zbuf)
{
  int idx = blockIdx.x * 256 + threadIdx.x;
  const int nl = 64*32*256;
  if (idx < nl) {
    int b = idx / (32*256); int r = idx % (32*256);
    Zbuf[(b*168 + 64)*256 + r] = Zl[idx];
  }
  const int ng = 64*64*256;
  if (idx < ng) {
    int b = idx / (64*256); int r = idx % (64*256);
    Zbuf[(b*168 + 96)*256 + r] = Zg[idx];
  }
}

__global__ void wave_kernel(const float* __restrict__ Zg, const float* __restrict__ phi,
                            const float* __restrict__ lW, const float* __restrict__ lb,
                            const float* __restrict__ l1W, const float* __restrict__ l1b,
                            const float* __restrict__ l2W, const float* __restrict__ l2b,
                            float* __restrict__ Zbuf)
{
  const int b = blockIdx.x;
  const int t = threadIdx.x;  // 64
  __shared__ float zg[64], x[64], K[16];
  zg[t] = Zg[(b*64 + t)*256];
  __syncthreads();
  float acc = lb[t];
  #pragma unroll 8
  for (int g = 0; g < 64; g++) acc = fmaf(zg[g], lW[t*64+g], acc);
  x[t] = fmaxf(acc, 0.f);
  __syncthreads();
  if (t < 16) {
    int p = t & 7;
    const float* W  = (t < 8) ? l1W : l2W;
    const float* bb = (t < 8) ? l1b : l2b;
    float k = bb[p];
    #pragma unroll 8
    for (int h = 0; h < 64; h++) k = fmaf(x[h], W[p*64+h], k);
    K[t] = k;
  }
  __syncthreads();
  for (int idx = t; idx < 8*256; idx += 64) {
    int p = idx >> 8; int ij = idx & 255; int i = ij >> 4; int j = ij & 15;
    float wv = K[p]*(float)i + K[p+8]*(float)j + phi[b*8+p]*TWO_PI_F;
    Zbuf[(b*168 + 160 + p)*256 + ij] = sinf(wv);
  }
}

// =====================================================================
extern "C" void kernel_launch(void* const* d_in, const int* in_sizes, int n_in,
                              void* d_out, int out_size)
{
  const float* Zl   = (const float*)d_in[0];
  const float* Zg   = (const float*)d_in[1];
  const float* imgs = (const float*)d_in[2];
  const float* phi  = (const float*)d_in[3];
  const float* lW   = (const float*)d_in[4];
  const float* lb   = (const float*)d_in[5];
  const float* l1W  = (const float*)d_in[6];
  const float* l1b  = (const float*)d_in[7];
  const float* l2W  = (const float*)d_in[8];
  const float* l2b  = (const float*)d_in[9];
  const float* cw0  = (const float*)d_in[10];
  const float* cg0  = (const float*)d_in[12];
  const float* cbe0 = (const float*)d_in[13];
  const float* cw1  = (const float*)d_in[14];
  const float* cg1  = (const float*)d_in[16];
  const float* cbe1 = (const float*)d_in[17];
  const float* cw2  = (const float*)d_in[18];
  const float* cb2  = (const float*)d_in[19];
  const float* gw0  = (const float*)d_in[20];
  const float* gg0  = (const float*)d_in[22];
  const float* gbe0 = (const float*)d_in[23];
  const float* gw1  = (const float*)d_in[24];
  const float* gg1  = (const float*)d_in[26];
  const float* gbe1 = (const float*)d_in[27];
  const float* gw2  = (const float*)d_in[28];
  const float* gb2  = (const float*)d_in[29];
  float* out = (float*)d_out;

  float *h0,*h1,*Zb,*g0,*g1;
  float *s0,*s1,*s2,*s3;
  float *a0,*c0,*a1,*c1,*a2,*c2,*a3,*c3;
  float *wTc0,*wTc1,*wTc2,*wTd0,*wTd1;
  cudaGetSymbolAddress((void**)&h0, d_h0);
  cudaGetSymbolAddress((void**)&h1, d_h1);
  cudaGetSymbolAddress((void**)&Zb, d_Zbuf);
  cudaGetSymbolAddress((void**)&g0, d_g0);
  cudaGetSymbolAddress((void**)&g1, d_g1);
  cudaGetSymbolAddress((void**)&s0, d_stat0);
  cudaGetSymbolAddress((void**)&s1, d_stat1);
  cudaGetSymbolAddress((void**)&s2, d_stat2);
  cudaGetSymbolAddress((void**)&s3, d_stat3);
  cudaGetSymbolAddress((void**)&a0, d_a0); cudaGetSymbolAddress((void**)&c0, d_c0);
  cudaGetSymbolAddress((void**)&a1, d_a1); cudaGetSymbolAddress((void**)&c1, d_c1);
  cudaGetSymbolAddress((void**)&a2, d_a2); cudaGetSymbolAddress((void**)&c2, d_c2);
  cudaGetSymbolAddress((void**)&a3, d_a3); cudaGetSymbolAddress((void**)&c3, d_c3);
  cudaGetSymbolAddress((void**)&wTc0, d_wTc0);
  cudaGetSymbolAddress((void**)&wTc1, d_wTc1);
  cudaGetSymbolAddress((void**)&wTc2, d_wTc2);
  cudaGetSymbolAddress((void**)&wTd0, d_wTd0);
  cudaGetSymbolAddress((void**)&wTd1, d_wTd1);

  zero_kernel<<<1,512>>>(s0, s1, s2, s3);                          // 0
  transpose_convs<<<512,256>>>(cw0, wTc0, cw1, wTc1, cw2, wTc2);   // 1
  transpose_deconvs<<<2688,256>>>(gw0, wTd0, gw1, wTd1);           // 2

  // encoder (stats fused) — conv0 at capture slot 3
  conv_s2_kernel<3,64,128,128,64,64, 64, 4,64,3,8,8, true, false,false,false,true>
      <<<dim3(16,1,64),256>>>(imgs, wTc0, nullptr, nullptr, nullptr, h0, s0);  // 3
  finalize_kernel<<<1,64>>>(s0, cg0, cbe0, a0, c0, 64, 1.f/(64.f*4096.f));
  conv_s2_kernel<64,128,64,64,32,32, 128, 8,128,2,4,8, false, true,false,false,true>
      <<<dim3(4,1,64),256>>>(h0, wTc1, nullptr, a0, c0, h1, s1);
  finalize_kernel<<<1,128>>>(s1, cg1, cbe1, a1, c1, 128, 1.f/(64.f*1024.f));
  conv_s2_kernel<128,64,32,32,16,16, 168, 8,64,4,2,16, true, true,true,true,false>
      <<<dim3(2,1,64),256>>>(h1, wTc2, cb2, a1, c1, Zb, nullptr);

  pack_kernel<<<4096,256>>>(Zl, Zg, Zb);
  wave_kernel<<<64,64>>>(Zg, phi, lW, lb, l1W, l1b, l2W, l2b, Zb);

  // generator (stats fused)
  deconv_kernel<168,256,16,16, 256, 8,256,8,2,16, false, false,true>
      <<<dim3(2,4,64),256>>>(Zb, wTd0, nullptr, nullptr, g0, s2);
  finalize_kernel<<<1,256>>>(s2, gg0, gbe0, a2, c2, 256, 1.f/(64.f*1024.f));
  deconv_kernel<256,128,32,32, 128, 8,128,8,4,16, true, true,true>
      <<<dim3(4,4,64),512>>>(g0, wTd1, a2, c2, g1, s3);
  finalize_kernel<<<1,128>>>(s3, gg1, gbe1, a3, c3, 128, 1.f/(64.f*4096.f));
  deconv2_kernel<<<dim3(4,4,64),128>>>(g1, gw2, gb2, a3, c3, out);
}

// round 14
// speedup vs baseline: 1.0940x; 1.0038x over previous
#include <cuda_runtime.h>
#include <math.h>

#define TWO_PI_F 6.2831853071795864769f

// ---------------- device scratch ----------------
__device__ float d_h0[64*64*64*64];
__device__ float d_h1[64*128*32*32];
__device__ float d_Zbuf[64*168*16*16];
__device__ float d_g0[64*256*32*32];
__device__ float d_g1[64*128*64*64];
__device__ float d_stat0[128];
__device__ float d_stat1[256];
__device__ float d_stat2[512];
__device__ float d_stat3[256];
__device__ float d_a0[64],  d_c0[64];
__device__ float d_a1[128], d_c1[128];
__device__ float d_a2[256], d_c2[256];
__device__ float d_a3[128], d_c3[128];
__device__ float d_wTc0[3*16*64];
__device__ float d_wTc1[64*16*128];
__device__ float d_wTc2[128*16*64];
__device__ float d_wTd0[4*168*4*256];
__device__ float d_wTd1[4*256*4*128];

// ---------------- packed f32x2 helpers ----------------
__device__ __forceinline__ unsigned long long pk2(float lo, float hi){
  unsigned long long r; asm("mov.b64 %0, {%1, %2};" : "=l"(r) : "f"(lo), "f"(hi)); return r;
}
__device__ __forceinline__ void fma2(unsigned long long& d, unsigned long long a, unsigned long long b){
  asm("fma.rn.f32x2 %0, %1, %2, %0;" : "+l"(d) : "l"(a), "l"(b));
}
__device__ __forceinline__ void unpk(unsigned long long v, float& lo, float& hi){
  asm("mov.b64 {%0, %1}, %2;" : "=f"(lo), "=f"(hi) : "l"(v));
}

// =====================================================================
// Weight transposes
// =====================================================================
__device__ __forceinline__ void tconv(const float* __restrict__ w, float* __restrict__ wT,
                                      int IC, int OC, int idx){
  int k = idx % 16; int ci = (idx/16) % IC; int co = idx/(16*IC);
  wT[(ci*16+k)*OC + co] = w[idx];
}
__device__ __forceinline__ void tdec(const float* __restrict__ w, float* __restrict__ wT,
                                     int IC, int OC, int idx){
  int kk = idx%16; int co = (idx/16)%OC; int ci = idx/(16*OC);
  int ky=kk>>2, kx=kk&3;
  int ry=(3-ky)&1, dd=(3-ky-ry)>>1;
  int rx=(3-kx)&1, ee=(3-kx-rx)>>1;
  wT[(((ry*2+rx)*IC+ci)*4 + dd*2+ee)*OC + co] = w[idx];
}
__global__ void transpose_convs(const float* w0, float* o0, const float* w1, float* o1,
                                const float* w2, float* o2){
  int idx = blockIdx.x*256 + threadIdx.x;
  if (idx < 3*64*16)   tconv(w0,o0,3,64,idx);
  if (idx < 64*128*16) tconv(w1,o1,64,128,idx);
  if (idx < 128*64*16) tconv(w2,o2,128,64,idx);
}
__global__ void transpose_deconvs(const float* w0, float* o0, const float* w1, float* o1){
  int idx = blockIdx.x*256+threadIdx.x;
  if (idx < 168*256*16) tdec(w0,o0,168,256,idx);
  if (idx < 256*128*16) tdec(w1,o1,256,128,idx);
}

// =====================================================================
// Strided conv k=4 s=2 p=1. ROWCACHE where regs allow; optional full
// register prefetch double-buffering of next chunk.
// =====================================================================
template<int IC, int OC, int IH, int IW, int OH, int OW, int OUT_CB,
         int TILE_OY, int CO_BLK, int CI_CHUNK, int NG_OX, int NG_CO,
         bool ROWCACHE, bool PREFETCH, bool ACT_IN_LRELU, bool BIAS, bool TANH_OUT, bool REDUCE>
__global__ void __launch_bounds__(NG_CO*NG_OX*TILE_OY)
conv_s2_kernel(const float* __restrict__ in, const float* __restrict__ wT,
               const float* __restrict__ bias,
               const float* __restrict__ a_in, const float* __restrict__ c_in,
               float* __restrict__ out, float* __restrict__ stat)
{
  constexpr int NT    = NG_CO * NG_OX * TILE_OY;
  constexpr int CO_T  = CO_BLK / NG_CO;
  constexpr int CO_P  = CO_T / 2;
  constexpr int ROWS  = 2*TILE_OY + 2;
  constexpr int COLSP = IW + 4;
  constexpr int TOTAL_IN = CI_CHUNK*ROWS*COLSP;
  constexpr int NITER = (TOTAL_IN + NT - 1)/NT;
  constexpr int WLEN4 = CI_CHUNK*16*CO_BLK/4;
  constexpr int NW    = (WLEN4 + NT - 1)/NT;
  static_assert(OW / NG_OX == 8, "");
  static_assert(CO_BLK == OC, "");
  static_assert((CO_P & (CO_P-1)) == 0, "");
  static_assert(!ROWCACHE || CO_P <= 4, "");

  __shared__ __align__(16) float sIn[CI_CHUNK][ROWS][COLSP];
  __shared__ __align__(16) float sW [CI_CHUNK][16][CO_BLK];
  __shared__ float sRed[2*CO_BLK];

  const int tid   = threadIdx.x;
  const int co_g  = tid % NG_CO;
  const int ox_g  = (tid / NG_CO) % NG_OX;
  const int oy_l  = tid / (NG_CO * NG_OX);
  const int b     = blockIdx.z;
  const int oy0   = blockIdx.x * TILE_OY;
  const int iy0   = 2*oy0 - 1;
  const int ox0   = ox_g * 8;
  const int co_t0 = co_g * CO_T;

  int gOff[NITER]; int ccA[ACT_IN_LRELU ? NITER : 1];
  #pragma unroll
  for (int i=0;i<NITER;i++){
    int idx = tid + i*NT;
    int cc  = idx / (ROWS*COLSP);
    int rem = idx % (ROWS*COLSP);
    int r   = rem / COLSP, col = rem % COLSP;
    int iy  = iy0 + r, ix = col - 1;
    bool ok = (idx < TOTAL_IN) && ix >= 0 && ix < IW && iy >= 0 && iy < IH;
    gOff[i] = ok ? ((b*IC + cc)*IH + iy)*IW + ix : -1;
    if constexpr (ACT_IN_LRELU) ccA[i] = cc;
  }

  unsigned long long acc[8][CO_P];
  #pragma unroll
  for (int u=0;u<8;u++)
    #pragma unroll
    for (int j=0;j<CO_P;j++) acc[u][j] = 0ULL;

  float* sInF = &sIn[0][0][0];
  float4* wd  = reinterpret_cast<float4*>(&sW[0][0][0]);

  auto ldin = [&](int ci0, float (&vin)[NITER]){
    const int cBase = ci0*IH*IW;
    #pragma unroll
    for (int i=0;i<NITER;i++){
      float v = 0.f;
      int go = gOff[i];
      if (go >= 0) {
        v = in[go + cBase];
        if constexpr (ACT_IN_LRELU) {
          float t = fmaf(a_in[ci0+ccA[i]], v, c_in[ci0+ccA[i]]);
          v = t > 0.f ? t : 0.2f*t;
        }
      }
      vin[i] = v;
    }
  };
  auto ldw = [&](int ci0, float4 (&vw)[NW]){
    const float4* ws = reinterpret_cast<const float4*>(wT + ci0*16*OC);
    #pragma unroll
    for (int i=0;i<NW;i++){
      int idx = tid + i*NT;
      if (idx < WLEN4) vw[i] = ws[idx];
    }
  };

  float vin[PREFETCH ? NITER : 1];
  float4 vw[PREFETCH ? NW : 1];
  if constexpr (PREFETCH) {
    float (&vinR)[NITER] = reinterpret_cast<float(&)[NITER]>(vin);
    float4 (&vwR)[NW] = reinterpret_cast<float4(&)[NW]>(vw);
    ldin(0, vinR); ldw(0, vwR);
  }

  for (int ci0 = 0; ci0 < IC; ci0 += CI_CHUNK) {
    if constexpr (PREFETCH) {
      float (&vinR)[NITER] = reinterpret_cast<float(&)[NITER]>(vin);
      float4 (&vwR)[NW] = reinterpret_cast<float4(&)[NW]>(vw);
      #pragma unroll
      for (int i=0;i<NITER;i++){
        int idx = tid + i*NT;
        if (idx < TOTAL_IN) sInF[idx] = vinR[i];
      }
      #pragma unroll
      for (int i=0;i<NW;i++){
        int idx = tid + i*NT;
        if (idx < WLEN4) wd[idx] = vwR[i];
      }
      __syncthreads();
      if (ci0 + CI_CHUNK < IC) { ldin(ci0+CI_CHUNK, vinR); ldw(ci0+CI_CHUNK, vwR); }
    } else {
      const int cBase = ci0*IH*IW;
      #pragma unroll
      for (int i=0;i<NITER;i++){
        int idx = tid + i*NT;
        if (idx < TOTAL_IN) {
          float v = 0.f;
          int go = gOff[i];
          if (go >= 0) {
            v = in[go + cBase];
            if constexpr (ACT_IN_LRELU) {
              float t = fmaf(a_in[ci0+ccA[i]], v, c_in[ci0+ccA[i]]);
              v = t > 0.f ? t : 0.2f*t;
            }
          }
          sInF[idx] = v;
        }
      }
      const float4* ws = reinterpret_cast<const float4*>(wT + ci0*16*OC);
      #pragma unroll
      for (int i = 0; i < NW; i++) {
        int idx = tid + i*NT;
        if (idx < WLEN4) wd[idx] = ws[idx];
      }
      __syncthreads();
    }

    #pragma unroll
    for (int cc=0; cc<CI_CHUNK; cc++) {
      if constexpr (ROWCACHE) {
        #pragma unroll
        for (int ky=0; ky<4; ky++) {
          const float* rowp = &sIn[cc][2*oy_l + ky][0] + 2*ox0;
          unsigned long long pv[18];
          {
            const float4* rp4 = reinterpret_cast<const float4*>(rowp);
            float4 q;
            q = rp4[0]; pv[0]=pk2(q.x,q.x); pv[1]=pk2(q.y,q.y); pv[2]=pk2(q.z,q.z); pv[3]=pk2(q.w,q.w);
            q = rp4[1]; pv[4]=pk2(q.x,q.x); pv[5]=pk2(q.y,q.y); pv[6]=pk2(q.z,q.z); pv[7]=pk2(q.w,q.w);
            q = rp4[2]; pv[8]=pk2(q.x,q.x); pv[9]=pk2(q.y,q.y); pv[10]=pk2(q.z,q.z); pv[11]=pk2(q.w,q.w);
            q = rp4[3]; pv[12]=pk2(q.x,q.x); pv[13]=pk2(q.y,q.y); pv[14]=pk2(q.z,q.z); pv[15]=pk2(q.w,q.w);
            float2 q2 = *reinterpret_cast<const float2*>(rowp + 16);
            pv[16]=pk2(q2.x,q2.x); pv[17]=pk2(q2.y,q2.y);
          }
          #pragma unroll
          for (int kx=0; kx<4; kx++) {
            const int k = ky*4 + kx;
            unsigned long long wv[CO_P];
            #pragma unroll
            for (int j=0;j<CO_P;j++){
              int p = (j + co_g) & (CO_P-1);
              wv[j] = *reinterpret_cast<const unsigned long long*>(&sW[cc][k][co_t0 + 2*p]);
            }
            #pragma unroll
            for (int u=0;u<8;u++)
              #pragma unroll
              for (int j=0;j<CO_P;j++) fma2(acc[u][j], pv[2*u+kx], wv[j]);
          }
        }
      } else {
        #pragma unroll
        for (int k=0;k<16;k++) {
          const int ky = k >> 2, kx = k & 3;
          unsigned long long wv[CO_P];
          #pragma unroll
          for (int j=0;j<CO_P;j++){
            int p = (j + co_g) & (CO_P-1);
            wv[j] = *reinterpret_cast<const unsigned long long*>(&sW[cc][k][co_t0 + 2*p]);
          }
          const float* rowp = &sIn[cc][2*oy_l + ky][0];
          #pragma unroll
          for (int u=0;u<8;u++) {
            float iv = rowp[2*(ox0+u) + kx];
            unsigned long long pv = pk2(iv, iv);
            #pragma unroll
            for (int j=0;j<CO_P;j++) fma2(acc[u][j], pv, wv[j]);
          }
        }
      }
    }
    __syncthreads();
  }

  if constexpr (REDUCE) {
    for (int i = tid; i < 2*CO_BLK; i += NT) sRed[i] = 0.f;
    __syncthreads();
  }

  const int oy = oy0 + oy_l;
  #pragma unroll
  for (int j=0;j<CO_P;j++){
    int p = (j + co_g) & (CO_P-1);
    float v0[8], v1[8];
    #pragma unroll
    for (int u=0;u<8;u++) unpk(acc[u][j], v0[u], v1[u]);
    const int co = co_t0 + 2*p;
    if constexpr (BIAS) {
      float b0 = bias[co], b1 = bias[co+1];
      #pragma unroll
      for (int u=0;u<8;u++){ v0[u]+=b0; v1[u]+=b1; }
    }
    if constexpr (TANH_OUT) {
      #pragma unroll
      for (int u=0;u<8;u++){ v0[u]=tanhf(v0[u]); v1[u]=tanhf(v1[u]); }
    }
    float4* p0 = reinterpret_cast<float4*>(&out[((b*OUT_CB + co  )*OH + oy)*OW + ox0]);
    float4* p1 = reinterpret_cast<float4*>(&out[((b*OUT_CB + co+1)*OH + oy)*OW + ox0]);
    p0[0] = make_float4(v0[0],v0[1],v0[2],v0[3]);
    p0[1] = make_float4(v0[4],v0[5],v0[6],v0[7]);
    p1[0] = make_float4(v1[0],v1[1],v1[2],v1[3]);
    p1[1] = make_float4(v1[4],v1[5],v1[6],v1[7]);
    if constexpr (REDUCE) {
      float s0=0.f,q0=0.f,s1=0.f,q1=0.f;
      #pragma unroll
      for (int u=0;u<8;u++){ s0+=v0[u]; q0=fmaf(v0[u],v0[u],q0); s1+=v1[u]; q1=fmaf(v1[u],v1[u],q1); }
      atomicAdd(&sRed[co],          s0);
      atomicAdd(&sRed[CO_BLK+co],   q0);
      atomicAdd(&sRed[co+1],        s1);
      atomicAdd(&sRed[CO_BLK+co+1], q1);
    }
  }
  if constexpr (REDUCE) {
    __syncthreads();
    for (int i2 = tid; i2 < 2*CO_BLK; i2 += NT) {
      int off = (i2 < CO_BLK) ? 0 : OC;
      int cl  = (i2 < CO_BLK) ? i2 : (i2 - CO_BLK);
      atomicAdd(&stat[off + cl], sRed[i2]);
    }
  }
}

// =====================================================================
// Transposed conv via parity decomposition. PF_IN / PF_W independently
// gate register prefetch of next chunk's input / weights.
// =====================================================================
template<int IC, int OC, int IH, int IW, int OUT_CB,
         int TILE_M, int CO_BLK, int CI_CHUNK, int NG_N, int NG_CO,
         bool PF_IN, bool PF_W, bool ACT_IN_RELU, bool REDUCE>
__global__ void __launch_bounds__(NG_N*NG_CO*TILE_M)
deconv_kernel(const float* __restrict__ in, const float* __restrict__ wT,
              const float* __restrict__ a_in, const float* __restrict__ c_in,
              float* __restrict__ out, float* __restrict__ stat)
{
  constexpr int NT    = NG_N * NG_CO * TILE_M;
  constexpr int CO_T  = CO_BLK / NG_CO;
  constexpr int CO_P  = CO_T / 2;
  constexpr int ROWS  = TILE_M + 1;
  constexpr int COLSP = IW + 2;
  constexpr int TOTAL_IN = CI_CHUNK*ROWS*COLSP;
  constexpr int NITER = (TOTAL_IN + NT - 1)/NT;
  constexpr int WLEN4 = CI_CHUNK*4*CO_BLK/4;
  constexpr int NW    = (WLEN4 + NT - 1)/NT;
  static_assert(IW / NG_N == 8, "");
  static_assert(CO_BLK == OC, "");
  static_assert((CO_P & (CO_P-1)) == 0, "");

  __shared__ __align__(16) float sIn[CI_CHUNK][ROWS][COLSP];
  __shared__ __align__(16) float sW [CI_CHUNK][4][CO_BLK];
  __shared__ float sRed[2*CO_BLK];

  const int tid    = threadIdx.x;
  const int n_g    = tid % NG_N;
  const int co_g   = (tid / NG_N) % NG_CO;
  const int m_l    = tid / (NG_N * NG_CO);
  const int m_tile = blockIdx.x;
  const int ry     = blockIdx.y >> 1, rx = blockIdx.y & 1;
  const int par    = blockIdx.y;
  const int b      = blockIdx.z;
  const int m0     = m_tile * TILE_M;
  const int n0     = n_g * 8;
  const int co_t0  = co_g * CO_T;

  int gOff[NITER]; int ccA[ACT_IN_RELU ? NITER : 1];
  #pragma unroll
  for (int i=0;i<NITER;i++){
    int idx = tid + i*NT;
    int cc  = idx / (ROWS*COLSP);
    int rem = idx % (ROWS*COLSP);
    int r   = rem / COLSP, col = rem % COLSP;
    int gy  = m0 + ry - 1 + r;
    int gx  = rx - 1 + col;
    bool ok = (idx < TOTAL_IN) && gx >= 0 && gx < IW && gy >= 0 && gy < IH;
    gOff[i] = ok ? ((b*IC + cc)*IH + gy)*IW + gx : -1;
    if constexpr (ACT_IN_RELU) ccA[i] = cc;
  }

  unsigned long long acc[8][CO_P];
  #pragma unroll
  for (int u=0;u<8;u++)
    #pragma unroll
    for (int j=0;j<CO_P;j++) acc[u][j] = 0ULL;

  float* sInF = &sIn[0][0][0];
  float4* wd  = reinterpret_cast<float4*>(&sW[0][0][0]);

  auto ldin = [&](int ci0, float (&vin)[NITER]){
    const int cBase = ci0*IH*IW;
    #pragma unroll
    for (int i=0;i<NITER;i++){
      float v = 0.f;
      int go = gOff[i];
      if (go >= 0) {
        v = in[go + cBase];
        if constexpr (ACT_IN_RELU)
          v = fmaxf(fmaf(a_in[ci0+ccA[i]], v, c_in[ci0+ccA[i]]), 0.f);
      }
      vin[i] = v;
    }
  };
  auto ldw = [&](int ci0, float4 (&vw)[NW]){
    const float4* ws = reinterpret_cast<const float4*>(wT + (par*IC + ci0)*4*OC);
    #pragma unroll
    for (int i=0;i<NW;i++){
      int idx = tid + i*NT;
      if (idx < WLEN4) vw[i] = ws[idx];
    }
  };

  float vin[PF_IN ? NITER : 1];
  float4 vw[PF_W ? NW : 1];
  if constexpr (PF_IN) {
    float (&vinR)[NITER] = reinterpret_cast<float(&)[NITER]>(vin);
    ldin(0, vinR);
  }
  if constexpr (PF_W) {
    float4 (&vwR)[NW] = reinterpret_cast<float4(&)[NW]>(vw);
    ldw(0, vwR);
  }

  for (int ci0 = 0; ci0 < IC; ci0 += CI_CHUNK) {
    if constexpr (PF_IN) {
      float (&vinR)[NITER] = reinterpret_cast<float(&)[NITER]>(vin);
      #pragma unroll
      for (int i=0;i<NITER;i++){
        int idx = tid + i*NT;
        if (idx < TOTAL_IN) sInF[idx] = vinR[i];
      }
    } else {
      const int cBase = ci0*IH*IW;
      #pragma unroll
      for (int i=0;i<NITER;i++){
        int idx = tid + i*NT;
        if (idx < TOTAL_IN) {
          float v = 0.f;
          int go = gOff[i];
          if (go >= 0) {
            v = in[go + cBase];
            if constexpr (ACT_IN_RELU)
              v = fmaxf(fmaf(a_in[ci0+ccA[i]], v, c_in[ci0+ccA[i]]), 0.f);
          }
          sInF[idx] = v;
        }
      }
    }
    if constexpr (PF_W) {
      float4 (&vwR)[NW] = reinterpret_cast<float4(&)[NW]>(vw);
      #pragma unroll
      for (int i=0;i<NW;i++){
        int idx = tid + i*NT;
        if (idx < WLEN4) wd[idx] = vwR[i];
      }
    } else {
      const float4* ws = reinterpret_cast<const float4*>(wT + (par*IC + ci0)*4*OC);
      #pragma unroll
      for (int i = 0; i < NW; i++) {
        int idx = tid + i*NT;
        if (idx < WLEN4) wd[idx] = ws[idx];
      }
    }
    __syncthreads();
    if (ci0 + CI_CHUNK < IC) {
      if constexpr (PF_IN) {
        float (&vinR)[NITER] = reinterpret_cast<float(&)[NITER]>(vin);
        ldin(ci0+CI_CHUNK, vinR);
      }
      if constexpr (PF_W) {
        float4 (&vwR)[NW] = reinterpret_cast<float4(&)[NW]>(vw);
        ldw(ci0+CI_CHUNK, vwR);
      }
    }

    #pragma unroll
    for (int cc=0; cc<CI_CHUNK; cc++) {
      #pragma unroll
      for (int t4=0;t4<4;t4++) {
        const int dd = t4 >> 1, ee = t4 & 1;
        unsigned long long wv[CO_P];
        #pragma unroll
        for (int j=0;j<CO_P;j++){
          int p = (j + co_g) & (CO_P-1);
          wv[j] = *reinterpret_cast<const unsigned long long*>(&sW[cc][t4][co_t0 + 2*p]);
        }
        const float* rowp = &sIn[cc][m_l + dd][0];
        #pragma unroll
        for (int u=0;u<8;u++) {
          float iv = rowp[n0 + u + ee];
          unsigned long long pv = pk2(iv, iv);
          #pragma unroll
          for (int j=0;j<CO_P;j++) fma2(acc[u][j], pv, wv[j]);
        }
      }
    }
    __syncthreads();
  }

  if constexpr (REDUCE) {
    for (int i = tid; i < 2*CO_BLK; i += NT) sRed[i] = 0.f;
    __syncthreads();
  }

  const int oy = 2*(m0 + m_l) + ry;
  const int OW2 = 2*IW, OH2 = 2*IH;
  #pragma unroll
  for (int j=0;j<CO_P;j++){
    int p = (j + co_g) & (CO_P-1);
    const int co = co_t0 + 2*p;
    float* r0 = &out[((b*OUT_CB + co  )*OH2 + oy)*OW2 + rx];
    float* r1 = &out[((b*OUT_CB + co+1)*OH2 + oy)*OW2 + rx];
    float s0=0.f,q0=0.f,s1=0.f,q1=0.f;
    #pragma unroll
    for (int u=0;u<8;u++){
      float v0, v1; unpk(acc[u][j], v0, v1);
      r0[2*(n0+u)] = v0;
      r1[2*(n0+u)] = v1;
      if constexpr (REDUCE) { s0+=v0; q0=fmaf(v0,v0,q0); s1+=v1; q1=fmaf(v1,v1,q1); }
    }
    if constexpr (REDUCE) {
      atomicAdd(&sRed[co],          s0);
      atomicAdd(&sRed[CO_BLK+co],   q0);
      atomicAdd(&sRed[co+1],        s1);
      atomicAdd(&sRed[CO_BLK+co+1], q1);
    }
  }
  if constexpr (REDUCE) {
    __syncthreads();
    for (int i2 = tid; i2 < 2*CO_BLK; i2 += NT) {
      int off = (i2 < CO_BLK) ? 0 : OC;
      int cl  = (i2 < CO_BLK) ? i2 : (i2 - CO_BLK);
      atomicAdd(&stat[off + cl], sRed[i2]);
    }
  }
}

// =====================================================================
// Final deconv 128->3 with bias + tanh
// =====================================================================
__global__ void __launch_bounds__(128)
deconv2_kernel(const float* __restrict__ in, const float* __restrict__ w,
               const float* __restrict__ bias,
               const float* __restrict__ a_in, const float* __restrict__ c_in,
               float* __restrict__ out)
{
  constexpr int IC=128, IH=64, IW=64, TILE_M=16, CI=4, NG_N=8;
  constexpr int NT=128, ROWS=TILE_M+1, COLSP=IW+2;
  constexpr int TOTAL_IN = CI*ROWS*COLSP;
  constexpr int NITER = (TOTAL_IN + NT - 1)/NT;
  __shared__ float sIn[CI][ROWS][COLSP];
  __shared__ float sW[CI][4][4];

  const int tid = threadIdx.x;
  const int n_g = tid % NG_N;
  const int m_l = tid / NG_N;
  const int m0  = blockIdx.x * TILE_M;
  const int ry  = blockIdx.y >> 1, rx = blockIdx.y & 1;
  const int b   = blockIdx.z;
  const int n0  = n_g * 8;

  int gOff[NITER]; int ccA[NITER];
  #pragma unroll
  for (int i=0;i<NITER;i++){
    int idx = tid + i*NT;
    int cc  = idx / (ROWS*COLSP);
    int rem = idx % (ROWS*COLSP);
    int r   = rem / COLSP, col = rem % COLSP;
    int gy  = m0 + ry - 1 + r;
    int gx  = rx - 1 + col;
    bool ok = (idx < TOTAL_IN) && gx >= 0 && gx < IW && gy >= 0 && gy < IH;
    gOff[i] = ok ? ((b*IC + cc)*IH + gy)*IW + gx : -1;
    ccA[i]  = cc;
  }

  float acc[3][8];
  #pragma unroll
  for (int co=0;co<3;co++)
    #pragma unroll
    for (int u=0;u<8;u++) acc[co][u] = 0.f;

  float* sInF = &sIn[0][0][0];

  for (int ci0 = 0; ci0 < IC; ci0 += CI) {
    const int cBase = ci0*IH*IW;
    #pragma unroll
    for (int i=0;i<NITER;i++){
      int idx = tid + i*NT;
      if (idx < TOTAL_IN) {
        float v = 0.f;
        int go = gOff[i];
        if (go >= 0)
          v = fmaxf(fmaf(a_in[ci0+ccA[i]], in[go + cBase], c_in[ci0+ccA[i]]), 0.f);
        sInF[idx] = v;
      }
    }
    if (tid < 48) {
      int cc = tid / 12, t4 = (tid / 3) % 4, co = tid % 3;
      int dd = t4 >> 1, ee = t4 & 1;
      sW[cc][t4][co] = w[((ci0+cc)*3 + co)*16 + (3-ry-2*dd)*4 + (3-rx-2*ee)];
    }
    __syncthreads();

    #pragma unroll
    for (int cc=0; cc<CI; cc++) {
      #pragma unroll
      for (int t4=0;t4<4;t4++) {
        const int dd = t4 >> 1, ee = t4 & 1;
        float w0 = sW[cc][t4][0], w1 = sW[cc][t4][1], w2 = sW[cc][t4][2];
        const float* rowp = &sIn[cc][m_l + dd][0];
        #pragma unroll
        for (int u=0;u<8;u++) {
          float iv = rowp[n0 + u + ee];
          acc[0][u] = fmaf(iv, w0, acc[0][u]);
          acc[1][u] = fmaf(iv, w1, acc[1][u]);
          acc[2][u] = fmaf(iv, w2, acc[2][u]);
        }
      }
    }
    __syncthreads();
  }

  const int oy = 2*(m0 + m_l) + ry;
  #pragma unroll
  for (int co=0;co<3;co++){
    float bb = bias[co];
    float* rp = &out[((b*3 + co)*128 + oy)*128 + rx];
    #pragma unroll
    for (int u=0;u<8;u++)
      rp[2*(n0+u)] = tanhf(acc[co][u] + bb);
  }
}

// =====================================================================
__global__ void finalize_kernel(const float* __restrict__ stat, const float* __restrict__ g,
                                const float* __restrict__ be,
                                float* __restrict__ a, float* __restrict__ cv,
                                int C, float invN)
{
  int c = threadIdx.x + blockIdx.x*blockDim.x;
  if (c >= C) return;
  float mean = stat[c] * invN;
  float var  = stat[C + c] * invN - mean*mean;
  float av = g[c] * rsqrtf(var + 1e-5f);
  a[c] = av;
  cv[c] = be[c] - mean * av;
}

__global__ void zero_kernel(float* s0, float* s1, float* s2, float* s3)
{
  int t = threadIdx.x;
  if (t < 128) s0[t] = 0.f;
  if (t < 256) s1[t] = 0.f;
  if (t < 512) s2[t] = 0.f;
  if (t < 256) s3[t] = 0.f;
}

__global__ void pack_kernel(const float* __restrict__ Zl, const float* __restrict__ Zg,
                            float* __restrict__ Zbuf)
{
  int idx = blockIdx.x * 256 + threadIdx.x;
  const int nl = 64*32*256;
  if (idx < nl) {
    int b = idx / (32*256); int r = idx % (32*256);
    Zbuf[(b*168 + 64)*256 + r] = Zl[idx];
  }
  const int ng = 64*64*256;
  if (idx < ng) {
    int b = idx / (64*256); int r = idx % (64*256);
    Zbuf[(b*168 + 96)*256 + r] = Zg[idx];
  }
}

__global__ void wave_kernel(const float* __restrict__ Zg, const float* __restrict__ phi,
                            const float* __restrict__ lW, const float* __restrict__ lb,
                            const float* __restrict__ l1W, const float* __restrict__ l1b,
                            const float* __restrict__ l2W, const float* __restrict__ l2b,
                            float* __restrict__ Zbuf)
{
  const int b = blockIdx.x;
  const int t = threadIdx.x;  // 64
  __shared__ float zg[64], x[64], K[16];
  zg[t] = Zg[(b*64 + t)*256];
  __syncthreads();
  float acc = lb[t];
  #pragma unroll 8
  for (int g = 0; g < 64; g++) acc = fmaf(zg[g], lW[t*64+g], acc);
  x[t] = fmaxf(acc, 0.f);
  __syncthreads();
  if (t < 16) {
    int p = t & 7;
    const float* W  = (t < 8) ? l1W : l2W;
    const float* bb = (t < 8) ? l1b : l2b;
    float k = bb[p];
    #pragma unroll 8
    for (int h = 0; h < 64; h++) k = fmaf(x[h], W[p*64+h], k);
    K[t] = k;
  }
  __syncthreads();
  for (int idx = t; idx < 8*256; idx += 64) {
    int p = idx >> 8; int ij = idx & 255; int i = ij >> 4; int j = ij & 15;
    float wv = K[p]*(float)i + K[p+8]*(float)j + phi[b*8+p]*TWO_PI_F;
    Zbuf[(b*168 + 160 + p)*256 + ij] = sinf(wv);
  }
}

// =====================================================================
extern "C" void kernel_launch(void* const* d_in, const int* in_sizes, int n_in,
                              void* d_out, int out_size)
{
  const float* Zl   = (const float*)d_in[0];
  const float* Zg   = (const float*)d_in[1];
  const float* imgs = (const float*)d_in[2];
  const float* phi  = (const float*)d_in[3];
  const float* lW   = (const float*)d_in[4];
  const float* lb   = (const float*)d_in[5];
  const float* l1W  = (const float*)d_in[6];
  const float* l1b  = (const float*)d_in[7];
  const float* l2W  = (const float*)d_in[8];
  const float* l2b  = (const float*)d_in[9];
  const float* cw0  = (const float*)d_in[10];
  const float* cg0  = (const float*)d_in[12];
  const float* cbe0 = (const float*)d_in[13];
  const float* cw1  = (const float*)d_in[14];
  const float* cg1  = (const float*)d_in[16];
  const float* cbe1 = (const float*)d_in[17];
  const float* cw2  = (const float*)d_in[18];
  const float* cb2  = (const float*)d_in[19];
  const float* gw0  = (const float*)d_in[20];
  const float* gg0  = (const float*)d_in[22];
  const float* gbe0 = (const float*)d_in[23];
  const float* gw1  = (const float*)d_in[24];
  const float* gg1  = (const float*)d_in[26];
  const float* gbe1 = (const float*)d_in[27];
  const float* gw2  = (const float*)d_in[28];
  const float* gb2  = (const float*)d_in[29];
  float* out = (float*)d_out;

  float *h0,*h1,*Zb,*g0,*g1;
  float *s0,*s1,*s2,*s3;
  float *a0,*c0,*a1,*c1,*a2,*c2,*a3,*c3;
  float *wTc0,*wTc1,*wTc2,*wTd0,*wTd1;
  cudaGetSymbolAddress((void**)&h0, d_h0);
  cudaGetSymbolAddress((void**)&h1, d_h1);
  cudaGetSymbolAddress((void**)&Zb, d_Zbuf);
  cudaGetSymbolAddress((void**)&g0, d_g0);
  cudaGetSymbolAddress((void**)&g1, d_g1);
  cudaGetSymbolAddress((void**)&s0, d_stat0);
  cudaGetSymbolAddress((void**)&s1, d_stat1);
  cudaGetSymbolAddress((void**)&s2, d_stat2);
  cudaGetSymbolAddress((void**)&s3, d_stat3);
  cudaGetSymbolAddress((void**)&a0, d_a0); cudaGetSymbolAddress((void**)&c0, d_c0);
  cudaGetSymbolAddress((void**)&a1, d_a1); cudaGetSymbolAddress((void**)&c1, d_c1);
  cudaGetSymbolAddress((void**)&a2, d_a2); cudaGetSymbolAddress((void**)&c2, d_c2);
  cudaGetSymbolAddress((void**)&a3, d_a3); cudaGetSymbolAddress((void**)&c3, d_c3);
  cudaGetSymbolAddress((void**)&wTc0, d_wTc0);
  cudaGetSymbolAddress((void**)&wTc1, d_wTc1);
  cudaGetSymbolAddress((void**)&wTc2, d_wTc2);
  cudaGetSymbolAddress((void**)&wTd0, d_wTd0);
  cudaGetSymbolAddress((void**)&wTd1, d_wTd1);

  zero_kernel<<<1,512>>>(s0, s1, s2, s3);                          // 0
  transpose_convs<<<512,256>>>(cw0, wTc0, cw1, wTc1, cw2, wTc2);   // 1
  transpose_deconvs<<<2688,256>>>(gw0, wTd0, gw1, wTd1);           // 2

  // encoder (stats fused) — conv0 at capture slot 3
  conv_s2_kernel<3,64,128,128,64,64, 64, 4,64,3,8,8, true,false, false,false,false,true>
      <<<dim3(16,1,64),256>>>(imgs, wTc0, nullptr, nullptr, nullptr, h0, s0);  // 3
  finalize_kernel<<<1,64>>>(s0, cg0, cbe0, a0, c0, 64, 1.f/(64.f*4096.f));
  conv_s2_kernel<64,128,64,64,32,32, 128, 8,128,2,4,8, false,false, true,false,false,true>
      <<<dim3(4,1,64),256>>>(h0, wTc1, nullptr, a0, c0, h1, s1);
  finalize_kernel<<<1,128>>>(s1, cg1, cbe1, a1, c1, 128, 1.f/(64.f*1024.f));
  conv_s2_kernel<128,64,32,32,16,16, 168, 8,64,4,2,16, true,true, true,true,true,false>
      <<<dim3(2,1,64),256>>>(h1, wTc2, cb2, a1, c1, Zb, nullptr);

  pack_kernel<<<4096,256>>>(Zl, Zg, Zb);
  wave_kernel<<<64,64>>>(Zg, phi, lW, lb, l1W, l1b, l2W, l2b, Zb);

  // generator (stats fused)
  deconv_kernel<168,256,16,16, 256, 8,256,8,2,16, true,false, false,true>
      <<<dim3(2,4,64),256>>>(Zb, wTd0, nullptr, nullptr, g0, s2);
  finalize_kernel<<<1,256>>>(s2, gg0, gbe0, a2, c2, 256, 1.f/(64.f*1024.f));
  deconv_kernel<256,128,32,32, 128, 8,128,8,4,16, true,true, true,true>
      <<<dim3(4,4,64),512>>>(g0, wTd1, a2, c2, g1, s3);
  finalize_kernel<<<1,128>>>(s3, gg1, gbe1, a3, c3, 128, 1.f/(64.f*4096.f));
  deconv2_kernel<<<dim3(4,4,64),128>>>(g1, gw2, gb2, a3, c3, out);
}

// round 16
// speedup vs baseline: 1.1039x; 1.0091x over previous
#include <cuda_runtime.h>
#include <math.h>

#define TWO_PI_F 6.2831853071795864769f

// ---------------- device scratch ----------------
__device__ float d_h0[64*64*64*64];
__device__ float d_h1[64*128*32*32];
__device__ float d_Zbuf[64*168*16*16];
__device__ float d_g0[64*256*32*32];
__device__ float d_g1[64*128*64*64];
__device__ float d_stat0[128];
__device__ float d_stat1[256];
__device__ float d_stat2[512];
__device__ float d_stat3[256];
__device__ float d_a0[64],  d_c0[64];
__device__ float d_a1[128], d_c1[128];
__device__ float d_a2[256], d_c2[256];
__device__ float d_a3[128], d_c3[128];
__device__ float d_wTc0[3*16*64];
__device__ float d_wTc1[64*16*128];
__device__ float d_wTc2[128*16*64];
__device__ float d_wTd0[4*168*4*256];
__device__ float d_wTd1[4*256*4*128];

// ---------------- packed f32x2 helpers ----------------
__device__ __forceinline__ unsigned long long pk2(float lo, float hi){
  unsigned long long r; asm("mov.b64 %0, {%1, %2};" : "=l"(r) : "f"(lo), "f"(hi)); return r;
}
__device__ __forceinline__ void fma2(unsigned long long& d, unsigned long long a, unsigned long long b){
  asm("fma.rn.f32x2 %0, %1, %2, %0;" : "+l"(d) : "l"(a), "l"(b));
}
__device__ __forceinline__ void unpk(unsigned long long v, float& lo, float& hi){
  asm("mov.b64 {%0, %1}, %2;" : "=f"(lo), "=f"(hi) : "l"(v));
}

// =====================================================================
// Weight transposes
// =====================================================================
__device__ __forceinline__ void tconv(const float* __restrict__ w, float* __restrict__ wT,
                                      int IC, int OC, int idx){
  int k = idx % 16; int ci = (idx/16) % IC; int co = idx/(16*IC);
  wT[(ci*16+k)*OC + co] = w[idx];
}
__device__ __forceinline__ void tdec(const float* __restrict__ w, float* __restrict__ wT,
                                     int IC, int OC, int idx){
  int kk = idx%16; int co = (idx/16)%OC; int ci = idx/(16*OC);
  int ky=kk>>2, kx=kk&3;
  int ry=(3-ky)&1, dd=(3-ky-ry)>>1;
  int rx=(3-kx)&1, ee=(3-kx-rx)>>1;
  wT[(((ry*2+rx)*IC+ci)*4 + dd*2+ee)*OC + co] = w[idx];
}
__global__ void transpose_convs(const float* w0, float* o0, const float* w1, float* o1,
                                const float* w2, float* o2){
  int idx = blockIdx.x*256 + threadIdx.x;
  if (idx < 3*64*16)   tconv(w0,o0,3,64,idx);
  if (idx < 64*128*16) tconv(w1,o1,64,128,idx);
  if (idx < 128*64*16) tconv(w2,o2,128,64,idx);
}
__global__ void transpose_deconvs(const float* w0, float* o0, const float* w1, float* o1){
  int idx = blockIdx.x*256+threadIdx.x;
  if (idx < 168*256*16) tdec(w0,o0,168,256,idx);
  if (idx < 256*128*16) tdec(w1,o1,256,128,idx);
}

// =====================================================================
// Strided conv k=4 s=2 p=1. ROWCACHE where regs allow; PF_IN / PF_W
// independently gate register prefetch of next chunk.
// =====================================================================
template<int IC, int OC, int IH, int IW, int OH, int OW, int OUT_CB,
         int TILE_OY, int CO_BLK, int CI_CHUNK, int NG_OX, int NG_CO,
         bool ROWCACHE, bool PF_IN, bool PF_W, bool ACT_IN_LRELU, bool BIAS, bool TANH_OUT, bool REDUCE>
__global__ void __launch_bounds__(NG_CO*NG_OX*TILE_OY)
conv_s2_kernel(const float* __restrict__ in, const float* __restrict__ wT,
               const float* __restrict__ bias,
               const float* __restrict__ a_in, const float* __restrict__ c_in,
               float* __restrict__ out, float* __restrict__ stat)
{
  constexpr int NT    = NG_CO * NG_OX * TILE_OY;
  constexpr int CO_T  = CO_BLK / NG_CO;
  constexpr int CO_P  = CO_T / 2;
  constexpr int ROWS  = 2*TILE_OY + 2;
  constexpr int COLSP = IW + 4;
  constexpr int TOTAL_IN = CI_CHUNK*ROWS*COLSP;
  constexpr int NITER = (TOTAL_IN + NT - 1)/NT;
  constexpr int WLEN4 = CI_CHUNK*16*CO_BLK/4;
  constexpr int NW    = (WLEN4 + NT - 1)/NT;
  static_assert(OW / NG_OX == 8, "");
  static_assert(CO_BLK == OC, "");
  static_assert((CO_P & (CO_P-1)) == 0, "");
  static_assert(!ROWCACHE || CO_P <= 4, "");

  __shared__ __align__(16) float sIn[CI_CHUNK][ROWS][COLSP];
  __shared__ __align__(16) float sW [CI_CHUNK][16][CO_BLK];
  __shared__ float sRed[2*CO_BLK];

  const int tid   = threadIdx.x;
  const int co_g  = tid % NG_CO;
  const int ox_g  = (tid / NG_CO) % NG_OX;
  const int oy_l  = tid / (NG_CO * NG_OX);
  const int b     = blockIdx.z;
  const int oy0   = blockIdx.x * TILE_OY;
  const int iy0   = 2*oy0 - 1;
  const int ox0   = ox_g * 8;
  const int co_t0 = co_g * CO_T;

  int gOff[NITER]; int ccA[ACT_IN_LRELU ? NITER : 1];
  #pragma unroll
  for (int i=0;i<NITER;i++){
    int idx = tid + i*NT;
    int cc  = idx / (ROWS*COLSP);
    int rem = idx % (ROWS*COLSP);
    int r   = rem / COLSP, col = rem % COLSP;
    int iy  = iy0 + r, ix = col - 1;
    bool ok = (idx < TOTAL_IN) && ix >= 0 && ix < IW && iy >= 0 && iy < IH;
    gOff[i] = ok ? ((b*IC + cc)*IH + iy)*IW + ix : -1;
    if constexpr (ACT_IN_LRELU) ccA[i] = cc;
  }

  unsigned long long acc[8][CO_P];
  #pragma unroll
  for (int u=0;u<8;u++)
    #pragma unroll
    for (int j=0;j<CO_P;j++) acc[u][j] = 0ULL;

  float* sInF = &sIn[0][0][0];
  float4* wd  = reinterpret_cast<float4*>(&sW[0][0][0]);

  auto ldin = [&](int ci0, float (&vin)[NITER]){
    const int cBase = ci0*IH*IW;
    #pragma unroll
    for (int i=0;i<NITER;i++){
      float v = 0.f;
      int go = gOff[i];
      if (go >= 0) {
        v = in[go + cBase];
        if constexpr (ACT_IN_LRELU) {
          float t = fmaf(a_in[ci0+ccA[i]], v, c_in[ci0+ccA[i]]);
          v = t > 0.f ? t : 0.2f*t;
        }
      }
      vin[i] = v;
    }
  };
  auto ldw = [&](int ci0, float4 (&vw)[NW]){
    const float4* ws = reinterpret_cast<const float4*>(wT + ci0*16*OC);
    #pragma unroll
    for (int i=0;i<NW;i++){
      int idx = tid + i*NT;
      if (idx < WLEN4) vw[i] = ws[idx];
    }
  };

  float vin[PF_IN ? NITER : 1];
  float4 vw[PF_W ? NW : 1];
  if constexpr (PF_IN) {
    float (&vinR)[NITER] = reinterpret_cast<float(&)[NITER]>(vin);
    ldin(0, vinR);
  }
  if constexpr (PF_W) {
    float4 (&vwR)[NW] = reinterpret_cast<float4(&)[NW]>(vw);
    ldw(0, vwR);
  }

  for (int ci0 = 0; ci0 < IC; ci0 += CI_CHUNK) {
    if constexpr (PF_IN) {
      float (&vinR)[NITER] = reinterpret_cast<float(&)[NITER]>(vin);
      #pragma unroll
      for (int i=0;i<NITER;i++){
        int idx = tid + i*NT;
        if (idx < TOTAL_IN) sInF[idx] = vinR[i];
      }
    } else {
      const int cBase = ci0*IH*IW;
      #pragma unroll
      for (int i=0;i<NITER;i++){
        int idx = tid + i*NT;
        if (idx < TOTAL_IN) {
          float v = 0.f;
          int go = gOff[i];
          if (go >= 0) {
            v = in[go + cBase];
            if constexpr (ACT_IN_LRELU) {
              float t = fmaf(a_in[ci0+ccA[i]], v, c_in[ci0+ccA[i]]);
              v = t > 0.f ? t : 0.2f*t;
            }
          }
          sInF[idx] = v;
        }
      }
    }
    if constexpr (PF_W) {
      float4 (&vwR)[NW] = reinterpret_cast<float4(&)[NW]>(vw);
      #pragma unroll
      for (int i=0;i<NW;i++){
        int idx = tid + i*NT;
        if (idx < WLEN4) wd[idx] = vwR[i];
      }
    } else {
      const float4* ws = reinterpret_cast<const float4*>(wT + ci0*16*OC);
      #pragma unroll
      for (int i = 0; i < NW; i++) {
        int idx = tid + i*NT;
        if (idx < WLEN4) wd[idx] = ws[idx];
      }
    }
    __syncthreads();
    if (ci0 + CI_CHUNK < IC) {
      if constexpr (PF_IN) {
        float (&vinR)[NITER] = reinterpret_cast<float(&)[NITER]>(vin);
        ldin(ci0+CI_CHUNK, vinR);
      }
      if constexpr (PF_W) {
        float4 (&vwR)[NW] = reinterpret_cast<float4(&)[NW]>(vw);
        ldw(ci0+CI_CHUNK, vwR);
      }
    }

    #pragma unroll
    for (int cc=0; cc<CI_CHUNK; cc++) {
      if constexpr (ROWCACHE) {
        #pragma unroll
        for (int ky=0; ky<4; ky++) {
          const float* rowp = &sIn[cc][2*oy_l + ky][0] + 2*ox0;
          unsigned long long pv[18];
          {
            const float4* rp4 = reinterpret_cast<const float4*>(rowp);
            float4 q;
            q = rp4[0]; pv[0]=pk2(q.x,q.x); pv[1]=pk2(q.y,q.y); pv[2]=pk2(q.z,q.z); pv[3]=pk2(q.w,q.w);
            q = rp4[1]; pv[4]=pk2(q.x,q.x); pv[5]=pk2(q.y,q.y); pv[6]=pk2(q.z,q.z); pv[7]=pk2(q.w,q.w);
            q = rp4[2]; pv[8]=pk2(q.x,q.x); pv[9]=pk2(q.y,q.y); pv[10]=pk2(q.z,q.z); pv[11]=pk2(q.w,q.w);
            q = rp4[3]; pv[12]=pk2(q.x,q.x); pv[13]=pk2(q.y,q.y); pv[14]=pk2(q.z,q.z); pv[15]=pk2(q.w,q.w);
            float2 q2 = *reinterpret_cast<const float2*>(rowp + 16);
            pv[16]=pk2(q2.x,q2.x); pv[17]=pk2(q2.y,q2.y);
          }
          #pragma unroll
          for (int kx=0; kx<4; kx++) {
            const int k = ky*4 + kx;
            unsigned long long wv[CO_P];
            #pragma unroll
            for (int j=0;j<CO_P;j++){
              int p = (j + co_g) & (CO_P-1);
              wv[j] = *reinterpret_cast<const unsigned long long*>(&sW[cc][k][co_t0 + 2*p]);
            }
            #pragma unroll
            for (int u=0;u<8;u++)
              #pragma unroll
              for (int j=0;j<CO_P;j++) fma2(acc[u][j], pv[2*u+kx], wv[j]);
          }
        }
      } else {
        #pragma unroll
        for (int k=0;k<16;k++) {
          const int ky = k >> 2, kx = k & 3;
          unsigned long long wv[CO_P];
          #pragma unroll
          for (int j=0;j<CO_P;j++){
            int p = (j + co_g) & (CO_P-1);
            wv[j] = *reinterpret_cast<const unsigned long long*>(&sW[cc][k][co_t0 + 2*p]);
          }
          const float* rowp = &sIn[cc][2*oy_l + ky][0];
          #pragma unroll
          for (int u=0;u<8;u++) {
            float iv = rowp[2*(ox0+u) + kx];
            unsigned long long pv = pk2(iv, iv);
            #pragma unroll
            for (int j=0;j<CO_P;j++) fma2(acc[u][j], pv, wv[j]);
          }
        }
      }
    }
    __syncthreads();
  }

  if constexpr (REDUCE) {
    for (int i = tid; i < 2*CO_BLK; i += NT) sRed[i] = 0.f;
    __syncthreads();
  }

  const int oy = oy0 + oy_l;
  #pragma unroll
  for (int j=0;j<CO_P;j++){
    int p = (j + co_g) & (CO_P-1);
    float v0[8], v1[8];
    #pragma unroll
    for (int u=0;u<8;u++) unpk(acc[u][j], v0[u], v1[u]);
    const int co = co_t0 + 2*p;
    if constexpr (BIAS) {
      float b0 = bias[co], b1 = bias[co+1];
      #pragma unroll
      for (int u=0;u<8;u++){ v0[u]+=b0; v1[u]+=b1; }
    }
    if constexpr (TANH_OUT) {
      #pragma unroll
      for (int u=0;u<8;u++){ v0[u]=tanhf(v0[u]); v1[u]=tanhf(v1[u]); }
    }
    float4* p0 = reinterpret_cast<float4*>(&out[((b*OUT_CB + co  )*OH + oy)*OW + ox0]);
    float4* p1 = reinterpret_cast<float4*>(&out[((b*OUT_CB + co+1)*OH + oy)*OW + ox0]);
    p0[0] = make_float4(v0[0],v0[1],v0[2],v0[3]);
    p0[1] = make_float4(v0[4],v0[5],v0[6],v0[7]);
    p1[0] = make_float4(v1[0],v1[1],v1[2],v1[3]);
    p1[1] = make_float4(v1[4],v1[5],v1[6],v1[7]);
    if constexpr (REDUCE) {
      float s0=0.f,q0=0.f,s1=0.f,q1=0.f;
      #pragma unroll
      for (int u=0;u<8;u++){ s0+=v0[u]; q0=fmaf(v0[u],v0[u],q0); s1+=v1[u]; q1=fmaf(v1[u],v1[u],q1); }
      atomicAdd(&sRed[co],          s0);
      atomicAdd(&sRed[CO_BLK+co],   q0);
      atomicAdd(&sRed[co+1],        s1);
      atomicAdd(&sRed[CO_BLK+co+1], q1);
    }
  }
  if constexpr (REDUCE) {
    __syncthreads();
    for (int i2 = tid; i2 < 2*CO_BLK; i2 += NT) {
      int off = (i2 < CO_BLK) ? 0 : OC;
      int cl  = (i2 < CO_BLK) ? i2 : (i2 - CO_BLK);
      atomicAdd(&stat[off + cl], sRed[i2]);
    }
  }
}

// =====================================================================
// Transposed conv via parity decomposition. PF_IN / PF_W prefetch flags.
// =====================================================================
template<int IC, int OC, int IH, int IW, int OUT_CB,
         int TILE_M, int CO_BLK, int CI_CHUNK, int NG_N, int NG_CO,
         bool PF_IN, bool PF_W, bool ACT_IN_RELU, bool REDUCE>
__global__ void __launch_bounds__(NG_N*NG_CO*TILE_M)
deconv_kernel(const float* __restrict__ in, const float* __restrict__ wT,
              const float* __restrict__ a_in, const float* __restrict__ c_in,
              float* __restrict__ out, float* __restrict__ stat)
{
  constexpr int NT    = NG_N * NG_CO * TILE_M;
  constexpr int CO_T  = CO_BLK / NG_CO;
  constexpr int CO_P  = CO_T / 2;
  constexpr int ROWS  = TILE_M + 1;
  constexpr int COLSP = IW + 2;
  constexpr int TOTAL_IN = CI_CHUNK*ROWS*COLSP;
  constexpr int NITER = (TOTAL_IN + NT - 1)/NT;
  constexpr int WLEN4 = CI_CHUNK*4*CO_BLK/4;
  constexpr int NW    = (WLEN4 + NT - 1)/NT;
  static_assert(IW / NG_N == 8, "");
  static_assert(CO_BLK == OC, "");
  static_assert((CO_P & (CO_P-1)) == 0, "");

  __shared__ __align__(16) float sIn[CI_CHUNK][ROWS][COLSP];
  __shared__ __align__(16) float sW [CI_CHUNK][4][CO_BLK];
  __shared__ float sRed[2*CO_BLK];

  const int tid    = threadIdx.x;
  const int n_g    = tid % NG_N;
  const int co_g   = (tid / NG_N) % NG_CO;
  const int m_l    = tid / (NG_N * NG_CO);
  const int m_tile = blockIdx.x;
  const int ry     = blockIdx.y >> 1, rx = blockIdx.y & 1;
  const int par    = blockIdx.y;
  const int b      = blockIdx.z;
  const int m0     = m_tile * TILE_M;
  const int n0     = n_g * 8;
  const int co_t0  = co_g * CO_T;

  int gOff[NITER]; int ccA[ACT_IN_RELU ? NITER : 1];
  #pragma unroll
  for (int i=0;i<NITER;i++){
    int idx = tid + i*NT;
    int cc  = idx / (ROWS*COLSP);
    int rem = idx % (ROWS*COLSP);
    int r   = rem / COLSP, col = rem % COLSP;
    int gy  = m0 + ry - 1 + r;
    int gx  = rx - 1 + col;
    bool ok = (idx < TOTAL_IN) && gx >= 0 && gx < IW && gy >= 0 && gy < IH;
    gOff[i] = ok ? ((b*IC + cc)*IH + gy)*IW + gx : -1;
    if constexpr (ACT_IN_RELU) ccA[i] = cc;
  }

  unsigned long long acc[8][CO_P];
  #pragma unroll
  for (int u=0;u<8;u++)
    #pragma unroll
    for (int j=0;j<CO_P;j++) acc[u][j] = 0ULL;

  float* sInF = &sIn[0][0][0];
  float4* wd  = reinterpret_cast<float4*>(&sW[0][0][0]);

  auto ldin = [&](int ci0, float (&vin)[NITER]){
    const int cBase = ci0*IH*IW;
    #pragma unroll
    for (int i=0;i<NITER;i++){
      float v = 0.f;
      int go = gOff[i];
      if (go >= 0) {
        v = in[go + cBase];
        if constexpr (ACT_IN_RELU)
          v = fmaxf(fmaf(a_in[ci0+ccA[i]], v, c_in[ci0+ccA[i]]), 0.f);
      }
      vin[i] = v;
    }
  };
  auto ldw = [&](int ci0, float4 (&vw)[NW]){
    const float4* ws = reinterpret_cast<const float4*>(wT + (par*IC + ci0)*4*OC);
    #pragma unroll
    for (int i=0;i<NW;i++){
      int idx = tid + i*NT;
      if (idx < WLEN4) vw[i] = ws[idx];
    }
  };

  float vin[PF_IN ? NITER : 1];
  float4 vw[PF_W ? NW : 1];
  if constexpr (PF_IN) {
    float (&vinR)[NITER] = reinterpret_cast<float(&)[NITER]>(vin);
    ldin(0, vinR);
  }
  if constexpr (PF_W) {
    float4 (&vwR)[NW] = reinterpret_cast<float4(&)[NW]>(vw);
    ldw(0, vwR);
  }

  for (int ci0 = 0; ci0 < IC; ci0 += CI_CHUNK) {
    if constexpr (PF_IN) {
      float (&vinR)[NITER] = reinterpret_cast<float(&)[NITER]>(vin);
      #pragma unroll
      for (int i=0;i<NITER;i++){
        int idx = tid + i*NT;
        if (idx < TOTAL_IN) sInF[idx] = vinR[i];
      }
    } else {
      const int cBase = ci0*IH*IW;
      #pragma unroll
      for (int i=0;i<NITER;i++){
        int idx = tid + i*NT;
        if (idx < TOTAL_IN) {
          float v = 0.f;
          int go = gOff[i];
          if (go >= 0) {
            v = in[go + cBase];
            if constexpr (ACT_IN_RELU)
              v = fmaxf(fmaf(a_in[ci0+ccA[i]], v, c_in[ci0+ccA[i]]), 0.f);
          }
          sInF[idx] = v;
        }
      }
    }
    if constexpr (PF_W) {
      float4 (&vwR)[NW] = reinterpret_cast<float4(&)[NW]>(vw);
      #pragma unroll
      for (int i=0;i<NW;i++){
        int idx = tid + i*NT;
        if (idx < WLEN4) wd[idx] = vwR[i];
      }
    } else {
      const float4* ws = reinterpret_cast<const float4*>(wT + (par*IC + ci0)*4*OC);
      #pragma unroll
      for (int i = 0; i < NW; i++) {
        int idx = tid + i*NT;
        if (idx < WLEN4) wd[idx] = ws[idx];
      }
    }
    __syncthreads();
    if (ci0 + CI_CHUNK < IC) {
      if constexpr (PF_IN) {
        float (&vinR)[NITER] = reinterpret_cast<float(&)[NITER]>(vin);
        ldin(ci0+CI_CHUNK, vinR);
      }
      if constexpr (PF_W) {
        float4 (&vwR)[NW] = reinterpret_cast<float4(&)[NW]>(vw);
        ldw(ci0+CI_CHUNK, vwR);
      }
    }

    #pragma unroll
    for (int cc=0; cc<CI_CHUNK; cc++) {
      #pragma unroll
      for (int t4=0;t4<4;t4++) {
        const int dd = t4 >> 1, ee = t4 & 1;
        unsigned long long wv[CO_P];
        #pragma unroll
        for (int j=0;j<CO_P;j++){
          int p = (j + co_g) & (CO_P-1);
          wv[j] = *reinterpret_cast<const unsigned long long*>(&sW[cc][t4][co_t0 + 2*p]);
        }
        const float* rowp = &sIn[cc][m_l + dd][0];
        #pragma unroll
        for (int u=0;u<8;u++) {
          float iv = rowp[n0 + u + ee];
          unsigned long long pv = pk2(iv, iv);
          #pragma unroll
          for (int j=0;j<CO_P;j++) fma2(acc[u][j], pv, wv[j]);
        }
      }
    }
    __syncthreads();
  }

  if constexpr (REDUCE) {
    for (int i = tid; i < 2*CO_BLK; i += NT) sRed[i] = 0.f;
    __syncthreads();
  }

  const int oy = 2*(m0 + m_l) + ry;
  const int OW2 = 2*IW, OH2 = 2*IH;
  #pragma unroll
  for (int j=0;j<CO_P;j++){
    int p = (j + co_g) & (CO_P-1);
    const int co = co_t0 + 2*p;
    float* r0 = &out[((b*OUT_CB + co  )*OH2 + oy)*OW2 + rx];
    float* r1 = &out[((b*OUT_CB + co+1)*OH2 + oy)*OW2 + rx];
    float s0=0.f,q0=0.f,s1=0.f,q1=0.f;
    #pragma unroll
    for (int u=0;u<8;u++){
      float v0, v1; unpk(acc[u][j], v0, v1);
      r0[2*(n0+u)] = v0;
      r1[2*(n0+u)] = v1;
      if constexpr (REDUCE) { s0+=v0; q0=fmaf(v0,v0,q0); s1+=v1; q1=fmaf(v1,v1,q1); }
    }
    if constexpr (REDUCE) {
      atomicAdd(&sRed[co],          s0);
      atomicAdd(&sRed[CO_BLK+co],   q0);
      atomicAdd(&sRed[co+1],        s1);
      atomicAdd(&sRed[CO_BLK+co+1], q1);
    }
  }
  if constexpr (REDUCE) {
    __syncthreads();
    for (int i2 = tid; i2 < 2*CO_BLK; i2 += NT) {
      int off = (i2 < CO_BLK) ? 0 : OC;
      int cl  = (i2 < CO_BLK) ? i2 : (i2 - CO_BLK);
      atomicAdd(&stat[off + cl], sRed[i2]);
    }
  }
}

// =====================================================================
// Final deconv 128->3 with bias + tanh
// =====================================================================
__global__ void __launch_bounds__(128)
deconv2_kernel(const float* __restrict__ in, const float* __restrict__ w,
               const float* __restrict__ bias,
               const float* __restrict__ a_in, const float* __restrict__ c_in,
               float* __restrict__ out)
{
  constexpr int IC=128, IH=64, IW=64, TILE_M=16, CI=4, NG_N=8;
  constexpr int NT=128, ROWS=TILE_M+1, COLSP=IW+2;
  constexpr int TOTAL_IN = CI*ROWS*COLSP;
  constexpr int NITER = (TOTAL_IN + NT - 1)/NT;
  __shared__ float sIn[CI][ROWS][COLSP];
  __shared__ float sW[CI][4][4];

  const int tid = threadIdx.x;
  const int n_g = tid % NG_N;
  const int m_l = tid / NG_N;
  const int m0  = blockIdx.x * TILE_M;
  const int ry  = blockIdx.y >> 1, rx = blockIdx.y & 1;
  const int b   = blockIdx.z;
  const int n0  = n_g * 8;

  int gOff[NITER]; int ccA[NITER];
  #pragma unroll
  for (int i=0;i<NITER;i++){
    int idx = tid + i*NT;
    int cc  = idx / (ROWS*COLSP);
    int rem = idx % (ROWS*COLSP);
    int r   = rem / COLSP, col = rem % COLSP;
    int gy  = m0 + ry - 1 + r;
    int gx  = rx - 1 + col;
    bool ok = (idx < TOTAL_IN) && gx >= 0 && gx < IW && gy >= 0 && gy < IH;
    gOff[i] = ok ? ((b*IC + cc)*IH + gy)*IW + gx : -1;
    ccA[i]  = cc;
  }

  float acc[3][8];
  #pragma unroll
  for (int co=0;co<3;co++)
    #pragma unroll
    for (int u=0;u<8;u++) acc[co][u] = 0.f;

  float* sInF = &sIn[0][0][0];

  for (int ci0 = 0; ci0 < IC; ci0 += CI) {
    const int cBase = ci0*IH*IW;
    #pragma unroll
    for (int i=0;i<NITER;i++){
      int idx = tid + i*NT;
      if (idx < TOTAL_IN) {
        float v = 0.f;
        int go = gOff[i];
        if (go >= 0)
          v = fmaxf(fmaf(a_in[ci0+ccA[i]], in[go + cBase], c_in[ci0+ccA[i]]), 0.f);
        sInF[idx] = v;
      }
    }
    if (tid < 48) {
      int cc = tid / 12, t4 = (tid / 3) % 4, co = tid % 3;
      int dd = t4 >> 1, ee = t4 & 1;
      sW[cc][t4][co] = w[((ci0+cc)*3 + co)*16 + (3-ry-2*dd)*4 + (3-rx-2*ee)];
    }
    __syncthreads();

    #pragma unroll
    for (int cc=0; cc<CI; cc++) {
      #pragma unroll
      for (int t4=0;t4<4;t4++) {
        const int dd = t4 >> 1, ee = t4 & 1;
        float w0 = sW[cc][t4][0], w1 = sW[cc][t4][1], w2 = sW[cc][t4][2];
        const float* rowp = &sIn[cc][m_l + dd][0];
        #pragma unroll
        for (int u=0;u<8;u++) {
          float iv = rowp[n0 + u + ee];
          acc[0][u] = fmaf(iv, w0, acc[0][u]);
          acc[1][u] = fmaf(iv, w1, acc[1][u]);
          acc[2][u] = fmaf(iv, w2, acc[2][u]);
        }
      }
    }
    __syncthreads();
  }

  const int oy = 2*(m0 + m_l) + ry;
  #pragma unroll
  for (int co=0;co<3;co++){
    float bb = bias[co];
    float* rp = &out[((b*3 + co)*128 + oy)*128 + rx];
    #pragma unroll
    for (int u=0;u<8;u++)
      rp[2*(n0+u)] = tanhf(acc[co][u] + bb);
  }
}

// =====================================================================
__global__ void finalize_kernel(const float* __restrict__ stat, const float* __restrict__ g,
                                const float* __restrict__ be,
                                float* __restrict__ a, float* __restrict__ cv,
                                int C, float invN)
{
  int c = threadIdx.x + blockIdx.x*blockDim.x;
  if (c >= C) return;
  float mean = stat[c] * invN;
  float var  = stat[C + c] * invN - mean*mean;
  float av = g[c] * rsqrtf(var + 1e-5f);
  a[c] = av;
  cv[c] = be[c] - mean * av;
}

__global__ void zero_kernel(float* s0, float* s1, float* s2, float* s3)
{
  int t = threadIdx.x;
  if (t < 128) s0[t] = 0.f;
  if (t < 256) s1[t] = 0.f;
  if (t < 512) s2[t] = 0.f;
  if (t < 256) s3[t] = 0.f;
}

__global__ void pack_kernel(const float* __restrict__ Zl, const float* __restrict__ Zg,
                            float* __restrict__ Zbuf)
{
  int idx = blockIdx.x * 256 + threadIdx.x;
  const int nl = 64*32*256;
  if (idx < nl) {
    int b = idx / (32*256); int r = idx % (32*256);
    Zbuf[(b*168 + 64)*256 + r] = Zl[idx];
  }
  const int ng = 64*64*256;
  if (idx < ng) {
    int b = idx / (64*256); int r = idx % (64*256);
    Zbuf[(b*168 + 96)*256 + r] = Zg[idx];
  }
}

__global__ void wave_kernel(const float* __restrict__ Zg, const float* __restrict__ phi,
                            const float* __restrict__ lW, const float* __restrict__ lb,
                            const float* __restrict__ l1W, const float* __restrict__ l1b,
                            const float* __restrict__ l2W, const float* __restrict__ l2b,
                            float* __restrict__ Zbuf)
{
  const int b = blockIdx.x;
  const int t = threadIdx.x;  // 64
  __shared__ float zg[64], x[64], K[16];
  zg[t] = Zg[(b*64 + t)*256];
  __syncthreads();
  float acc = lb[t];
  #pragma unroll 8
  for (int g = 0; g < 64; g++) acc = fmaf(zg[g], lW[t*64+g], acc);
  x[t] = fmaxf(acc, 0.f);
  __syncthreads();
  if (t < 16) {
    int p = t & 7;
    const float* W  = (t < 8) ? l1W : l2W;
    const float* bb = (t < 8) ? l1b : l2b;
    float k = bb[p];
    #pragma unroll 8
    for (int h = 0; h < 64; h++) k = fmaf(x[h], W[p*64+h], k);
    K[t] = k;
  }
  __syncthreads();
  for (int idx = t; idx < 8*256; idx += 64) {
    int p = idx >> 8; int ij = idx & 255; int i = ij >> 4; int j = ij & 15;
    float wv = K[p]*(float)i + K[p+8]*(float)j + phi[b*8+p]*TWO_PI_F;
    Zbuf[(b*168 + 160 + p)*256 + ij] = sinf(wv);
  }
}

// =====================================================================
extern "C" void kernel_launch(void* const* d_in, const int* in_sizes, int n_in,
                              void* d_out, int out_size)
{
  const float* Zl   = (const float*)d_in[0];
  const float* Zg   = (const float*)d_in[1];
  const float* imgs = (const float*)d_in[2];
  const float* phi  = (const float*)d_in[3];
  const float* lW   = (const float*)d_in[4];
  const float* lb   = (const float*)d_in[5];
  const float* l1W  = (const float*)d_in[6];
  const float* l1b  = (const float*)d_in[7];
  const float* l2W  = (const float*)d_in[8];
  const float* l2b  = (const float*)d_in[9];
  const float* cw0  = (const float*)d_in[10];
  const float* cg0  = (const float*)d_in[12];
  const float* cbe0 = (const float*)d_in[13];
  const float* cw1  = (const float*)d_in[14];
  const float* cg1  = (const float*)d_in[16];
  const float* cbe1 = (const float*)d_in[17];
  const float* cw2  = (const float*)d_in[18];
  const float* cb2  = (const float*)d_in[19];
  const float* gw0  = (const float*)d_in[20];
  const float* gg0  = (const float*)d_in[22];
  const float* gbe0 = (const float*)d_in[23];
  const float* gw1  = (const float*)d_in[24];
  const float* gg1  = (const float*)d_in[26];
  const float* gbe1 = (const float*)d_in[27];
  const float* gw2  = (const float*)d_in[28];
  const float* gb2  = (const float*)d_in[29];
  float* out = (float*)d_out;

  float *h0,*h1,*Zb,*g0,*g1;
  float *s0,*s1,*s2,*s3;
  float *a0,*c0,*a1,*c1,*a2,*c2,*a3,*c3;
  float *wTc0,*wTc1,*wTc2,*wTd0,*wTd1;
  cudaGetSymbolAddress((void**)&h0, d_h0);
  cudaGetSymbolAddress((void**)&h1, d_h1);
  cudaGetSymbolAddress((void**)&Zb, d_Zbuf);
  cudaGetSymbolAddress((void**)&g0, d_g0);
  cudaGetSymbolAddress((void**)&g1, d_g1);
  cudaGetSymbolAddress((void**)&s0, d_stat0);
  cudaGetSymbolAddress((void**)&s1, d_stat1);
  cudaGetSymbolAddress((void**)&s2, d_stat2);
  cudaGetSymbolAddress((void**)&s3, d_stat3);
  cudaGetSymbolAddress((void**)&a0, d_a0); cudaGetSymbolAddress((void**)&c0, d_c0);
  cudaGetSymbolAddress((void**)&a1, d_a1); cudaGetSymbolAddress((void**)&c1, d_c1);
  cudaGetSymbolAddress((void**)&a2, d_a2); cudaGetSymbolAddress((void**)&c2, d_c2);
  cudaGetSymbolAddress((void**)&a3, d_a3); cudaGetSymbolAddress((void**)&c3, d_c3);
  cudaGetSymbolAddress((void**)&wTc0, d_wTc0);
  cudaGetSymbolAddress((void**)&wTc1, d_wTc1);
  cudaGetSymbolAddress((void**)&wTc2, d_wTc2);
  cudaGetSymbolAddress((void**)&wTd0, d_wTd0);
  cudaGetSymbolAddress((void**)&wTd1, d_wTd1);

  zero_kernel<<<1,512>>>(s0, s1, s2, s3);                          // 0
  transpose_convs<<<512,256>>>(cw0, wTc0, cw1, wTc1, cw2, wTc2);   // 1
  transpose_deconvs<<<2688,256>>>(gw0, wTd0, gw1, wTd1);           // 2

  // encoder (stats fused) — conv0 at capture slot 3
  conv_s2_kernel<3,64,128,128,64,64, 64, 4,64,3,8,8, true,false,false, false,false,false,true>
      <<<dim3(16,1,64),256>>>(imgs, wTc0, nullptr, nullptr, nullptr, h0, s0);  // 3
  finalize_kernel<<<1,64>>>(s0, cg0, cbe0, a0, c0, 64, 1.f/(64.f*4096.f));
  conv_s2_kernel<64,128,64,64,32,32, 128, 8,128,2,4,8, false,true,true, true,false,false,true>
      <<<dim3(4,1,64),256>>>(h0, wTc1, nullptr, a0, c0, h1, s1);
  finalize_kernel<<<1,128>>>(s1, cg1, cbe1, a1, c1, 128, 1.f/(64.f*1024.f));
  conv_s2_kernel<128,64,32,32,16,16, 168, 8,64,4,2,16, true,true,true, true,true,true,false>
      <<<dim3(2,1,64),256>>>(h1, wTc2, cb2, a1, c1, Zb, nullptr);

  pack_kernel<<<4096,256>>>(Zl, Zg, Zb);
  wave_kernel<<<64,64>>>(Zg, phi, lW, lb, l1W, l1b, l2W, l2b, Zb);

  // generator (stats fused)
  deconv_kernel<168,256,16,16, 256, 8,256,8,2,16, true,true, false,true>
      <<<dim3(2,4,64),256>>>(Zb, wTd0, nullptr, nullptr, g0, s2);
  finalize_kernel<<<1,256>>>(s2, gg0, gbe0, a2, c2, 256, 1.f/(64.f*1024.f));
  deconv_kernel<256,128,32,32, 128, 8,128,8,4,16, true,true, true,true>
      <<<dim3(4,4,64),512>>>(g0, wTd1, a2, c2, g1, s3);
  finalize_kernel<<<1,128>>>(s3, gg1, gbe1, a3, c3, 128, 1.f/(64.f*4096.f));
  deconv2_kernel<<<dim3(4,4,64),128>>>(g1, gw2, gb2, a3, c3, out);
}